// round 1
// baseline (speedup 1.0000x reference)
#include <cuda_runtime.h>

#define NSEQ 512
#define DMODEL 128
#define DFFN 2048
#define LN_EPS 1e-5f

// ---- scratch (device globals; no runtime allocation) ----
__device__ float g_mem[(size_t)NSEQ * NSEQ * DMODEL];   // memory tensor (s, n, d)
__device__ float g_ns[NSEQ * DMODEL];                   // node @ w_mem_s + b_mem
__device__ float g_nt[NSEQ * DMODEL];                   // node @ w_mem_t
__device__ float g_q[NSEQ * DMODEL];                    // node @ wq + bq
__device__ float g_qh[NSEQ * DMODEL * 8];               // [n][c][h] = sum_dh wk[c,h*16+dh]*q[n,h*16+dh] * 0.25
__device__ float g_ctx[NSEQ * DMODEL];
__device__ float g_x1[NSEQ * DMODEL];

__device__ __forceinline__ float warp_sum(float v) {
#pragma unroll
    for (int o = 16; o; o >>= 1) v += __shfl_xor_sync(0xffffffffu, v, o);
    return v;
}
__device__ __forceinline__ float warp_max(float v) {
#pragma unroll
    for (int o = 16; o; o >>= 1) v = fmaxf(v, __shfl_xor_sync(0xffffffffu, v, o));
    return v;
}

// ---- small precompute: ns, nt, q -----------------------------------------
__global__ void k_pre(const float* __restrict__ node,
                      const float* __restrict__ w_mem_s, const float* __restrict__ b_mem,
                      const float* __restrict__ w_mem_t,
                      const float* __restrict__ wq, const float* __restrict__ bq) {
    int row = blockIdx.x, which = blockIdx.y, d = threadIdx.x;
    __shared__ float xs[DMODEL];
    xs[d] = node[row * DMODEL + d];
    __syncthreads();
    const float* W = (which == 0) ? w_mem_s : (which == 1) ? w_mem_t : wq;
    float acc = (which == 0) ? b_mem[d] : (which == 2) ? bq[d] : 0.f;
#pragma unroll 4
    for (int c = 0; c < DMODEL; c++) acc += xs[c] * W[c * DMODEL + d];
    float* out = (which == 0) ? g_ns : (which == 1) ? g_nt : g_q;
    out[row * DMODEL + d] = acc;
}

// ---- qh precompute: folds wk into q (bk drops via softmax invariance) ----
__global__ void k_qh(const float* __restrict__ wk) {
    int n = blockIdx.x, c = threadIdx.x;
    __shared__ float qs[DMODEL];
    qs[c] = g_q[n * DMODEL + c];
    __syncthreads();
    const float* wrow = wk + c * DMODEL;
#pragma unroll
    for (int h = 0; h < 8; h++) {
        float a = 0.f;
#pragma unroll
        for (int dh = 0; dh < 16; dh++) a += wrow[h * 16 + dh] * qs[h * 16 + dh];
        g_qh[n * 1024 + c * 8 + h] = a * 0.25f;  // fold 1/sqrt(DH)
    }
}

// ---- big GEMM 1: memory = relu(LN(edge @ w_mem_e + ns[n] + nt[s])) -------
__global__ __launch_bounds__(256) void k_mem(
    const float* __restrict__ edge, const float* __restrict__ W,
    const float* __restrict__ gln, const float* __restrict__ bln) {
    __shared__ float As[128][36];
    __shared__ float Bs[32][128];
    const int t = threadIdx.x, warp = t >> 5, lane = t & 31;
    const size_t m0 = (size_t)blockIdx.x * 128;
    float acc[16][4];
#pragma unroll
    for (int i = 0; i < 16; i++) { acc[i][0] = 0.f; acc[i][1] = 0.f; acc[i][2] = 0.f; acc[i][3] = 0.f; }

    for (int kt = 0; kt < 128; kt += 32) {
#pragma unroll
        for (int i = 0; i < 4; i++) {
            int row = (t >> 3) + i * 32, k = (t & 7) * 4;
            *(float4*)&As[row][k] = *(const float4*)&edge[(m0 + row) * 128 + kt + k];
        }
#pragma unroll
        for (int i = 0; i < 4; i++) {
            int kr = (t >> 5) + i * 8, c4 = (t & 31) * 4;
            *(float4*)&Bs[kr][c4] = *(const float4*)&W[(size_t)(kt + kr) * 128 + c4];
        }
        __syncthreads();
#pragma unroll
        for (int kk = 0; kk < 32; kk++) {
            float4 b = *(float4*)&Bs[kk][lane * 4];
#pragma unroll
            for (int i = 0; i < 16; i++) {
                float a = As[warp * 16 + i][kk];
                acc[i][0] += a * b.x; acc[i][1] += a * b.y;
                acc[i][2] += a * b.z; acc[i][3] += a * b.w;
            }
        }
        __syncthreads();
    }
    const int c0 = lane * 4;
    float4 g4 = *(const float4*)&gln[c0];
    float4 bb4 = *(const float4*)&bln[c0];
#pragma unroll
    for (int i = 0; i < 16; i++) {
        size_t r = m0 + warp * 16 + i;
        int s = (int)(r >> 9), n = (int)(r & 511);
        float4 nsv = *(const float4*)&g_ns[n * 128 + c0];
        float4 ntv = *(const float4*)&g_nt[s * 128 + c0];
        float v0 = acc[i][0] + nsv.x + ntv.x, v1 = acc[i][1] + nsv.y + ntv.y;
        float v2 = acc[i][2] + nsv.z + ntv.z, v3 = acc[i][3] + nsv.w + ntv.w;
        float sum = warp_sum(v0 + v1 + v2 + v3);
        float sq  = warp_sum(v0 * v0 + v1 * v1 + v2 * v2 + v3 * v3);
        float mean = sum * (1.f / 128.f);
        float var = sq * (1.f / 128.f) - mean * mean;
        float rs = rsqrtf(var + LN_EPS);
        float4 o;
        o.x = fmaxf((v0 - mean) * rs * g4.x + bb4.x, 0.f);
        o.y = fmaxf((v1 - mean) * rs * g4.y + bb4.y, 0.f);
        o.z = fmaxf((v2 - mean) * rs * g4.z + bb4.z, 0.f);
        o.w = fmaxf((v3 - mean) * rs * g4.w + bb4.w, 0.f);
        *(float4*)&g_mem[r * 128 + c0] = o;
    }
}

// ---- big GEMM 2: edge_new = LN(edge + relu(LN(memory @ w_pe + b_pe))) ----
__global__ __launch_bounds__(256) void k_edge(
    const float* __restrict__ edge, const float* __restrict__ W,
    const float* __restrict__ bpe,
    const float* __restrict__ g1, const float* __restrict__ b1,
    const float* __restrict__ g2, const float* __restrict__ b2,
    float* __restrict__ out_edge) {
    __shared__ float As[128][36];
    __shared__ float Bs[32][128];
    const int t = threadIdx.x, warp = t >> 5, lane = t & 31;
    const size_t m0 = (size_t)blockIdx.x * 128;
    float acc[16][4];
#pragma unroll
    for (int i = 0; i < 16; i++) { acc[i][0] = 0.f; acc[i][1] = 0.f; acc[i][2] = 0.f; acc[i][3] = 0.f; }

    for (int kt = 0; kt < 128; kt += 32) {
#pragma unroll
        for (int i = 0; i < 4; i++) {
            int row = (t >> 3) + i * 32, k = (t & 7) * 4;
            *(float4*)&As[row][k] = *(const float4*)&g_mem[(m0 + row) * 128 + kt + k];
        }
#pragma unroll
        for (int i = 0; i < 4; i++) {
            int kr = (t >> 5) + i * 8, c4 = (t & 31) * 4;
            *(float4*)&Bs[kr][c4] = *(const float4*)&W[(size_t)(kt + kr) * 128 + c4];
        }
        __syncthreads();
#pragma unroll
        for (int kk = 0; kk < 32; kk++) {
            float4 b = *(float4*)&Bs[kk][lane * 4];
#pragma unroll
            for (int i = 0; i < 16; i++) {
                float a = As[warp * 16 + i][kk];
                acc[i][0] += a * b.x; acc[i][1] += a * b.y;
                acc[i][2] += a * b.z; acc[i][3] += a * b.w;
            }
        }
        __syncthreads();
    }
    const int c0 = lane * 4;
    float4 bp  = *(const float4*)&bpe[c0];
    float4 g1v = *(const float4*)&g1[c0];
    float4 b1v = *(const float4*)&b1[c0];
    float4 g2v = *(const float4*)&g2[c0];
    float4 b2v = *(const float4*)&b2[c0];
#pragma unroll
    for (int i = 0; i < 16; i++) {
        size_t r = m0 + warp * 16 + i;
        float v0 = acc[i][0] + bp.x, v1 = acc[i][1] + bp.y;
        float v2 = acc[i][2] + bp.z, v3 = acc[i][3] + bp.w;
        float sum = warp_sum(v0 + v1 + v2 + v3);
        float sq  = warp_sum(v0 * v0 + v1 * v1 + v2 * v2 + v3 * v3);
        float mean = sum * (1.f / 128.f);
        float rs = rsqrtf(sq * (1.f / 128.f) - mean * mean + LN_EPS);
        float u0 = fmaxf((v0 - mean) * rs * g1v.x + b1v.x, 0.f);
        float u1 = fmaxf((v1 - mean) * rs * g1v.y + b1v.y, 0.f);
        float u2 = fmaxf((v2 - mean) * rs * g1v.z + b1v.z, 0.f);
        float u3 = fmaxf((v3 - mean) * rs * g1v.w + b1v.w, 0.f);
        float4 e = *(const float4*)&edge[r * 128 + c0];
        float w0 = e.x + u0, w1 = e.y + u1, w2 = e.z + u2, w3 = e.w + u3;
        float sum2 = warp_sum(w0 + w1 + w2 + w3);
        float sq2  = warp_sum(w0 * w0 + w1 * w1 + w2 * w2 + w3 * w3);
        float mean2 = sum2 * (1.f / 128.f);
        float rs2 = rsqrtf(sq2 * (1.f / 128.f) - mean2 * mean2 + LN_EPS);
        float4 o;
        o.x = (w0 - mean2) * rs2 * g2v.x + b2v.x;
        o.y = (w1 - mean2) * rs2 * g2v.y + b2v.y;
        o.z = (w2 - mean2) * rs2 * g2v.z + b2v.z;
        o.w = (w3 - mean2) * rs2 * g2v.w + b2v.w;
        *(float4*)&out_edge[r * 128 + c0] = o;
    }
}

// ---- attention: scores via qh, softmax, r = attn^T @ Mcol, ctx = r @ wv --
__global__ __launch_bounds__(256) void k_attn(
    const unsigned char* __restrict__ mask,
    const float* __restrict__ wv, const float* __restrict__ bv) {
    int n = blockIdx.x, t = threadIdx.x, warp = t >> 5, lane = t & 31;
    __shared__ float qh_s[128 * 8];
    __shared__ float S[512 * 8];
    __shared__ float r_s[8][128];
    for (int i = t; i < 1024; i += 256) qh_s[i] = g_qh[n * 1024 + i];
    __syncthreads();

    // pass 1: scores (warp per s)
    for (int sb = 0; sb < 64; sb++) {
        int s = sb * 8 + warp;
        const float* m = &g_mem[((size_t)s * 512 + n) * 128];
        float a0 = 0, a1 = 0, a2 = 0, a3 = 0, a4 = 0, a5 = 0, a6 = 0, a7 = 0;
#pragma unroll
        for (int j = 0; j < 4; j++) {
            int c = lane + j * 32;
            float mv = m[c];
            float4 qa = *(float4*)&qh_s[c * 8];
            float4 qb = *(float4*)&qh_s[c * 8 + 4];
            a0 += mv * qa.x; a1 += mv * qa.y; a2 += mv * qa.z; a3 += mv * qa.w;
            a4 += mv * qb.x; a5 += mv * qb.y; a6 += mv * qb.z; a7 += mv * qb.w;
        }
        a0 = warp_sum(a0); a1 = warp_sum(a1); a2 = warp_sum(a2); a3 = warp_sum(a3);
        a4 = warp_sum(a4); a5 = warp_sum(a5); a6 = warp_sum(a6); a7 = warp_sum(a7);
        if (lane == 0) {
            bool mk = mask[n * 512 + s] != 0;
            const float NEG = -3.402823466e38f;
            S[s * 8 + 0] = mk ? NEG : a0; S[s * 8 + 1] = mk ? NEG : a1;
            S[s * 8 + 2] = mk ? NEG : a2; S[s * 8 + 3] = mk ? NEG : a3;
            S[s * 8 + 4] = mk ? NEG : a4; S[s * 8 + 5] = mk ? NEG : a5;
            S[s * 8 + 6] = mk ? NEG : a6; S[s * 8 + 7] = mk ? NEG : a7;
        }
    }
    __syncthreads();

    // softmax per head (warp = h)
    {
        int h = warp;
        float mx = -3.402823466e38f;
        for (int s = lane; s < 512; s += 32) mx = fmaxf(mx, S[s * 8 + h]);
        mx = warp_max(mx);
        float sum = 0.f;
        for (int s = lane; s < 512; s += 32) {
            float e = __expf(S[s * 8 + h] - mx);
            S[s * 8 + h] = e;
            sum += e;
        }
        sum = warp_sum(sum);
        float inv = 1.f / sum;
        for (int s = lane; s < 512; s += 32) S[s * 8 + h] *= inv;
    }
    __syncthreads();

    // pass 2: r[h,:] = sum_s attn[s,h] * memory[s,n,:]
    {
        int h = warp;
        float a0 = 0, a1 = 0, a2 = 0, a3 = 0;
        for (int s = 0; s < 512; s++) {
            const float* m = &g_mem[((size_t)s * 512 + n) * 128];
            float a = S[s * 8 + h];
            a0 += a * m[lane]; a1 += a * m[lane + 32];
            a2 += a * m[lane + 64]; a3 += a * m[lane + 96];
        }
        r_s[h][lane] = a0; r_s[h][lane + 32] = a1;
        r_s[h][lane + 64] = a2; r_s[h][lane + 96] = a3;
    }
    __syncthreads();

    // ctx[h, dh] = r[h,:] @ wv[:, h*16+dh] + bv   (sum attn = 1)
    if (t < 128) {
        int h = t >> 4;
        float a = bv[t];
#pragma unroll 4
        for (int c = 0; c < 128; c++) a += r_s[h][c] * wv[c * 128 + t];
        g_ctx[n * 128 + t] = a;
    }
}

// ---- x1 = LN(node + ctx @ wo + bo) ---------------------------------------
__global__ void k_out1(const float* __restrict__ node, const float* __restrict__ wo,
                       const float* __restrict__ bo, const float* __restrict__ g2,
                       const float* __restrict__ b2) {
    int row = blockIdx.x, d = threadIdx.x;
    __shared__ float cs[128];
    __shared__ float rsum[4], rsq[4];
    cs[d] = g_ctx[row * 128 + d];
    __syncthreads();
    float a = bo[d];
#pragma unroll 4
    for (int c = 0; c < 128; c++) a += cs[c] * wo[c * 128 + d];
    a += node[row * 128 + d];
    float s1 = warp_sum(a), s2 = warp_sum(a * a);
    if ((d & 31) == 0) { rsum[d >> 5] = s1; rsq[d >> 5] = s2; }
    __syncthreads();
    float sum = rsum[0] + rsum[1] + rsum[2] + rsum[3];
    float sq = rsq[0] + rsq[1] + rsq[2] + rsq[3];
    float mean = sum * (1.f / 128.f);
    float rs = rsqrtf(sq * (1.f / 128.f) - mean * mean + LN_EPS);
    g_x1[row * 128 + d] = (a - mean) * rs * g2[d] + b2[d];
}

// ---- FFN + final LN (4 rows per block to amortize weight reads) ----------
__global__ __launch_bounds__(256) void k_ffn(
    const float* __restrict__ w1, const float* __restrict__ b1,
    const float* __restrict__ w2, const float* __restrict__ b2,
    const float* __restrict__ g3, const float* __restrict__ b3,
    float* __restrict__ out_x) {
    __shared__ float xs[4][128];
    __shared__ float hs[4 * 2048];
    __shared__ float resid[4][128];
    int t = threadIdx.x;
    int r0 = blockIdx.x * 4;
    for (int i = t; i < 512; i += 256) xs[i >> 7][i & 127] = g_x1[r0 * 128 + i];
    __syncthreads();
#pragma unroll
    for (int j = 0; j < 8; j++) {
        int col = t + j * 256;
        float bb = b1[col];
        float a0 = bb, a1 = bb, a2 = bb, a3 = bb;
#pragma unroll 4
        for (int c = 0; c < 128; c++) {
            float w = w1[c * 2048 + col];
            a0 += xs[0][c] * w; a1 += xs[1][c] * w;
            a2 += xs[2][c] * w; a3 += xs[3][c] * w;
        }
        hs[0 * 2048 + col] = fmaxf(a0, 0.f);
        hs[1 * 2048 + col] = fmaxf(a1, 0.f);
        hs[2 * 2048 + col] = fmaxf(a2, 0.f);
        hs[3 * 2048 + col] = fmaxf(a3, 0.f);
    }
    __syncthreads();
    if (t < 128) {
        float bb = b2[t];
        float a0 = bb, a1 = bb, a2 = bb, a3 = bb;
#pragma unroll 4
        for (int c = 0; c < 2048; c++) {
            float w = w2[c * 128 + t];
            a0 += hs[c] * w; a1 += hs[2048 + c] * w;
            a2 += hs[4096 + c] * w; a3 += hs[6144 + c] * w;
        }
        resid[0][t] = a0 + xs[0][t];
        resid[1][t] = a1 + xs[1][t];
        resid[2][t] = a2 + xs[2][t];
        resid[3][t] = a3 + xs[3][t];
    }
    __syncthreads();
    int warp = t >> 5, lane = t & 31;
    if (warp < 4) {
        int row = warp;
        float v0 = resid[row][lane], v1 = resid[row][lane + 32];
        float v2 = resid[row][lane + 64], v3 = resid[row][lane + 96];
        float sum = warp_sum(v0 + v1 + v2 + v3);
        float sq = warp_sum(v0 * v0 + v1 * v1 + v2 * v2 + v3 * v3);
        float mean = sum * (1.f / 128.f);
        float rs = rsqrtf(sq * (1.f / 128.f) - mean * mean + LN_EPS);
        out_x[(r0 + row) * 128 + lane]      = (v0 - mean) * rs * g3[lane]      + b3[lane];
        out_x[(r0 + row) * 128 + lane + 32] = (v1 - mean) * rs * g3[lane + 32] + b3[lane + 32];
        out_x[(r0 + row) * 128 + lane + 64] = (v2 - mean) * rs * g3[lane + 64] + b3[lane + 64];
        out_x[(r0 + row) * 128 + lane + 96] = (v3 - mean) * rs * g3[lane + 96] + b3[lane + 96];
    }
}

extern "C" void kernel_launch(void* const* d_in, const int* in_sizes, int n_in,
                              void* d_out, int out_size) {
    (void)in_sizes; (void)n_in; (void)out_size;
    const float* node     = (const float*)d_in[0];
    const float* edge     = (const float*)d_in[1];
    const unsigned char* mask = (const unsigned char*)d_in[2];
    const float* w_mem_e  = (const float*)d_in[3];
    const float* w_mem_s  = (const float*)d_in[4];
    const float* w_mem_t  = (const float*)d_in[5];
    const float* b_mem    = (const float*)d_in[6];
    const float* g_ln_mem = (const float*)d_in[7];
    const float* b_ln_mem = (const float*)d_in[8];
    const float* w_pe     = (const float*)d_in[9];
    const float* b_pe     = (const float*)d_in[10];
    const float* g_ln_pe  = (const float*)d_in[11];
    const float* b_ln_pe  = (const float*)d_in[12];
    const float* g_ln_edge= (const float*)d_in[13];
    const float* b_ln_edge= (const float*)d_in[14];
    const float* wq       = (const float*)d_in[15];
    const float* bq       = (const float*)d_in[16];
    const float* wk       = (const float*)d_in[17];
    /* bk (d_in[18]) provably drops out of softmax */
    const float* wv       = (const float*)d_in[19];
    const float* bv       = (const float*)d_in[20];
    const float* wo       = (const float*)d_in[21];
    const float* bo       = (const float*)d_in[22];
    const float* g_ln2    = (const float*)d_in[23];
    const float* b_ln2    = (const float*)d_in[24];
    const float* w_ff1    = (const float*)d_in[25];
    const float* b_ff1    = (const float*)d_in[26];
    const float* w_ff2    = (const float*)d_in[27];
    const float* b_ff2    = (const float*)d_in[28];
    const float* g_ln3    = (const float*)d_in[29];
    const float* b_ln3    = (const float*)d_in[30];

    float* out_x = (float*)d_out;
    float* out_edge = (float*)d_out + NSEQ * DMODEL;

    k_pre<<<dim3(512, 3), 128>>>(node, w_mem_s, b_mem, w_mem_t, wq, bq);
    k_qh<<<512, 128>>>(wk);
    k_mem<<<2048, 256>>>(edge, w_mem_e, g_ln_mem, b_ln_mem);
    k_edge<<<2048, 256>>>(edge, w_pe, b_pe, g_ln_pe, b_ln_pe, g_ln_edge, b_ln_edge, out_edge);
    k_attn<<<512, 256>>>(mask, wv, bv);
    k_out1<<<512, 128>>>(node, wo, bo, g_ln2, b_ln2);
    k_ffn<<<128, 256>>>(w_ff1, b_ff1, w_ff2, b_ff2, g_ln3, b_ln3, out_x);
}

// round 3
// speedup vs baseline: 1.3253x; 1.3253x over previous
#include <cuda_runtime.h>
#include <cuda_bf16.h>
#include <cstdint>

#define NSEQ 512
#define DMODEL 128
#define LN_EPS 1e-5f

// ---- scratch (device globals; no runtime allocation) ----
__device__ float g_mem[(size_t)NSEQ * NSEQ * DMODEL];   // memory tensor (s, n, d)
__device__ float g_ns[NSEQ * DMODEL];
__device__ float g_nt[NSEQ * DMODEL];
__device__ float g_q[NSEQ * DMODEL];
__device__ float g_qh[NSEQ * 1024];                     // [n][h][c]
__device__ float g_ctx[NSEQ * DMODEL];
__device__ float g_x1[NSEQ * DMODEL];
__device__ float g_scoresT[(size_t)NSEQ * 8 * NSEQ];    // [n][h][s]
__device__ float g_attnT[(size_t)NSEQ * NSEQ * 8];      // [s][n][h]
__device__ float g_rpart[4 * (size_t)NSEQ * 8 * DMODEL];// [chunk][n][h][c]

__device__ __forceinline__ float warp_sum(float v) {
#pragma unroll
    for (int o = 16; o; o >>= 1) v += __shfl_xor_sync(0xffffffffu, v, o);
    return v;
}
__device__ __forceinline__ float warp_max(float v) {
#pragma unroll
    for (int o = 16; o; o >>= 1) v = fmaxf(v, __shfl_xor_sync(0xffffffffu, v, o));
    return v;
}

// bf16 m16n8k16 mma, fp32 accum (sm_80+; arch-neutral, no tcgen05)
__device__ __forceinline__ void mma_bf16(float* c, const uint32_t* a, const uint32_t* b) {
    asm volatile(
        "mma.sync.aligned.m16n8k16.row.col.f32.bf16.bf16.f32 "
        "{%0,%1,%2,%3}, {%4,%5,%6,%7}, {%8,%9}, {%0,%1,%2,%3};"
        : "+f"(c[0]), "+f"(c[1]), "+f"(c[2]), "+f"(c[3])
        : "r"(a[0]), "r"(a[1]), "r"(a[2]), "r"(a[3]), "r"(b[0]), "r"(b[1]));
}
// pack two floats (lo-half = a, hi-half = b) as bf16x2 (round-to-nearest)
__device__ __forceinline__ uint32_t pack_bf2(float a, float b) {
    __nv_bfloat162 p = __floats2bfloat162_rn(a, b);
    return *(uint32_t*)&p;
}

// ============ small precompute: ns, nt, q ============
__global__ void k_pre(const float* __restrict__ node,
                      const float* __restrict__ w_mem_s, const float* __restrict__ b_mem,
                      const float* __restrict__ w_mem_t,
                      const float* __restrict__ wq, const float* __restrict__ bq) {
    int row = blockIdx.x, which = blockIdx.y, d = threadIdx.x;
    __shared__ float xs[DMODEL];
    xs[d] = node[row * DMODEL + d];
    __syncthreads();
    const float* W = (which == 0) ? w_mem_s : (which == 1) ? w_mem_t : wq;
    float acc = (which == 0) ? b_mem[d] : (which == 2) ? bq[d] : 0.f;
#pragma unroll 4
    for (int c = 0; c < DMODEL; c++) acc += xs[c] * W[c * DMODEL + d];
    float* out = (which == 0) ? g_ns : (which == 1) ? g_nt : g_q;
    out[row * DMODEL + d] = acc;
}

// qh[n][h][c] = sum_dh wk[c, h*16+dh] * q[n, h*16+dh] * 0.25  (bk drops out of softmax)
__global__ void k_qh(const float* __restrict__ wk) {
    int n = blockIdx.x, c = threadIdx.x;
    __shared__ float qs[DMODEL];
    qs[c] = g_q[n * DMODEL + c];
    __syncthreads();
    const float* wrow = wk + c * DMODEL;
#pragma unroll
    for (int h = 0; h < 8; h++) {
        float a = 0.f;
#pragma unroll
        for (int dh = 0; dh < 16; dh++) a += wrow[h * 16 + dh] * qs[h * 16 + dh];
        g_qh[n * 1024 + h * 128 + c] = a * 0.25f;
    }
}

// ============ bf16x3 tensor-core GEMM: 128x128 tile, K=128 ============
// smem: Ah u32[128][68], Al u32[128][68], Bh u32[64][132], Bl u32[64][132], Dst f32[128][132]
#define OFF_AL 34816
#define OFF_BH 69632
#define OFF_BL 103424
#define OFF_D  137216
#define GSMEM  204800

// mode 0: g_mem = relu(LN(edge @ W + ns[n] + nt[s]))
// mode 1: outp  = LN(edge + relu(LN(g_mem @ W + bpe)))
__global__ __launch_bounds__(256) void k_gemm(
    const float* __restrict__ Asrc, const float* __restrict__ W, int mode,
    const float* __restrict__ gA, const float* __restrict__ bA,
    const float* __restrict__ res_in, const float* __restrict__ bpe,
    const float* __restrict__ gB, const float* __restrict__ bB,
    float* __restrict__ outp) {
    extern __shared__ char sm[];
    uint32_t* Ah = (uint32_t*)sm;
    uint32_t* Al = (uint32_t*)(sm + OFF_AL);
    uint32_t* Bh = (uint32_t*)(sm + OFF_BH);
    uint32_t* Bl = (uint32_t*)(sm + OFF_BL);
    float*   Dst = (float*)(sm + OFF_D);
    const int t = threadIdx.x;
    const float* Abase = mode ? (const float*)g_mem : Asrc;
    const float* At = Abase + (size_t)blockIdx.x * 16384;

    // ---- convert B (weight 128x128, [k][n] row-major) to packed bf16 hi/lo ----
#pragma unroll
    for (int j = 0; j < 32; j++) {
        int e = t + j * 256;            // 8192 k-pairs*n
        int kp = e >> 7, n = e & 127;
        float a = W[(2 * kp) * 128 + n];
        float b = W[(2 * kp + 1) * 128 + n];
        uint32_t ab = __float_as_uint(a), bb = __float_as_uint(b);
        Bh[kp * 132 + n] = (bb & 0xFFFF0000u) | (ab >> 16);
        float la = a - __uint_as_float(ab & 0xFFFF0000u);
        float lb = b - __uint_as_float(bb & 0xFFFF0000u);
        Bl[kp * 132 + n] = pack_bf2(la, lb);
    }
    // ---- load+convert A tile (128 rows x 128 k) ----
#pragma unroll
    for (int j = 0; j < 16; j++) {
        int idx = t + j * 256;          // 4096 float4s
        int row = idx >> 5, c4 = (idx & 31) * 4;
        float4 v = *(const float4*)(At + row * 128 + c4);
        int kp = c4 >> 1;
        uint32_t x = __float_as_uint(v.x), y = __float_as_uint(v.y);
        uint32_t z = __float_as_uint(v.z), w = __float_as_uint(v.w);
        uint32_t h0 = (y & 0xFFFF0000u) | (x >> 16);
        uint32_t h1 = (w & 0xFFFF0000u) | (z >> 16);
        float lx = v.x - __uint_as_float(x & 0xFFFF0000u);
        float ly = v.y - __uint_as_float(y & 0xFFFF0000u);
        float lz = v.z - __uint_as_float(z & 0xFFFF0000u);
        float lw = v.w - __uint_as_float(w & 0xFFFF0000u);
        *(uint2*)&Ah[row * 68 + kp] = make_uint2(h0, h1);
        *(uint2*)&Al[row * 68 + kp] = make_uint2(pack_bf2(lx, ly), pack_bf2(lz, lw));
    }
    __syncthreads();

    // ---- MMA: 8 warps, warp tile 64(m) x 32(n) ----
    const int w = t >> 5, lane = t & 31;
    const int wm = w >> 2, wn = w & 3;
    const int gid = lane >> 2, lid = lane & 3;
    float acc[4][4][4];
#pragma unroll
    for (int mt = 0; mt < 4; mt++)
#pragma unroll
        for (int nt = 0; nt < 4; nt++)
#pragma unroll
            for (int q = 0; q < 4; q++) acc[mt][nt][q] = 0.f;

#pragma unroll
    for (int ks = 0; ks < 8; ks++) {
        const int kb = ks * 8;
        uint32_t a_h[4][4], a_l[4][4], b_h[4][2], b_l[4][2];
#pragma unroll
        for (int mt = 0; mt < 4; mt++) {
            int r = wm * 64 + mt * 16 + gid;
            a_h[mt][0] = Ah[r * 68 + kb + lid];
            a_h[mt][1] = Ah[(r + 8) * 68 + kb + lid];
            a_h[mt][2] = Ah[r * 68 + kb + lid + 4];
            a_h[mt][3] = Ah[(r + 8) * 68 + kb + lid + 4];
            a_l[mt][0] = Al[r * 68 + kb + lid];
            a_l[mt][1] = Al[(r + 8) * 68 + kb + lid];
            a_l[mt][2] = Al[r * 68 + kb + lid + 4];
            a_l[mt][3] = Al[(r + 8) * 68 + kb + lid + 4];
        }
#pragma unroll
        for (int nt = 0; nt < 4; nt++) {
            int n = wn * 32 + nt * 8 + gid;
            b_h[nt][0] = Bh[(kb + lid) * 132 + n];
            b_h[nt][1] = Bh[(kb + lid + 4) * 132 + n];
            b_l[nt][0] = Bl[(kb + lid) * 132 + n];
            b_l[nt][1] = Bl[(kb + lid + 4) * 132 + n];
        }
#pragma unroll
        for (int mt = 0; mt < 4; mt++)
#pragma unroll
            for (int nt = 0; nt < 4; nt++) {
                mma_bf16(acc[mt][nt], a_h[mt], b_h[nt]);
                mma_bf16(acc[mt][nt], a_h[mt], b_l[nt]);
                mma_bf16(acc[mt][nt], a_l[mt], b_h[nt]);
            }
    }

    // ---- stage D to smem ----
#pragma unroll
    for (int mt = 0; mt < 4; mt++)
#pragma unroll
        for (int nt = 0; nt < 4; nt++) {
            int r = wm * 64 + mt * 16 + gid;
            int c = wn * 32 + nt * 8 + lid * 2;
            *(float2*)&Dst[r * 132 + c] = make_float2(acc[mt][nt][0], acc[mt][nt][1]);
            *(float2*)&Dst[(r + 8) * 132 + c] = make_float2(acc[mt][nt][2], acc[mt][nt][3]);
        }
    __syncthreads();

    // ---- fused LN epilogue: warp w handles rows w*16 .. w*16+15 ----
    const int c0 = lane * 4;
    if (mode == 0) {
        float4 g4 = *(const float4*)&gA[c0];
        float4 bb4 = *(const float4*)&bA[c0];
#pragma unroll
        for (int i = 0; i < 16; i++) {
            int tr = w * 16 + i;
            size_t rr = (size_t)blockIdx.x * 128 + tr;
            int nn = (int)(rr & 511), ssi = (int)(rr >> 9);
            float4 dv = *(float4*)&Dst[tr * 132 + c0];
            float4 a = *(const float4*)&g_ns[nn * 128 + c0];
            float4 b = *(const float4*)&g_nt[ssi * 128 + c0];
            float v0 = dv.x + a.x + b.x, v1 = dv.y + a.y + b.y;
            float v2 = dv.z + a.z + b.z, v3 = dv.w + a.w + b.w;
            float sum = warp_sum(v0 + v1 + v2 + v3);
            float sq  = warp_sum(v0 * v0 + v1 * v1 + v2 * v2 + v3 * v3);
            float mean = sum * (1.f / 128.f);
            float rs = rsqrtf(sq * (1.f / 128.f) - mean * mean + LN_EPS);
            float4 o;
            o.x = fmaxf((v0 - mean) * rs * g4.x + bb4.x, 0.f);
            o.y = fmaxf((v1 - mean) * rs * g4.y + bb4.y, 0.f);
            o.z = fmaxf((v2 - mean) * rs * g4.z + bb4.z, 0.f);
            o.w = fmaxf((v3 - mean) * rs * g4.w + bb4.w, 0.f);
            *(float4*)&g_mem[rr * 128 + c0] = o;
        }
    } else {
        float4 bp  = *(const float4*)&bpe[c0];
        float4 g1v = *(const float4*)&gA[c0];
        float4 b1v = *(const float4*)&bA[c0];
        float4 g2v = *(const float4*)&gB[c0];
        float4 b2v = *(const float4*)&bB[c0];
#pragma unroll
        for (int i = 0; i < 16; i++) {
            int tr = w * 16 + i;
            size_t rr = (size_t)blockIdx.x * 128 + tr;
            float4 dv = *(float4*)&Dst[tr * 132 + c0];
            float v0 = dv.x + bp.x, v1 = dv.y + bp.y;
            float v2 = dv.z + bp.z, v3 = dv.w + bp.w;
            float sum = warp_sum(v0 + v1 + v2 + v3);
            float sq  = warp_sum(v0 * v0 + v1 * v1 + v2 * v2 + v3 * v3);
            float mean = sum * (1.f / 128.f);
            float rs = rsqrtf(sq * (1.f / 128.f) - mean * mean + LN_EPS);
            float u0 = fmaxf((v0 - mean) * rs * g1v.x + b1v.x, 0.f);
            float u1 = fmaxf((v1 - mean) * rs * g1v.y + b1v.y, 0.f);
            float u2 = fmaxf((v2 - mean) * rs * g1v.z + b1v.z, 0.f);
            float u3 = fmaxf((v3 - mean) * rs * g1v.w + b1v.w, 0.f);
            float4 e = *(const float4*)&res_in[rr * 128 + c0];
            float w0 = e.x + u0, w1 = e.y + u1, w2 = e.z + u2, w3 = e.w + u3;
            float sum2 = warp_sum(w0 + w1 + w2 + w3);
            float sq2  = warp_sum(w0 * w0 + w1 * w1 + w2 * w2 + w3 * w3);
            float mean2 = sum2 * (1.f / 128.f);
            float rs2 = rsqrtf(sq2 * (1.f / 128.f) - mean2 * mean2 + LN_EPS);
            float4 o;
            o.x = (w0 - mean2) * rs2 * g2v.x + b2v.x;
            o.y = (w1 - mean2) * rs2 * g2v.y + b2v.y;
            o.z = (w2 - mean2) * rs2 * g2v.z + b2v.z;
            o.w = (w3 - mean2) * rs2 * g2v.w + b2v.w;
            *(float4*)&outp[rr * 128 + c0] = o;
        }
    }
}

// ============ attention ============
// scores[n][h][s] = sum_c memory[s,n,c] * qh[n][h][c]
__global__ __launch_bounds__(256) void k_scores(const unsigned char* __restrict__ mask) {
    int n = blockIdx.x, t = threadIdx.x;
    __shared__ float qh_s[1024];
    for (int i = t; i < 1024; i += 256) qh_s[i] = g_qh[n * 1024 + i];
    __syncthreads();
#pragma unroll
    for (int rep = 0; rep < 2; rep++) {
        int s = rep * 256 + t;
        const float* m = g_mem + ((size_t)s * 512 + n) * 128;
        float a[8];
#pragma unroll
        for (int h = 0; h < 8; h++) a[h] = 0.f;
#pragma unroll 8
        for (int c4 = 0; c4 < 32; c4++) {
            float4 mv = *(const float4*)(m + c4 * 4);
#pragma unroll
            for (int h = 0; h < 8; h++) {
                float4 q = *(const float4*)(qh_s + h * 128 + c4 * 4);
                a[h] += mv.x*q.x + mv.y*q.y + mv.z*q.z + mv.w*q.w;
            }
        }
        bool mk = mask[n * 512 + s] != 0;
        const float NEG = -3.402823466e38f;
#pragma unroll
        for (int h = 0; h < 8; h++)
            g_scoresT[((size_t)n * 8 + h) * 512 + s] = mk ? NEG : a[h];
    }
}

__global__ void k_softmax() {   // 512 blocks, 256 thr; warp = head
    int n = blockIdx.x, t = threadIdx.x, h = t >> 5, lane = t & 31;
    const float* row = g_scoresT + ((size_t)n * 8 + h) * 512;
    float mx = -3.402823466e38f;
#pragma unroll
    for (int i = 0; i < 16; i++) mx = fmaxf(mx, row[lane + i * 32]);
    mx = warp_max(mx);
    float e[16], sum = 0.f;
#pragma unroll
    for (int i = 0; i < 16; i++) { e[i] = __expf(row[lane + i * 32] - mx); sum += e[i]; }
    sum = warp_sum(sum);
    float inv = 1.f / sum;
#pragma unroll
    for (int i = 0; i < 16; i++)
        g_attnT[(size_t)(lane + i * 32) * 4096 + n * 8 + h] = e[i] * inv;
}

// r_part[chunk][n][h][c] = sum_{s in chunk} attn[s,n,h] * memory[s,n,c]
__global__ __launch_bounds__(256) void k_wsum() {
    int n0 = blockIdx.x * 16, chunk = blockIdx.y;
    int t = threadIdx.x, nl = t >> 4, cg = t & 15, c0 = cg * 8;
    __shared__ float a_s[8 * 128];
    float acc[64];
#pragma unroll
    for (int i = 0; i < 64; i++) acc[i] = 0.f;
    for (int ts = 0; ts < 16; ts++) {
        int s0 = chunk * 128 + ts * 8;
        __syncthreads();
#pragma unroll
        for (int k = 0; k < 4; k++) {
            int i = t + k * 256;
            int sl = i >> 7, off = i & 127;
            a_s[i] = g_attnT[(size_t)(s0 + sl) * 4096 + n0 * 8 + off];
        }
        __syncthreads();
#pragma unroll
        for (int sl = 0; sl < 8; sl++) {
            const float* m = g_mem + ((size_t)(s0 + sl) * 512 + n0 + nl) * 128 + c0;
            float4 m0v = *(const float4*)m;
            float4 m1v = *(const float4*)(m + 4);
#pragma unroll
            for (int h = 0; h < 8; h++) {
                float a = a_s[sl * 128 + nl * 8 + h];
                acc[h*8+0] += a * m0v.x; acc[h*8+1] += a * m0v.y;
                acc[h*8+2] += a * m0v.z; acc[h*8+3] += a * m0v.w;
                acc[h*8+4] += a * m1v.x; acc[h*8+5] += a * m1v.y;
                acc[h*8+6] += a * m1v.z; acc[h*8+7] += a * m1v.w;
            }
        }
    }
    float* rp = g_rpart + (size_t)chunk * 524288 + ((size_t)(n0 + nl) * 8) * 128 + c0;
#pragma unroll
    for (int h = 0; h < 8; h++) {
        *(float4*)(rp + h * 128)     = make_float4(acc[h*8+0], acc[h*8+1], acc[h*8+2], acc[h*8+3]);
        *(float4*)(rp + h * 128 + 4) = make_float4(acc[h*8+4], acc[h*8+5], acc[h*8+6], acc[h*8+7]);
    }
}

// ctx[n,d] = sum_c r[n,h(d),c] * wv[c,d] + bv[d]   (sum attn = 1)
__global__ void k_ctx(const float* __restrict__ wv, const float* __restrict__ bv) {
    int n = blockIdx.x, d = threadIdx.x, h = d >> 4;
    const float* r0 = g_rpart + ((size_t)n * 8 + h) * 128;
    float a = bv[d];
#pragma unroll 4
    for (int c = 0; c < 128; c++) {
        float rv = r0[c] + r0[524288 + c] + r0[1048576 + c] + r0[1572864 + c];
        a += rv * wv[c * 128 + d];
    }
    g_ctx[n * 128 + d] = a;
}

// ============ x1 = LN(node + ctx @ wo + bo) ============
__global__ void k_out1(const float* __restrict__ node, const float* __restrict__ wo,
                       const float* __restrict__ bo, const float* __restrict__ g2,
                       const float* __restrict__ b2) {
    int row = blockIdx.x, d = threadIdx.x;
    __shared__ float cs[128];
    __shared__ float rsum[4], rsq[4];
    cs[d] = g_ctx[row * 128 + d];
    __syncthreads();
    float a = bo[d];
#pragma unroll 4
    for (int c = 0; c < 128; c++) a += cs[c] * wo[c * 128 + d];
    a += node[row * 128 + d];
    float s1 = warp_sum(a), s2 = warp_sum(a * a);
    if ((d & 31) == 0) { rsum[d >> 5] = s1; rsq[d >> 5] = s2; }
    __syncthreads();
    float sum = rsum[0] + rsum[1] + rsum[2] + rsum[3];
    float sq = rsq[0] + rsq[1] + rsq[2] + rsq[3];
    float mean = sum * (1.f / 128.f);
    float rs = rsqrtf(sq * (1.f / 128.f) - mean * mean + LN_EPS);
    g_x1[row * 128 + d] = (a - mean) * rs * g2[d] + b2[d];
}

// ============ FFN + final LN ============
__global__ __launch_bounds__(256) void k_ffn(
    const float* __restrict__ w1, const float* __restrict__ b1,
    const float* __restrict__ w2, const float* __restrict__ b2,
    const float* __restrict__ g3, const float* __restrict__ b3,
    float* __restrict__ out_x) {
    __shared__ float xs[4][128];
    __shared__ float hs[4 * 2048];
    __shared__ float resid[4][128];
    int t = threadIdx.x;
    int r0 = blockIdx.x * 4;
    for (int i = t; i < 512; i += 256) xs[i >> 7][i & 127] = g_x1[r0 * 128 + i];
    __syncthreads();
#pragma unroll
    for (int j = 0; j < 8; j++) {
        int col = t + j * 256;
        float bb = b1[col];
        float a0 = bb, a1 = bb, a2 = bb, a3 = bb;
#pragma unroll 4
        for (int c = 0; c < 128; c++) {
            float w = w1[c * 2048 + col];
            a0 += xs[0][c] * w; a1 += xs[1][c] * w;
            a2 += xs[2][c] * w; a3 += xs[3][c] * w;
        }
        hs[0 * 2048 + col] = fmaxf(a0, 0.f);
        hs[1 * 2048 + col] = fmaxf(a1, 0.f);
        hs[2 * 2048 + col] = fmaxf(a2, 0.f);
        hs[3 * 2048 + col] = fmaxf(a3, 0.f);
    }
    __syncthreads();
    if (t < 128) {
        float bb = b2[t];
        float a0 = bb, a1 = bb, a2 = bb, a3 = bb;
#pragma unroll 4
        for (int c = 0; c < 2048; c++) {
            float w = w2[c * 128 + t];
            a0 += hs[c] * w; a1 += hs[2048 + c] * w;
            a2 += hs[4096 + c] * w; a3 += hs[6144 + c] * w;
        }
        resid[0][t] = a0 + xs[0][t];
        resid[1][t] = a1 + xs[1][t];
        resid[2][t] = a2 + xs[2][t];
        resid[3][t] = a3 + xs[3][t];
    }
    __syncthreads();
    int warp = t >> 5, lane = t & 31;
    if (warp < 4) {
        int row = warp;
        float v0 = resid[row][lane], v1 = resid[row][lane + 32];
        float v2 = resid[row][lane + 64], v3 = resid[row][lane + 96];
        float sum = warp_sum(v0 + v1 + v2 + v3);
        float sq = warp_sum(v0 * v0 + v1 * v1 + v2 * v2 + v3 * v3);
        float mean = sum * (1.f / 128.f);
        float rs = rsqrtf(sq * (1.f / 128.f) - mean * mean + LN_EPS);
        out_x[(r0 + row) * 128 + lane]      = (v0 - mean) * rs * g3[lane]      + b3[lane];
        out_x[(r0 + row) * 128 + lane + 32] = (v1 - mean) * rs * g3[lane + 32] + b3[lane + 32];
        out_x[(r0 + row) * 128 + lane + 64] = (v2 - mean) * rs * g3[lane + 64] + b3[lane + 64];
        out_x[(r0 + row) * 128 + lane + 96] = (v3 - mean) * rs * g3[lane + 96] + b3[lane + 96];
    }
}

extern "C" void kernel_launch(void* const* d_in, const int* in_sizes, int n_in,
                              void* d_out, int out_size) {
    (void)in_sizes; (void)n_in; (void)out_size;
    const float* node     = (const float*)d_in[0];
    const float* edge     = (const float*)d_in[1];
    const unsigned char* mask = (const unsigned char*)d_in[2];
    const float* w_mem_e  = (const float*)d_in[3];
    const float* w_mem_s  = (const float*)d_in[4];
    const float* w_mem_t  = (const float*)d_in[5];
    const float* b_mem    = (const float*)d_in[6];
    const float* g_ln_mem = (const float*)d_in[7];
    const float* b_ln_mem = (const float*)d_in[8];
    const float* w_pe     = (const float*)d_in[9];
    const float* b_pe     = (const float*)d_in[10];
    const float* g_ln_pe  = (const float*)d_in[11];
    const float* b_ln_pe  = (const float*)d_in[12];
    const float* g_ln_edge= (const float*)d_in[13];
    const float* b_ln_edge= (const float*)d_in[14];
    const float* wq       = (const float*)d_in[15];
    const float* bq       = (const float*)d_in[16];
    const float* wk       = (const float*)d_in[17];
    /* bk (d_in[18]) provably drops out of softmax */
    const float* wv       = (const float*)d_in[19];
    const float* bv       = (const float*)d_in[20];
    const float* wo       = (const float*)d_in[21];
    const float* bo       = (const float*)d_in[22];
    const float* g_ln2    = (const float*)d_in[23];
    const float* b_ln2    = (const float*)d_in[24];
    const float* w_ff1    = (const float*)d_in[25];
    const float* b_ff1    = (const float*)d_in[26];
    const float* w_ff2    = (const float*)d_in[27];
    const float* b_ff2    = (const float*)d_in[28];
    const float* g_ln3    = (const float*)d_in[29];
    const float* b_ln3    = (const float*)d_in[30];

    float* out_x = (float*)d_out;
    float* out_edge = (float*)d_out + NSEQ * DMODEL;

    static int smem_set = 0;
    if (!smem_set) {
        cudaFuncSetAttribute(k_gemm, cudaFuncAttributeMaxDynamicSharedMemorySize, GSMEM);
        smem_set = 1;
    }

    k_pre<<<dim3(512, 3), 128>>>(node, w_mem_s, b_mem, w_mem_t, wq, bq);
    k_qh<<<512, 128>>>(wk);
    // memory = relu(LN(edge @ w_mem_e + ns + nt))
    k_gemm<<<2048, 256, GSMEM>>>(edge, w_mem_e, 0, g_ln_mem, b_ln_mem,
                                 nullptr, nullptr, nullptr, nullptr, nullptr);
    // edge_new = LN(edge + relu(LN(memory @ w_pe + b_pe)))
    k_gemm<<<2048, 256, GSMEM>>>(nullptr, w_pe, 1, g_ln_pe, b_ln_pe,
                                 edge, b_pe, g_ln_edge, b_ln_edge, out_edge);
    k_scores<<<512, 256>>>(mask);
    k_softmax<<<512, 256>>>();
    k_wsum<<<dim3(32, 4), 256>>>();
    k_ctx<<<512, 128>>>(wv, bv);
    k_out1<<<512, 128>>>(node, wo, bo, g_ln2, b_ln2);
    k_ffn<<<128, 256>>>(w_ff1, b_ff1, w_ff2, b_ff2, g_ln3, b_ln3, out_x);
}

// round 4
// speedup vs baseline: 1.4102x; 1.0641x over previous
#include <cuda_runtime.h>
#include <cuda_bf16.h>
#include <cuda_fp16.h>
#include <cstdint>

#define NSEQ 512
#define DMODEL 128
#define LN_EPS 1e-5f

// ---- scratch (device globals; no runtime allocation) ----
__device__ float g_mem[(size_t)NSEQ * NSEQ * DMODEL];   // memory tensor (s, n, d)
__device__ float g_ns[NSEQ * DMODEL];
__device__ float g_nt[NSEQ * DMODEL];
__device__ float g_q[NSEQ * DMODEL];
__device__ float g_qh[NSEQ * 1024];                     // [n][h][c]
__device__ float g_ctx[NSEQ * DMODEL];
__device__ float g_x1[NSEQ * DMODEL];

__device__ __forceinline__ float warp_sum(float v) {
#pragma unroll
    for (int o = 16; o; o >>= 1) v += __shfl_xor_sync(0xffffffffu, v, o);
    return v;
}
__device__ __forceinline__ float warp_max(float v) {
#pragma unroll
    for (int o = 16; o; o >>= 1) v = fmaxf(v, __shfl_xor_sync(0xffffffffu, v, o));
    return v;
}

// bf16 m16n8k16 mma, fp32 accum (sm_80+; arch-neutral)
__device__ __forceinline__ void mma_bf16(float* c, const uint32_t* a, const uint32_t* b) {
    asm volatile(
        "mma.sync.aligned.m16n8k16.row.col.f32.bf16.bf16.f32 "
        "{%0,%1,%2,%3}, {%4,%5,%6,%7}, {%8,%9}, {%0,%1,%2,%3};"
        : "+f"(c[0]), "+f"(c[1]), "+f"(c[2]), "+f"(c[3])
        : "r"(a[0]), "r"(a[1]), "r"(a[2]), "r"(a[3]), "r"(b[0]), "r"(b[1]));
}
__device__ __forceinline__ uint32_t pack_bf2(float a, float b) {
    __nv_bfloat162 p = __floats2bfloat162_rn(a, b);
    return *(uint32_t*)&p;
}

// ============ small precompute: ns, nt, q ============
__global__ void k_pre(const float* __restrict__ node,
                      const float* __restrict__ w_mem_s, const float* __restrict__ b_mem,
                      const float* __restrict__ w_mem_t,
                      const float* __restrict__ wq, const float* __restrict__ bq) {
    int row = blockIdx.x, which = blockIdx.y, d = threadIdx.x;
    __shared__ float xs[DMODEL];
    xs[d] = node[row * DMODEL + d];
    __syncthreads();
    const float* W = (which == 0) ? w_mem_s : (which == 1) ? w_mem_t : wq;
    float acc = (which == 0) ? b_mem[d] : (which == 2) ? bq[d] : 0.f;
#pragma unroll 4
    for (int c = 0; c < DMODEL; c++) acc += xs[c] * W[c * DMODEL + d];
    float* out = (which == 0) ? g_ns : (which == 1) ? g_nt : g_q;
    out[row * DMODEL + d] = acc;
}

// qh[n][h][c] = sum_dh wk[c, h*16+dh] * q[n, h*16+dh] * 0.25  (bk drops out of softmax)
__global__ void k_qh(const float* __restrict__ wk) {
    int n = blockIdx.x, c = threadIdx.x;
    __shared__ float qs[DMODEL];
    qs[c] = g_q[n * DMODEL + c];
    __syncthreads();
    const float* wrow = wk + c * DMODEL;
#pragma unroll
    for (int h = 0; h < 8; h++) {
        float a = 0.f;
#pragma unroll
        for (int dh = 0; dh < 16; dh++) a += wrow[h * 16 + dh] * qs[h * 16 + dh];
        g_qh[n * 1024 + h * 128 + c] = a * 0.25f;
    }
}

// ============ bf16x3 tensor-core GEMM, K split into 2 chunks, 2 CTAs/SM ============
// smem: Ah u32[128][36], Al u32[128][36], Bh u32[64][132], Bl u32[64][132], ps/pq f32[128][4]
#define AH_OFF 0
#define AL_OFF 18432
#define BH_OFF 36864
#define BL_OFF 70656
#define PS_OFF 104448
#define PQ_OFF 106496
#define GSMEM  108544

__device__ __forceinline__ void load_achunk(const float* __restrict__ At, int coff,
                                            uint32_t* Ah, uint32_t* Al, int t) {
#pragma unroll
    for (int j = 0; j < 8; j++) {
        int idx = t + j * 256;
        int row = idx >> 4, c4 = (idx & 15) * 4;
        float4 v = *(const float4*)(At + row * 128 + coff + c4);
        uint32_t x = __float_as_uint(v.x), y = __float_as_uint(v.y);
        uint32_t z = __float_as_uint(v.z), w = __float_as_uint(v.w);
        uint32_t h0 = (y & 0xFFFF0000u) | (x >> 16);
        uint32_t h1 = (w & 0xFFFF0000u) | (z >> 16);
        float lx = v.x - __uint_as_float(x & 0xFFFF0000u);
        float ly = v.y - __uint_as_float(y & 0xFFFF0000u);
        float lz = v.z - __uint_as_float(z & 0xFFFF0000u);
        float lw = v.w - __uint_as_float(w & 0xFFFF0000u);
        int kp = c4 >> 1;
        *(uint2*)&Ah[row * 36 + kp] = make_uint2(h0, h1);
        *(uint2*)&Al[row * 36 + kp] = make_uint2(pack_bf2(lx, ly), pack_bf2(lz, lw));
    }
}

// mode 0: g_mem = relu(LN(edge @ W + ns[n] + nt[s]))
// mode 1: outp  = LN(edge + relu(LN(g_mem @ W + bpe)))
__global__ __launch_bounds__(256, 2) void k_gemm(
    const float* __restrict__ Asrc, const float* __restrict__ W, int mode,
    const float* __restrict__ gA, const float* __restrict__ bA,
    const float* __restrict__ res_in, const float* __restrict__ bpe,
    const float* __restrict__ gB, const float* __restrict__ bB,
    float* __restrict__ outp) {
    extern __shared__ char sm[];
    uint32_t* Ah = (uint32_t*)(sm + AH_OFF);
    uint32_t* Al = (uint32_t*)(sm + AL_OFF);
    uint32_t* Bh = (uint32_t*)(sm + BH_OFF);
    uint32_t* Bl = (uint32_t*)(sm + BL_OFF);
    float* ps = (float*)(sm + PS_OFF);
    float* pq = (float*)(sm + PQ_OFF);
    const int t = threadIdx.x;
    const float* Abase = mode ? (const float*)g_mem : Asrc;
    const float* At = Abase + (size_t)blockIdx.x * 16384;

    // ---- convert B (weight 128x128 [k][n]) to packed bf16 hi/lo ----
#pragma unroll
    for (int j = 0; j < 32; j++) {
        int e = t + j * 256;
        int kp = e >> 7, n = e & 127;
        float a = W[(2 * kp) * 128 + n];
        float b = W[(2 * kp + 1) * 128 + n];
        uint32_t ab = __float_as_uint(a), bb = __float_as_uint(b);
        Bh[kp * 132 + n] = (bb & 0xFFFF0000u) | (ab >> 16);
        float la = a - __uint_as_float(ab & 0xFFFF0000u);
        float lb = b - __uint_as_float(bb & 0xFFFF0000u);
        Bl[kp * 132 + n] = pack_bf2(la, lb);
    }
    load_achunk(At, 0, Ah, Al, t);
    __syncthreads();

    const int w = t >> 5, lane = t & 31;
    const int wm = w >> 2, wn = w & 3;
    const int gid = lane >> 2, lid = lane & 3;
    float acc[4][4][4];
#pragma unroll
    for (int mt = 0; mt < 4; mt++)
#pragma unroll
        for (int nt = 0; nt < 4; nt++)
#pragma unroll
            for (int q = 0; q < 4; q++) acc[mt][nt][q] = 0.f;

#pragma unroll
    for (int chunk = 0; chunk < 2; chunk++) {
#pragma unroll
        for (int ks2 = 0; ks2 < 4; ks2++) {
            const int kbA = ks2 * 8, kbB = chunk * 32 + ks2 * 8;
            uint32_t a_h[4][4], a_l[4][4], b_h[4][2], b_l[4][2];
#pragma unroll
            for (int mt = 0; mt < 4; mt++) {
                int r = wm * 64 + mt * 16 + gid;
                a_h[mt][0] = Ah[r * 36 + kbA + lid];
                a_h[mt][1] = Ah[(r + 8) * 36 + kbA + lid];
                a_h[mt][2] = Ah[r * 36 + kbA + lid + 4];
                a_h[mt][3] = Ah[(r + 8) * 36 + kbA + lid + 4];
                a_l[mt][0] = Al[r * 36 + kbA + lid];
                a_l[mt][1] = Al[(r + 8) * 36 + kbA + lid];
                a_l[mt][2] = Al[r * 36 + kbA + lid + 4];
                a_l[mt][3] = Al[(r + 8) * 36 + kbA + lid + 4];
            }
#pragma unroll
            for (int nt = 0; nt < 4; nt++) {
                int n = wn * 32 + nt * 8 + gid;
                b_h[nt][0] = Bh[(kbB + lid) * 132 + n];
                b_h[nt][1] = Bh[(kbB + lid + 4) * 132 + n];
                b_l[nt][0] = Bl[(kbB + lid) * 132 + n];
                b_l[nt][1] = Bl[(kbB + lid + 4) * 132 + n];
            }
#pragma unroll
            for (int mt = 0; mt < 4; mt++)
#pragma unroll
                for (int nt = 0; nt < 4; nt++) {
                    mma_bf16(acc[mt][nt], a_h[mt], b_h[nt]);
                    mma_bf16(acc[mt][nt], a_h[mt], b_l[nt]);
                    mma_bf16(acc[mt][nt], a_l[mt], b_h[nt]);
                }
        }
        __syncthreads();
        if (chunk == 0) { load_achunk(At, 64, Ah, Al, t); __syncthreads(); }
    }

    // ---- register epilogue ----
    int cc[4];
#pragma unroll
    for (int nt = 0; nt < 4; nt++) cc[nt] = wn * 32 + nt * 8 + lid * 2;

    if (mode == 0) {
        const int s_tile = blockIdx.x >> 2, nbase = (blockIdx.x & 3) * 128;
        // add ns[n] + nt[s]
#pragma unroll
        for (int nt = 0; nt < 4; nt++) {
            float2 ntv = *(const float2*)&g_nt[s_tile * 128 + cc[nt]];
#pragma unroll
            for (int mt = 0; mt < 4; mt++) {
                int r0 = wm * 64 + mt * 16 + gid;
                float2 n0 = *(const float2*)&g_ns[(nbase + r0) * 128 + cc[nt]];
                float2 n1 = *(const float2*)&g_ns[(nbase + r0 + 8) * 128 + cc[nt]];
                acc[mt][nt][0] += n0.x + ntv.x; acc[mt][nt][1] += n0.y + ntv.y;
                acc[mt][nt][2] += n1.x + ntv.x; acc[mt][nt][3] += n1.y + ntv.y;
            }
        }
        // row partial sums
        float s8[8], q8[8];
#pragma unroll
        for (int mt = 0; mt < 4; mt++) {
            float sl = 0, ql = 0, sh = 0, qh = 0;
#pragma unroll
            for (int nt = 0; nt < 4; nt++) {
                sl += acc[mt][nt][0] + acc[mt][nt][1];
                ql += acc[mt][nt][0]*acc[mt][nt][0] + acc[mt][nt][1]*acc[mt][nt][1];
                sh += acc[mt][nt][2] + acc[mt][nt][3];
                qh += acc[mt][nt][2]*acc[mt][nt][2] + acc[mt][nt][3]*acc[mt][nt][3];
            }
            s8[mt*2] = sl; q8[mt*2] = ql; s8[mt*2+1] = sh; q8[mt*2+1] = qh;
        }
#pragma unroll
        for (int i = 0; i < 8; i++) {
            s8[i] += __shfl_xor_sync(0xffffffffu, s8[i], 1);
            s8[i] += __shfl_xor_sync(0xffffffffu, s8[i], 2);
            q8[i] += __shfl_xor_sync(0xffffffffu, q8[i], 1);
            q8[i] += __shfl_xor_sync(0xffffffffu, q8[i], 2);
        }
        if (lid == 0) {
#pragma unroll
            for (int mt = 0; mt < 4; mt++) {
                int r0 = wm * 64 + mt * 16 + gid;
                ps[r0 * 4 + wn] = s8[mt*2];  pq[r0 * 4 + wn] = q8[mt*2];
                ps[(r0+8)*4 + wn] = s8[mt*2+1]; pq[(r0+8)*4 + wn] = q8[mt*2+1];
            }
        }
        __syncthreads();
        float mean[8], rstd[8];
#pragma unroll
        for (int mt = 0; mt < 4; mt++) {
#pragma unroll
            for (int hh = 0; hh < 2; hh++) {
                int r = wm * 64 + mt * 16 + gid + hh * 8;
                float4 a = *(float4*)&ps[r * 4];
                float4 b = *(float4*)&pq[r * 4];
                float m = (a.x + a.y + a.z + a.w) * (1.f/128.f);
                float v = (b.x + b.y + b.z + b.w) * (1.f/128.f) - m * m;
                mean[mt*2+hh] = m; rstd[mt*2+hh] = rsqrtf(v + LN_EPS);
            }
        }
        float* orow = g_mem + (size_t)blockIdx.x * 16384;
#pragma unroll
        for (int nt = 0; nt < 4; nt++) {
            float2 gv = *(const float2*)&gA[cc[nt]];
            float2 bv2 = *(const float2*)&bA[cc[nt]];
#pragma unroll
            for (int mt = 0; mt < 4; mt++) {
                int r0 = wm * 64 + mt * 16 + gid;
                float2 o0, o1;
                o0.x = fmaxf((acc[mt][nt][0]-mean[mt*2])*rstd[mt*2]*gv.x + bv2.x, 0.f);
                o0.y = fmaxf((acc[mt][nt][1]-mean[mt*2])*rstd[mt*2]*gv.y + bv2.y, 0.f);
                o1.x = fmaxf((acc[mt][nt][2]-mean[mt*2+1])*rstd[mt*2+1]*gv.x + bv2.x, 0.f);
                o1.y = fmaxf((acc[mt][nt][3]-mean[mt*2+1])*rstd[mt*2+1]*gv.y + bv2.y, 0.f);
                *(float2*)&orow[r0 * 128 + cc[nt]] = o0;
                *(float2*)&orow[(r0 + 8) * 128 + cc[nt]] = o1;
            }
        }
    } else {
        // v = acc + bpe
#pragma unroll
        for (int nt = 0; nt < 4; nt++) {
            float2 bp = *(const float2*)&bpe[cc[nt]];
#pragma unroll
            for (int mt = 0; mt < 4; mt++) {
                acc[mt][nt][0] += bp.x; acc[mt][nt][1] += bp.y;
                acc[mt][nt][2] += bp.x; acc[mt][nt][3] += bp.y;
            }
        }
        // ---- reduction 1 ----
        float s8[8], q8[8];
#pragma unroll
        for (int mt = 0; mt < 4; mt++) {
            float sl = 0, ql = 0, sh = 0, qh = 0;
#pragma unroll
            for (int nt = 0; nt < 4; nt++) {
                sl += acc[mt][nt][0] + acc[mt][nt][1];
                ql += acc[mt][nt][0]*acc[mt][nt][0] + acc[mt][nt][1]*acc[mt][nt][1];
                sh += acc[mt][nt][2] + acc[mt][nt][3];
                qh += acc[mt][nt][2]*acc[mt][nt][2] + acc[mt][nt][3]*acc[mt][nt][3];
            }
            s8[mt*2] = sl; q8[mt*2] = ql; s8[mt*2+1] = sh; q8[mt*2+1] = qh;
        }
#pragma unroll
        for (int i = 0; i < 8; i++) {
            s8[i] += __shfl_xor_sync(0xffffffffu, s8[i], 1);
            s8[i] += __shfl_xor_sync(0xffffffffu, s8[i], 2);
            q8[i] += __shfl_xor_sync(0xffffffffu, q8[i], 1);
            q8[i] += __shfl_xor_sync(0xffffffffu, q8[i], 2);
        }
        if (lid == 0) {
#pragma unroll
            for (int mt = 0; mt < 4; mt++) {
                int r0 = wm * 64 + mt * 16 + gid;
                ps[r0 * 4 + wn] = s8[mt*2];  pq[r0 * 4 + wn] = q8[mt*2];
                ps[(r0+8)*4 + wn] = s8[mt*2+1]; pq[(r0+8)*4 + wn] = q8[mt*2+1];
            }
        }
        __syncthreads();
        float mean[8], rstd[8];
#pragma unroll
        for (int mt = 0; mt < 4; mt++) {
#pragma unroll
            for (int hh = 0; hh < 2; hh++) {
                int r = wm * 64 + mt * 16 + gid + hh * 8;
                float4 a = *(float4*)&ps[r * 4];
                float4 b = *(float4*)&pq[r * 4];
                float m = (a.x + a.y + a.z + a.w) * (1.f/128.f);
                float v = (b.x + b.y + b.z + b.w) * (1.f/128.f) - m * m;
                mean[mt*2+hh] = m; rstd[mt*2+hh] = rsqrtf(v + LN_EPS);
            }
        }
        // u = relu(LN1), w = edge + u  (overwrite acc)
        const float* erow = res_in + (size_t)blockIdx.x * 16384;
#pragma unroll
        for (int nt = 0; nt < 4; nt++) {
            float2 g1 = *(const float2*)&gA[cc[nt]];
            float2 b1 = *(const float2*)&bA[cc[nt]];
#pragma unroll
            for (int mt = 0; mt < 4; mt++) {
                int r0 = wm * 64 + mt * 16 + gid;
                float2 e0 = *(const float2*)&erow[r0 * 128 + cc[nt]];
                float2 e1 = *(const float2*)&erow[(r0 + 8) * 128 + cc[nt]];
                acc[mt][nt][0] = e0.x + fmaxf((acc[mt][nt][0]-mean[mt*2])*rstd[mt*2]*g1.x + b1.x, 0.f);
                acc[mt][nt][1] = e0.y + fmaxf((acc[mt][nt][1]-mean[mt*2])*rstd[mt*2]*g1.y + b1.y, 0.f);
                acc[mt][nt][2] = e1.x + fmaxf((acc[mt][nt][2]-mean[mt*2+1])*rstd[mt*2+1]*g1.x + b1.x, 0.f);
                acc[mt][nt][3] = e1.y + fmaxf((acc[mt][nt][3]-mean[mt*2+1])*rstd[mt*2+1]*g1.y + b1.y, 0.f);
            }
        }
        __syncthreads();   // protect ps/pq reuse
        // ---- reduction 2 ----
#pragma unroll
        for (int mt = 0; mt < 4; mt++) {
            float sl = 0, ql = 0, sh = 0, qh = 0;
#pragma unroll
            for (int nt = 0; nt < 4; nt++) {
                sl += acc[mt][nt][0] + acc[mt][nt][1];
                ql += acc[mt][nt][0]*acc[mt][nt][0] + acc[mt][nt][1]*acc[mt][nt][1];
                sh += acc[mt][nt][2] + acc[mt][nt][3];
                qh += acc[mt][nt][2]*acc[mt][nt][2] + acc[mt][nt][3]*acc[mt][nt][3];
            }
            s8[mt*2] = sl; q8[mt*2] = ql; s8[mt*2+1] = sh; q8[mt*2+1] = qh;
        }
#pragma unroll
        for (int i = 0; i < 8; i++) {
            s8[i] += __shfl_xor_sync(0xffffffffu, s8[i], 1);
            s8[i] += __shfl_xor_sync(0xffffffffu, s8[i], 2);
            q8[i] += __shfl_xor_sync(0xffffffffu, q8[i], 1);
            q8[i] += __shfl_xor_sync(0xffffffffu, q8[i], 2);
        }
        if (lid == 0) {
#pragma unroll
            for (int mt = 0; mt < 4; mt++) {
                int r0 = wm * 64 + mt * 16 + gid;
                ps[r0 * 4 + wn] = s8[mt*2];  pq[r0 * 4 + wn] = q8[mt*2];
                ps[(r0+8)*4 + wn] = s8[mt*2+1]; pq[(r0+8)*4 + wn] = q8[mt*2+1];
            }
        }
        __syncthreads();
#pragma unroll
        for (int mt = 0; mt < 4; mt++) {
#pragma unroll
            for (int hh = 0; hh < 2; hh++) {
                int r = wm * 64 + mt * 16 + gid + hh * 8;
                float4 a = *(float4*)&ps[r * 4];
                float4 b = *(float4*)&pq[r * 4];
                float m = (a.x + a.y + a.z + a.w) * (1.f/128.f);
                float v = (b.x + b.y + b.z + b.w) * (1.f/128.f) - m * m;
                mean[mt*2+hh] = m; rstd[mt*2+hh] = rsqrtf(v + LN_EPS);
            }
        }
        float* orow = outp + (size_t)blockIdx.x * 16384;
#pragma unroll
        for (int nt = 0; nt < 4; nt++) {
            float2 g2 = *(const float2*)&gB[cc[nt]];
            float2 b2 = *(const float2*)&bB[cc[nt]];
#pragma unroll
            for (int mt = 0; mt < 4; mt++) {
                int r0 = wm * 64 + mt * 16 + gid;
                float2 o0, o1;
                o0.x = (acc[mt][nt][0]-mean[mt*2])*rstd[mt*2]*g2.x + b2.x;
                o0.y = (acc[mt][nt][1]-mean[mt*2])*rstd[mt*2]*g2.y + b2.y;
                o1.x = (acc[mt][nt][2]-mean[mt*2+1])*rstd[mt*2+1]*g2.x + b2.x;
                o1.y = (acc[mt][nt][3]-mean[mt*2+1])*rstd[mt*2+1]*g2.y + b2.y;
                *(float2*)&orow[r0 * 128 + cc[nt]] = o0;
                *(float2*)&orow[(r0 + 8) * 128 + cc[nt]] = o1;
            }
        }
    }
}

// ============ fused attention: one block per n ============
// smem: mh half[512][132] | qs f32[8][128] | att f32[8][512] | mk u8[512]
#define MH_BYTES   135168
#define QS_OFF     135168
#define ATT_OFF    139264
#define MK_OFF     155648
#define ATT_SMEM   156160
__global__ __launch_bounds__(256) void k_attn2(
    const unsigned char* __restrict__ mask,
    const float* __restrict__ wv, const float* __restrict__ bv) {
    extern __shared__ char sm[];
    __half* mh = (__half*)sm;
    float* qs = (float*)(sm + QS_OFF);
    float* att = (float*)(sm + ATT_OFF);
    unsigned char* mk = (unsigned char*)(sm + MK_OFF);
    const int n = blockIdx.x, t = threadIdx.x, w = t >> 5, lane = t & 31;

    for (int i = t; i < 1024; i += 256) qs[i] = g_qh[n * 1024 + i];
    for (int i = t; i < 512; i += 256) mk[i] = mask[n * 512 + i];
#pragma unroll 4
    for (int j = 0; j < 64; j++) {
        int idx = t + j * 256;
        int s = idx >> 5, c4 = (idx & 31) * 4;
        float4 v = *(const float4*)&g_mem[((size_t)s * 512 + n) * 128 + c4];
        *(__half2*)&mh[s * 132 + c4]     = __floats2half2_rn(v.x, v.y);
        *(__half2*)&mh[s * 132 + c4 + 2] = __floats2half2_rn(v.z, v.w);
    }
    __syncthreads();

    // ---- scores + softmax: warp = head, lane owns s = sg*32+lane ----
    {
        const int h = w;
        float sc[16];
#pragma unroll
        for (int sg = 0; sg < 16; sg++) {
            int s = sg * 32 + lane;
            const __half* mrow = &mh[s * 132];
            float a = 0.f;
#pragma unroll 8
            for (int ch = 0; ch < 32; ch++) {
                float2 f0 = __half22float2(*(__half2*)&mrow[ch * 4]);
                float2 f1 = __half22float2(*(__half2*)&mrow[ch * 4 + 2]);
                float4 q = *(float4*)&qs[h * 128 + ch * 4];
                a += f0.x * q.x + f0.y * q.y + f1.x * q.z + f1.y * q.w;
            }
            sc[sg] = mk[s] ? -3.402823466e38f : a;
        }
        float mx = sc[0];
#pragma unroll
        for (int sg = 1; sg < 16; sg++) mx = fmaxf(mx, sc[sg]);
        mx = warp_max(mx);
        float sum = 0.f;
#pragma unroll
        for (int sg = 0; sg < 16; sg++) { sc[sg] = __expf(sc[sg] - mx); sum += sc[sg]; }
        sum = warp_sum(sum);
        float inv = 1.f / sum;
#pragma unroll
        for (int sg = 0; sg < 16; sg++) att[h * 512 + sg * 32 + lane] = sc[sg] * inv;
    }
    __syncthreads();

    // ---- weighted sum: warp w handles s in [w*64, w*64+64); all 8 heads ----
    float r8[8][4];
#pragma unroll
    for (int h = 0; h < 8; h++)
#pragma unroll
        for (int q = 0; q < 4; q++) r8[h][q] = 0.f;
    for (int si = 0; si < 64; si++) {
        int s = w * 64 + si;
        float2 f0 = __half22float2(*(__half2*)&mh[s * 132 + lane * 4]);
        float2 f1 = __half22float2(*(__half2*)&mh[s * 132 + lane * 4 + 2]);
#pragma unroll
        for (int h = 0; h < 8; h++) {
            float a = att[h * 512 + s];
            r8[h][0] += a * f0.x; r8[h][1] += a * f0.y;
            r8[h][2] += a * f1.x; r8[h][3] += a * f1.y;
        }
    }
    __syncthreads();                     // all mh reads done
    float* rp = (float*)sm;              // [warp][h][128] partials (16KB, aliases mh)
#pragma unroll
    for (int h = 0; h < 8; h++)
        *(float4*)&rp[(w * 8 + h) * 128 + lane * 4] =
            make_float4(r8[h][0], r8[h][1], r8[h][2], r8[h][3]);
    __syncthreads();
    float* rfin = (float*)(sm + 16384);  // [h][128] (4KB, aliases mh)
    for (int i = t; i < 1024; i += 256) {
        int h = i >> 7, c = i & 127;
        float v = 0.f;
#pragma unroll
        for (int ww = 0; ww < 8; ww++) v += rp[(ww * 8 + h) * 128 + c];
        rfin[i] = v;
    }
    __syncthreads();

    // ---- ctx = r @ wv + bv (sum attn = 1 folds bv through) ----
    if (t < 128) {
        int h = t >> 4;
        float a = bv[t];
#pragma unroll 4
        for (int c = 0; c < 128; c++) a += rfin[h * 128 + c] * wv[c * 128 + t];
        g_ctx[n * 128 + t] = a;
    }
}

// ============ x1 = LN(node + ctx @ wo + bo) ============
__global__ void k_out1(const float* __restrict__ node, const float* __restrict__ wo,
                       const float* __restrict__ bo, const float* __restrict__ g2,
                       const float* __restrict__ b2) {
    int row = blockIdx.x, d = threadIdx.x;
    __shared__ float cs[128];
    __shared__ float rsum[4], rsq[4];
    cs[d] = g_ctx[row * 128 + d];
    __syncthreads();
    float a = bo[d];
#pragma unroll 4
    for (int c = 0; c < 128; c++) a += cs[c] * wo[c * 128 + d];
    a += node[row * 128 + d];
    float s1 = warp_sum(a), s2 = warp_sum(a * a);
    if ((d & 31) == 0) { rsum[d >> 5] = s1; rsq[d >> 5] = s2; }
    __syncthreads();
    float sum = rsum[0] + rsum[1] + rsum[2] + rsum[3];
    float sq = rsq[0] + rsq[1] + rsq[2] + rsq[3];
    float mean = sum * (1.f / 128.f);
    float rs = rsqrtf(sq * (1.f / 128.f) - mean * mean + LN_EPS);
    g_x1[row * 128 + d] = (a - mean) * rs * g2[d] + b2[d];
}

// ============ FFN + final LN ============
__global__ __launch_bounds__(256) void k_ffn(
    const float* __restrict__ w1, const float* __restrict__ b1,
    const float* __restrict__ w2, const float* __restrict__ b2,
    const float* __restrict__ g3, const float* __restrict__ b3,
    float* __restrict__ out_x) {
    __shared__ float xs[4][128];
    __shared__ float hs[4 * 2048];
    __shared__ float resid[4][128];
    int t = threadIdx.x;
    int r0 = blockIdx.x * 4;
    for (int i = t; i < 512; i += 256) xs[i >> 7][i & 127] = g_x1[r0 * 128 + i];
    __syncthreads();
#pragma unroll
    for (int j = 0; j < 8; j++) {
        int col = t + j * 256;
        float bb = b1[col];
        float a0 = bb, a1 = bb, a2 = bb, a3 = bb;
#pragma unroll 4
        for (int c = 0; c < 128; c++) {
            float w = w1[c * 2048 + col];
            a0 += xs[0][c] * w; a1 += xs[1][c] * w;
            a2 += xs[2][c] * w; a3 += xs[3][c] * w;
        }
        hs[0 * 2048 + col] = fmaxf(a0, 0.f);
        hs[1 * 2048 + col] = fmaxf(a1, 0.f);
        hs[2 * 2048 + col] = fmaxf(a2, 0.f);
        hs[3 * 2048 + col] = fmaxf(a3, 0.f);
    }
    __syncthreads();
    if (t < 128) {
        float bb = b2[t];
        float a0 = bb, a1 = bb, a2 = bb, a3 = bb;
#pragma unroll 4
        for (int c = 0; c < 2048; c++) {
            float w = w2[c * 128 + t];
            a0 += hs[c] * w; a1 += hs[2048 + c] * w;
            a2 += hs[4096 + c] * w; a3 += hs[6144 + c] * w;
        }
        resid[0][t] = a0 + xs[0][t];
        resid[1][t] = a1 + xs[1][t];
        resid[2][t] = a2 + xs[2][t];
        resid[3][t] = a3 + xs[3][t];
    }
    __syncthreads();
    int warp = t >> 5, lane = t & 31;
    if (warp < 4) {
        int row = warp;
        float v0 = resid[row][lane], v1 = resid[row][lane + 32];
        float v2 = resid[row][lane + 64], v3 = resid[row][lane + 96];
        float sum = warp_sum(v0 + v1 + v2 + v3);
        float sq = warp_sum(v0 * v0 + v1 * v1 + v2 * v2 + v3 * v3);
        float mean = sum * (1.f / 128.f);
        float rs = rsqrtf(sq * (1.f / 128.f) - mean * mean + LN_EPS);
        out_x[(r0 + row) * 128 + lane]      = (v0 - mean) * rs * g3[lane]      + b3[lane];
        out_x[(r0 + row) * 128 + lane + 32] = (v1 - mean) * rs * g3[lane + 32] + b3[lane + 32];
        out_x[(r0 + row) * 128 + lane + 64] = (v2 - mean) * rs * g3[lane + 64] + b3[lane + 64];
        out_x[(r0 + row) * 128 + lane + 96] = (v3 - mean) * rs * g3[lane + 96] + b3[lane + 96];
    }
}

extern "C" void kernel_launch(void* const* d_in, const int* in_sizes, int n_in,
                              void* d_out, int out_size) {
    (void)in_sizes; (void)n_in; (void)out_size;
    const float* node     = (const float*)d_in[0];
    const float* edge     = (const float*)d_in[1];
    const unsigned char* mask = (const unsigned char*)d_in[2];
    const float* w_mem_e  = (const float*)d_in[3];
    const float* w_mem_s  = (const float*)d_in[4];
    const float* w_mem_t  = (const float*)d_in[5];
    const float* b_mem    = (const float*)d_in[6];
    const float* g_ln_mem = (const float*)d_in[7];
    const float* b_ln_mem = (const float*)d_in[8];
    const float* w_pe     = (const float*)d_in[9];
    const float* b_pe     = (const float*)d_in[10];
    const float* g_ln_pe  = (const float*)d_in[11];
    const float* b_ln_pe  = (const float*)d_in[12];
    const float* g_ln_edge= (const float*)d_in[13];
    const float* b_ln_edge= (const float*)d_in[14];
    const float* wq       = (const float*)d_in[15];
    const float* bq       = (const float*)d_in[16];
    const float* wk       = (const float*)d_in[17];
    /* bk (d_in[18]) provably drops out of softmax */
    const float* wv       = (const float*)d_in[19];
    const float* bv       = (const float*)d_in[20];
    const float* wo       = (const float*)d_in[21];
    const float* bo       = (const float*)d_in[22];
    const float* g_ln2    = (const float*)d_in[23];
    const float* b_ln2    = (const float*)d_in[24];
    const float* w_ff1    = (const float*)d_in[25];
    const float* b_ff1    = (const float*)d_in[26];
    const float* w_ff2    = (const float*)d_in[27];
    const float* b_ff2    = (const float*)d_in[28];
    const float* g_ln3    = (const float*)d_in[29];
    const float* b_ln3    = (const float*)d_in[30];

    float* out_x = (float*)d_out;
    float* out_edge = (float*)d_out + NSEQ * DMODEL;

    cudaFuncSetAttribute(k_gemm, cudaFuncAttributeMaxDynamicSharedMemorySize, GSMEM);
    cudaFuncSetAttribute(k_attn2, cudaFuncAttributeMaxDynamicSharedMemorySize, ATT_SMEM);

    k_pre<<<dim3(512, 3), 128>>>(node, w_mem_s, b_mem, w_mem_t, wq, bq);
    k_qh<<<512, 128>>>(wk);
    // memory = relu(LN(edge @ w_mem_e + ns + nt))
    k_gemm<<<2048, 256, GSMEM>>>(edge, w_mem_e, 0, g_ln_mem, b_ln_mem,
                                 nullptr, nullptr, nullptr, nullptr, nullptr);
    // edge_new = LN(edge + relu(LN(memory @ w_pe + b_pe)))
    k_gemm<<<2048, 256, GSMEM>>>(nullptr, w_pe, 1, g_ln_pe, b_ln_pe,
                                 edge, b_pe, g_ln_edge, b_ln_edge, out_edge);
    k_attn2<<<512, 256, ATT_SMEM>>>(mask, wv, bv);
    k_out1<<<512, 128>>>(node, wo, bo, g_ln2, b_ln2);
    k_ffn<<<128, 256>>>(w_ff1, b_ff1, w_ff2, b_ff2, g_ln3, b_ln3, out_x);
}

// round 5
// speedup vs baseline: 1.5331x; 1.0872x over previous
#include <cuda_runtime.h>
#include <cuda_bf16.h>
#include <cstdint>

#define NSEQ 512
#define DMODEL 128
#define LN_EPS 1e-5f

// ---- scratch (device globals; no runtime allocation) ----
__device__ float g_mem[(size_t)NSEQ * NSEQ * DMODEL];   // memory tensor (s, n, d)
__device__ float g_ns[NSEQ * DMODEL];
__device__ float g_nt[NSEQ * DMODEL];
__device__ float g_q[NSEQ * DMODEL];
__device__ float g_qh[NSEQ * 1024];                     // [n][h][c]
__device__ float g_ctx[NSEQ * DMODEL];
__device__ float g_x1[NSEQ * DMODEL];

__device__ __forceinline__ float warp_sum(float v) {
#pragma unroll
    for (int o = 16; o; o >>= 1) v += __shfl_xor_sync(0xffffffffu, v, o);
    return v;
}
__device__ __forceinline__ float warp_max(float v) {
#pragma unroll
    for (int o = 16; o; o >>= 1) v = fmaxf(v, __shfl_xor_sync(0xffffffffu, v, o));
    return v;
}
__device__ __forceinline__ uint32_t smem_u32(const void* p) {
    uint32_t a;
    asm("{ .reg .u64 t; cvta.to.shared.u64 t, %1; cvt.u32.u64 %0, t; }" : "=r"(a) : "l"(p));
    return a;
}

// bf16 m16n8k16 mma, fp32 accum (sm_80+; arch-neutral)
__device__ __forceinline__ void mma_bf16(float* c, const uint32_t* a, const uint32_t* b) {
    asm volatile(
        "mma.sync.aligned.m16n8k16.row.col.f32.bf16.bf16.f32 "
        "{%0,%1,%2,%3}, {%4,%5,%6,%7}, {%8,%9}, {%0,%1,%2,%3};"
        : "+f"(c[0]), "+f"(c[1]), "+f"(c[2]), "+f"(c[3])
        : "r"(a[0]), "r"(a[1]), "r"(a[2]), "r"(a[3]), "r"(b[0]), "r"(b[1]));
}
#define LDSM4(r0, r1, r2, r3, addr)                                                     \
    asm volatile("ldmatrix.sync.aligned.m8n8.x4.shared.b16 {%0,%1,%2,%3}, [%4];"        \
        : "=r"(r0), "=r"(r1), "=r"(r2), "=r"(r3) : "r"(addr))
#define LDSM2(r0, r1, addr)                                                             \
    asm volatile("ldmatrix.sync.aligned.m8n8.x2.shared.b16 {%0,%1}, [%2];"              \
        : "=r"(r0), "=r"(r1) : "r"(addr))

__device__ __forceinline__ uint32_t pack_bf2(float a, float b) {
    __nv_bfloat162 p = __floats2bfloat162_rn(a, b);
    return *(uint32_t*)&p;
}

// ============ small precompute: ns, nt, q ============
__global__ void k_pre(const float* __restrict__ node,
                      const float* __restrict__ w_mem_s, const float* __restrict__ b_mem,
                      const float* __restrict__ w_mem_t,
                      const float* __restrict__ wq, const float* __restrict__ bq) {
    int row = blockIdx.x, which = blockIdx.y, d = threadIdx.x;
    __shared__ float xs[DMODEL];
    xs[d] = node[row * DMODEL + d];
    __syncthreads();
    const float* W = (which == 0) ? w_mem_s : (which == 1) ? w_mem_t : wq;
    float acc = (which == 0) ? b_mem[d] : (which == 2) ? bq[d] : 0.f;
#pragma unroll 8
    for (int c = 0; c < DMODEL; c++) acc += xs[c] * W[c * DMODEL + d];
    float* out = (which == 0) ? g_ns : (which == 1) ? g_nt : g_q;
    out[row * DMODEL + d] = acc;
}

// qh[n][h][c] = sum_dh wk[c, h*16+dh] * q[n, h*16+dh] * 0.25  (bk drops out of softmax)
__global__ void k_qh(const float* __restrict__ wk) {
    int n = blockIdx.x, c = threadIdx.x;
    __shared__ float qs[DMODEL];
    qs[c] = g_q[n * DMODEL + c];
    __syncthreads();
    const float* wrow = wk + c * DMODEL;
#pragma unroll
    for (int h = 0; h < 8; h++) {
        float a = 0.f;
#pragma unroll
        for (int dh = 0; dh < 16; dh++) a += wrow[h * 16 + dh] * qs[h * 16 + dh];
        g_qh[n * 1024 + h * 128 + c] = a * 0.25f;
    }
}

// ============ bf16x3 tensor-core GEMM with ldmatrix, 2 CTAs/SM ============
// Ah/Al u32[128][36] (k chunk of 64, packed bf16x2); Bh/Bl u32[128][68] n-major
#define AH_OFF 0
#define AL_OFF 18432
#define BH_OFF 36864
#define BL_OFF 71680
#define PS_OFF 106496
#define PQ_OFF 108544
#define GSMEM  110592

__device__ __forceinline__ void load_achunk(const float* __restrict__ At, int coff,
                                            uint32_t* Ah, uint32_t* Al, int t) {
#pragma unroll
    for (int j = 0; j < 8; j++) {
        int idx = t + j * 256;
        int row = idx >> 4, c4 = (idx & 15) * 4;
        float4 v = *(const float4*)(At + row * 128 + coff + c4);
        uint32_t x = __float_as_uint(v.x), y = __float_as_uint(v.y);
        uint32_t z = __float_as_uint(v.z), w = __float_as_uint(v.w);
        uint32_t h0 = (y & 0xFFFF0000u) | (x >> 16);
        uint32_t h1 = (w & 0xFFFF0000u) | (z >> 16);
        float lx = v.x - __uint_as_float(x & 0xFFFF0000u);
        float ly = v.y - __uint_as_float(y & 0xFFFF0000u);
        float lz = v.z - __uint_as_float(z & 0xFFFF0000u);
        float lw = v.w - __uint_as_float(w & 0xFFFF0000u);
        int kp = c4 >> 1;
        *(uint2*)&Ah[row * 36 + kp] = make_uint2(h0, h1);
        *(uint2*)&Al[row * 36 + kp] = make_uint2(pack_bf2(lx, ly), pack_bf2(lz, lw));
    }
}

// mode 0: g_mem = relu(LN(edge @ W + ns[n] + nt[s]))
// mode 1: outp  = LN(edge + relu(LN(g_mem @ W + bpe)))
__global__ __launch_bounds__(256, 2) void k_gemm(
    const float* __restrict__ Asrc, const float* __restrict__ W, int mode,
    const float* __restrict__ gA, const float* __restrict__ bA,
    const float* __restrict__ res_in, const float* __restrict__ bpe,
    const float* __restrict__ gB, const float* __restrict__ bB,
    float* __restrict__ outp) {
    extern __shared__ char sm[];
    uint32_t* Ah = (uint32_t*)(sm + AH_OFF);
    uint32_t* Al = (uint32_t*)(sm + AL_OFF);
    uint32_t* Bh = (uint32_t*)(sm + BH_OFF);
    uint32_t* Bl = (uint32_t*)(sm + BL_OFF);
    float* ps = (float*)(sm + PS_OFF);
    float* pq = (float*)(sm + PQ_OFF);
    const int t = threadIdx.x;
    const float* Abase = mode ? (const float*)g_mem : Asrc;
    const float* At = Abase + (size_t)blockIdx.x * 16384;

    // ---- convert B (weight 128x128 [k][n]) to n-major packed bf16 hi/lo ----
#pragma unroll
    for (int j = 0; j < 32; j++) {
        int e = t + j * 256;
        int kp = e >> 7, n = e & 127;
        float a = W[(2 * kp) * 128 + n];
        float b = W[(2 * kp + 1) * 128 + n];
        uint32_t ab = __float_as_uint(a), bb = __float_as_uint(b);
        Bh[n * 68 + kp] = (bb & 0xFFFF0000u) | (ab >> 16);
        float la = a - __uint_as_float(ab & 0xFFFF0000u);
        float lb = b - __uint_as_float(bb & 0xFFFF0000u);
        Bl[n * 68 + kp] = pack_bf2(la, lb);
    }
    load_achunk(At, 0, Ah, Al, t);
    __syncthreads();

    const int w = t >> 5, lane = t & 31;
    const int wm = w >> 2, wn = w & 3;
    const int gid = lane >> 2, lid = lane & 3;
    const uint32_t sb = smem_u32(sm);
    // ldmatrix lane->address maps (see mma fragment layout)
    const uint32_t aoff = (uint32_t)((lane & 15) * 144 + (lane >> 4) * 16);
    const uint32_t boff = (uint32_t)(((lane >> 4) * 8 + (lane & 7)) * 272 + ((lane >> 3) & 1) * 16);
    uint32_t addrA[4], addrB[2];
#pragma unroll
    for (int mt = 0; mt < 4; mt++)
        addrA[mt] = sb + AH_OFF + (wm * 64 + mt * 16) * 144 + aoff;
#pragma unroll
    for (int p = 0; p < 2; p++)
        addrB[p] = sb + BH_OFF + (wn * 32 + p * 16) * 272 + boff;

    float acc[4][4][4];
#pragma unroll
    for (int mt = 0; mt < 4; mt++)
#pragma unroll
        for (int nt = 0; nt < 4; nt++)
#pragma unroll
            for (int q = 0; q < 4; q++) acc[mt][nt][q] = 0.f;

#pragma unroll
    for (int chunk = 0; chunk < 2; chunk++) {
#pragma unroll
        for (int ks2 = 0; ks2 < 4; ks2++) {
            const uint32_t bAo = ks2 * 32;
            const uint32_t bBo = chunk * 128 + ks2 * 32;
            uint32_t ah[4][4], al[4][4], bh[4][2], bl[4][2];
#pragma unroll
            for (int mt = 0; mt < 4; mt++) {
                LDSM4(ah[mt][0], ah[mt][1], ah[mt][2], ah[mt][3], addrA[mt] + bAo);
                LDSM4(al[mt][0], al[mt][1], al[mt][2], al[mt][3], addrA[mt] + 18432 + bAo);
            }
            LDSM4(bh[0][0], bh[0][1], bh[1][0], bh[1][1], addrB[0] + bBo);
            LDSM4(bh[2][0], bh[2][1], bh[3][0], bh[3][1], addrB[1] + bBo);
            LDSM4(bl[0][0], bl[0][1], bl[1][0], bl[1][1], addrB[0] + 34816 + bBo);
            LDSM4(bl[2][0], bl[2][1], bl[3][0], bl[3][1], addrB[1] + 34816 + bBo);
#pragma unroll
            for (int mt = 0; mt < 4; mt++)
#pragma unroll
                for (int nt = 0; nt < 4; nt++) {
                    mma_bf16(acc[mt][nt], ah[mt], bh[nt]);
                    mma_bf16(acc[mt][nt], ah[mt], bl[nt]);
                    mma_bf16(acc[mt][nt], al[mt], bh[nt]);
                }
        }
        __syncthreads();
        if (chunk == 0) { load_achunk(At, 64, Ah, Al, t); __syncthreads(); }
    }

    // ---- register epilogue ----
    int cc[4];
#pragma unroll
    for (int nt = 0; nt < 4; nt++) cc[nt] = wn * 32 + nt * 8 + lid * 2;

    if (mode == 0) {
        const int s_tile = blockIdx.x >> 2, nbase = (blockIdx.x & 3) * 128;
#pragma unroll
        for (int nt = 0; nt < 4; nt++) {
            float2 ntv = *(const float2*)&g_nt[s_tile * 128 + cc[nt]];
#pragma unroll
            for (int mt = 0; mt < 4; mt++) {
                int r0 = wm * 64 + mt * 16 + gid;
                float2 n0 = *(const float2*)&g_ns[(nbase + r0) * 128 + cc[nt]];
                float2 n1 = *(const float2*)&g_ns[(nbase + r0 + 8) * 128 + cc[nt]];
                acc[mt][nt][0] += n0.x + ntv.x; acc[mt][nt][1] += n0.y + ntv.y;
                acc[mt][nt][2] += n1.x + ntv.x; acc[mt][nt][3] += n1.y + ntv.y;
            }
        }
        float s8[8], q8[8];
#pragma unroll
        for (int mt = 0; mt < 4; mt++) {
            float sl = 0, ql = 0, sh = 0, qh = 0;
#pragma unroll
            for (int nt = 0; nt < 4; nt++) {
                sl += acc[mt][nt][0] + acc[mt][nt][1];
                ql += acc[mt][nt][0]*acc[mt][nt][0] + acc[mt][nt][1]*acc[mt][nt][1];
                sh += acc[mt][nt][2] + acc[mt][nt][3];
                qh += acc[mt][nt][2]*acc[mt][nt][2] + acc[mt][nt][3]*acc[mt][nt][3];
            }
            s8[mt*2] = sl; q8[mt*2] = ql; s8[mt*2+1] = sh; q8[mt*2+1] = qh;
        }
#pragma unroll
        for (int i = 0; i < 8; i++) {
            s8[i] += __shfl_xor_sync(0xffffffffu, s8[i], 1);
            s8[i] += __shfl_xor_sync(0xffffffffu, s8[i], 2);
            q8[i] += __shfl_xor_sync(0xffffffffu, q8[i], 1);
            q8[i] += __shfl_xor_sync(0xffffffffu, q8[i], 2);
        }
        if (lid == 0) {
#pragma unroll
            for (int mt = 0; mt < 4; mt++) {
                int r0 = wm * 64 + mt * 16 + gid;
                ps[r0 * 4 + wn] = s8[mt*2];  pq[r0 * 4 + wn] = q8[mt*2];
                ps[(r0+8)*4 + wn] = s8[mt*2+1]; pq[(r0+8)*4 + wn] = q8[mt*2+1];
            }
        }
        __syncthreads();
        float mean[8], rstd[8];
#pragma unroll
        for (int mt = 0; mt < 4; mt++) {
#pragma unroll
            for (int hh = 0; hh < 2; hh++) {
                int r = wm * 64 + mt * 16 + gid + hh * 8;
                float4 a = *(float4*)&ps[r * 4];
                float4 b = *(float4*)&pq[r * 4];
                float m = (a.x + a.y + a.z + a.w) * (1.f/128.f);
                float v = (b.x + b.y + b.z + b.w) * (1.f/128.f) - m * m;
                mean[mt*2+hh] = m; rstd[mt*2+hh] = rsqrtf(v + LN_EPS);
            }
        }
        float* orow = g_mem + (size_t)blockIdx.x * 16384;
#pragma unroll
        for (int nt = 0; nt < 4; nt++) {
            float2 gv = *(const float2*)&gA[cc[nt]];
            float2 bv2 = *(const float2*)&bA[cc[nt]];
#pragma unroll
            for (int mt = 0; mt < 4; mt++) {
                int r0 = wm * 64 + mt * 16 + gid;
                float2 o0, o1;
                o0.x = fmaxf((acc[mt][nt][0]-mean[mt*2])*rstd[mt*2]*gv.x + bv2.x, 0.f);
                o0.y = fmaxf((acc[mt][nt][1]-mean[mt*2])*rstd[mt*2]*gv.y + bv2.y, 0.f);
                o1.x = fmaxf((acc[mt][nt][2]-mean[mt*2+1])*rstd[mt*2+1]*gv.x + bv2.x, 0.f);
                o1.y = fmaxf((acc[mt][nt][3]-mean[mt*2+1])*rstd[mt*2+1]*gv.y + bv2.y, 0.f);
                *(float2*)&orow[r0 * 128 + cc[nt]] = o0;
                *(float2*)&orow[(r0 + 8) * 128 + cc[nt]] = o1;
            }
        }
    } else {
#pragma unroll
        for (int nt = 0; nt < 4; nt++) {
            float2 bp = *(const float2*)&bpe[cc[nt]];
#pragma unroll
            for (int mt = 0; mt < 4; mt++) {
                acc[mt][nt][0] += bp.x; acc[mt][nt][1] += bp.y;
                acc[mt][nt][2] += bp.x; acc[mt][nt][3] += bp.y;
            }
        }
        float s8[8], q8[8];
#pragma unroll
        for (int mt = 0; mt < 4; mt++) {
            float sl = 0, ql = 0, sh = 0, qh = 0;
#pragma unroll
            for (int nt = 0; nt < 4; nt++) {
                sl += acc[mt][nt][0] + acc[mt][nt][1];
                ql += acc[mt][nt][0]*acc[mt][nt][0] + acc[mt][nt][1]*acc[mt][nt][1];
                sh += acc[mt][nt][2] + acc[mt][nt][3];
                qh += acc[mt][nt][2]*acc[mt][nt][2] + acc[mt][nt][3]*acc[mt][nt][3];
            }
            s8[mt*2] = sl; q8[mt*2] = ql; s8[mt*2+1] = sh; q8[mt*2+1] = qh;
        }
#pragma unroll
        for (int i = 0; i < 8; i++) {
            s8[i] += __shfl_xor_sync(0xffffffffu, s8[i], 1);
            s8[i] += __shfl_xor_sync(0xffffffffu, s8[i], 2);
            q8[i] += __shfl_xor_sync(0xffffffffu, q8[i], 1);
            q8[i] += __shfl_xor_sync(0xffffffffu, q8[i], 2);
        }
        if (lid == 0) {
#pragma unroll
            for (int mt = 0; mt < 4; mt++) {
                int r0 = wm * 64 + mt * 16 + gid;
                ps[r0 * 4 + wn] = s8[mt*2];  pq[r0 * 4 + wn] = q8[mt*2];
                ps[(r0+8)*4 + wn] = s8[mt*2+1]; pq[(r0+8)*4 + wn] = q8[mt*2+1];
            }
        }
        __syncthreads();
        float mean[8], rstd[8];
#pragma unroll
        for (int mt = 0; mt < 4; mt++) {
#pragma unroll
            for (int hh = 0; hh < 2; hh++) {
                int r = wm * 64 + mt * 16 + gid + hh * 8;
                float4 a = *(float4*)&ps[r * 4];
                float4 b = *(float4*)&pq[r * 4];
                float m = (a.x + a.y + a.z + a.w) * (1.f/128.f);
                float v = (b.x + b.y + b.z + b.w) * (1.f/128.f) - m * m;
                mean[mt*2+hh] = m; rstd[mt*2+hh] = rsqrtf(v + LN_EPS);
            }
        }
        const float* erow = res_in + (size_t)blockIdx.x * 16384;
#pragma unroll
        for (int nt = 0; nt < 4; nt++) {
            float2 g1 = *(const float2*)&gA[cc[nt]];
            float2 b1 = *(const float2*)&bA[cc[nt]];
#pragma unroll
            for (int mt = 0; mt < 4; mt++) {
                int r0 = wm * 64 + mt * 16 + gid;
                float2 e0 = *(const float2*)&erow[r0 * 128 + cc[nt]];
                float2 e1 = *(const float2*)&erow[(r0 + 8) * 128 + cc[nt]];
                acc[mt][nt][0] = e0.x + fmaxf((acc[mt][nt][0]-mean[mt*2])*rstd[mt*2]*g1.x + b1.x, 0.f);
                acc[mt][nt][1] = e0.y + fmaxf((acc[mt][nt][1]-mean[mt*2])*rstd[mt*2]*g1.y + b1.y, 0.f);
                acc[mt][nt][2] = e1.x + fmaxf((acc[mt][nt][2]-mean[mt*2+1])*rstd[mt*2+1]*g1.x + b1.x, 0.f);
                acc[mt][nt][3] = e1.y + fmaxf((acc[mt][nt][3]-mean[mt*2+1])*rstd[mt*2+1]*g1.y + b1.y, 0.f);
            }
        }
        __syncthreads();
#pragma unroll
        for (int mt = 0; mt < 4; mt++) {
            float sl = 0, ql = 0, sh = 0, qh = 0;
#pragma unroll
            for (int nt = 0; nt < 4; nt++) {
                sl += acc[mt][nt][0] + acc[mt][nt][1];
                ql += acc[mt][nt][0]*acc[mt][nt][0] + acc[mt][nt][1]*acc[mt][nt][1];
                sh += acc[mt][nt][2] + acc[mt][nt][3];
                qh += acc[mt][nt][2]*acc[mt][nt][2] + acc[mt][nt][3]*acc[mt][nt][3];
            }
            s8[mt*2] = sl; q8[mt*2] = ql; s8[mt*2+1] = sh; q8[mt*2+1] = qh;
        }
#pragma unroll
        for (int i = 0; i < 8; i++) {
            s8[i] += __shfl_xor_sync(0xffffffffu, s8[i], 1);
            s8[i] += __shfl_xor_sync(0xffffffffu, s8[i], 2);
            q8[i] += __shfl_xor_sync(0xffffffffu, q8[i], 1);
            q8[i] += __shfl_xor_sync(0xffffffffu, q8[i], 2);
        }
        if (lid == 0) {
#pragma unroll
            for (int mt = 0; mt < 4; mt++) {
                int r0 = wm * 64 + mt * 16 + gid;
                ps[r0 * 4 + wn] = s8[mt*2];  pq[r0 * 4 + wn] = q8[mt*2];
                ps[(r0+8)*4 + wn] = s8[mt*2+1]; pq[(r0+8)*4 + wn] = q8[mt*2+1];
            }
        }
        __syncthreads();
#pragma unroll
        for (int mt = 0; mt < 4; mt++) {
#pragma unroll
            for (int hh = 0; hh < 2; hh++) {
                int r = wm * 64 + mt * 16 + gid + hh * 8;
                float4 a = *(float4*)&ps[r * 4];
                float4 b = *(float4*)&pq[r * 4];
                float m = (a.x + a.y + a.z + a.w) * (1.f/128.f);
                float v = (b.x + b.y + b.z + b.w) * (1.f/128.f) - m * m;
                mean[mt*2+hh] = m; rstd[mt*2+hh] = rsqrtf(v + LN_EPS);
            }
        }
        float* orow = outp + (size_t)blockIdx.x * 16384;
#pragma unroll
        for (int nt = 0; nt < 4; nt++) {
            float2 g2 = *(const float2*)&gB[cc[nt]];
            float2 b2 = *(const float2*)&bB[cc[nt]];
#pragma unroll
            for (int mt = 0; mt < 4; mt++) {
                int r0 = wm * 64 + mt * 16 + gid;
                float2 o0, o1;
                o0.x = (acc[mt][nt][0]-mean[mt*2])*rstd[mt*2]*g2.x + b2.x;
                o0.y = (acc[mt][nt][1]-mean[mt*2])*rstd[mt*2]*g2.y + b2.y;
                o1.x = (acc[mt][nt][2]-mean[mt*2+1])*rstd[mt*2+1]*g2.x + b2.x;
                o1.y = (acc[mt][nt][3]-mean[mt*2+1])*rstd[mt*2+1]*g2.y + b2.y;
                *(float2*)&orow[r0 * 128 + cc[nt]] = o0;
                *(float2*)&orow[(r0 + 8) * 128 + cc[nt]] = o1;
            }
        }
    }
}

// ============ fused attention (MMA scores): one block per n ============
// smem: mh bf16[512][136] | qb bf16[8][136] | att f32[8][512] | mk u8[512]
#define MH_OFF   0
#define QB_OFF   139264
#define ATT_OFF  141440
#define MK_OFF   157824
#define ATT_SMEM 158336
__global__ __launch_bounds__(256) void k_attn2(
    const unsigned char* __restrict__ mask,
    const float* __restrict__ wv, const float* __restrict__ bv) {
    extern __shared__ char sm[];
    __nv_bfloat16* mh = (__nv_bfloat16*)(sm + MH_OFF);
    __nv_bfloat16* qb = (__nv_bfloat16*)(sm + QB_OFF);
    float* att = (float*)(sm + ATT_OFF);
    unsigned char* mk = (unsigned char*)(sm + MK_OFF);
    const int n = blockIdx.x, t = threadIdx.x, w = t >> 5, lane = t & 31;
    const uint32_t sb = smem_u32(sm);

    for (int i = t; i < 1024; i += 256) {
        int h = i >> 7, c = i & 127;
        qb[h * 136 + c] = __float2bfloat16_rn(g_qh[n * 1024 + i]);
    }
    for (int i = t; i < 512; i += 256) mk[i] = mask[n * 512 + i];
#pragma unroll 4
    for (int j = 0; j < 64; j++) {
        int idx = t + j * 256;
        int s = idx >> 5, c4 = (idx & 31) * 4;
        float4 v = *(const float4*)&g_mem[((size_t)s * 512 + n) * 128 + c4];
        *(uint2*)&mh[s * 136 + c4] = make_uint2(pack_bf2(v.x, v.y), pack_bf2(v.z, v.w));
    }
    __syncthreads();

    // ---- scores via MMA: warp w covers s in [w*64, w*64+64), heads = N dim ----
    {
        const int l2 = lane & 15;
        const uint32_t aoffA = (uint32_t)((lane & 15) * 272 + (lane >> 4) * 16);
        const uint32_t qaddr = sb + QB_OFF + (uint32_t)((l2 & 7) * 272 + ((l2 >> 3) & 1) * 16);
        float acc[4][4];
#pragma unroll
        for (int mt = 0; mt < 4; mt++)
#pragma unroll
            for (int q = 0; q < 4; q++) acc[mt][q] = 0.f;
#pragma unroll
        for (int ks = 0; ks < 8; ks++) {
            uint32_t bq[2];
            LDSM2(bq[0], bq[1], qaddr + ks * 32);
#pragma unroll
            for (int mt = 0; mt < 4; mt++) {
                uint32_t a[4];
                LDSM4(a[0], a[1], a[2], a[3],
                      sb + MH_OFF + (w * 64 + mt * 16) * 272 + aoffA + ks * 32);
                mma_bf16(acc[mt], a, bq);
            }
        }
        const int gid = lane >> 2, lid = lane & 3;
#pragma unroll
        for (int mt = 0; mt < 4; mt++) {
            int s = w * 64 + mt * 16 + gid;
            att[(2 * lid) * 512 + s]     = acc[mt][0];
            att[(2 * lid + 1) * 512 + s] = acc[mt][1];
            att[(2 * lid) * 512 + s + 8]     = acc[mt][2];
            att[(2 * lid + 1) * 512 + s + 8] = acc[mt][3];
        }
    }
    __syncthreads();

    // ---- softmax per head (warp = head), apply mask here ----
    {
        const int h = w;
        float sc[16];
        float mx = -3.402823466e38f;
#pragma unroll
        for (int i = 0; i < 16; i++) {
            int s = lane + i * 32;
            sc[i] = mk[s] ? -3.402823466e38f : att[h * 512 + s];
            mx = fmaxf(mx, sc[i]);
        }
        mx = warp_max(mx);
        float sum = 0.f;
#pragma unroll
        for (int i = 0; i < 16; i++) { sc[i] = __expf(sc[i] - mx); sum += sc[i]; }
        sum = warp_sum(sum);
        float inv = 1.f / sum;
#pragma unroll
        for (int i = 0; i < 16; i++) att[h * 512 + lane + i * 32] = sc[i] * inv;
    }
    __syncthreads();

    // ---- weighted sum: warp w handles s in [w*64, w*64+64); all 8 heads ----
    float r8[8][4];
#pragma unroll
    for (int h = 0; h < 8; h++)
#pragma unroll
        for (int q = 0; q < 4; q++) r8[h][q] = 0.f;
    for (int si = 0; si < 64; si++) {
        int s = w * 64 + si;
        float2 f0 = __bfloat1622float2(*(__nv_bfloat162*)&mh[s * 136 + lane * 4]);
        float2 f1 = __bfloat1622float2(*(__nv_bfloat162*)&mh[s * 136 + lane * 4 + 2]);
#pragma unroll
        for (int h = 0; h < 8; h++) {
            float a = att[h * 512 + s];
            r8[h][0] += a * f0.x; r8[h][1] += a * f0.y;
            r8[h][2] += a * f1.x; r8[h][3] += a * f1.y;
        }
    }
    __syncthreads();                     // all mh reads done
    float* rp = (float*)sm;              // [warp][h][128] partials (16KB, aliases mh)
#pragma unroll
    for (int h = 0; h < 8; h++)
        *(float4*)&rp[(w * 8 + h) * 128 + lane * 4] =
            make_float4(r8[h][0], r8[h][1], r8[h][2], r8[h][3]);
    __syncthreads();
    float* rfin = (float*)(sm + 16384);  // [h][128] (4KB, aliases mh tail)
    for (int i = t; i < 1024; i += 256) {
        int h = i >> 7, c = i & 127;
        float v = 0.f;
#pragma unroll
        for (int ww = 0; ww < 8; ww++) v += rp[(ww * 8 + h) * 128 + c];
        rfin[i] = v;
    }
    __syncthreads();

    // ---- ctx = r @ wv + bv (sum attn = 1 folds bv through) ----
    if (t < 128) {
        int h = t >> 4;
        float a = bv[t];
#pragma unroll 8
        for (int c = 0; c < 128; c++) a += rfin[h * 128 + c] * wv[c * 128 + t];
        g_ctx[n * 128 + t] = a;
    }
}

// ============ x1 = LN(node + ctx @ wo + bo) ============
__global__ void k_out1(const float* __restrict__ node, const float* __restrict__ wo,
                       const float* __restrict__ bo, const float* __restrict__ g2,
                       const float* __restrict__ b2) {
    int row = blockIdx.x, d = threadIdx.x;
    __shared__ float cs[128];
    __shared__ float rsum[4], rsq[4];
    cs[d] = g_ctx[row * 128 + d];
    __syncthreads();
    float a = bo[d];
#pragma unroll 8
    for (int c = 0; c < 128; c++) a += cs[c] * wo[c * 128 + d];
    a += node[row * 128 + d];
    float s1 = warp_sum(a), s2 = warp_sum(a * a);
    if ((d & 31) == 0) { rsum[d >> 5] = s1; rsq[d >> 5] = s2; }
    __syncthreads();
    float sum = rsum[0] + rsum[1] + rsum[2] + rsum[3];
    float sq = rsq[0] + rsq[1] + rsq[2] + rsq[3];
    float mean = sum * (1.f / 128.f);
    float rs = rsqrtf(sq * (1.f / 128.f) - mean * mean + LN_EPS);
    g_x1[row * 128 + d] = (a - mean) * rs * g2[d] + b2[d];
}

// ============ FFN + final LN ============
__global__ __launch_bounds__(256) void k_ffn(
    const float* __restrict__ w1, const float* __restrict__ b1,
    const float* __restrict__ w2, const float* __restrict__ b2,
    const float* __restrict__ g3, const float* __restrict__ b3,
    float* __restrict__ out_x) {
    __shared__ float xs[4][128];
    __shared__ float hs[4 * 2048];
    __shared__ float resid[4][128];
    int t = threadIdx.x;
    int r0 = blockIdx.x * 4;
    for (int i = t; i < 512; i += 256) xs[i >> 7][i & 127] = g_x1[r0 * 128 + i];
    __syncthreads();
#pragma unroll
    for (int j = 0; j < 8; j++) {
        int col = t + j * 256;
        float bb = b1[col];
        float a0 = bb, a1 = bb, a2 = bb, a3 = bb;
#pragma unroll 4
        for (int c = 0; c < 128; c++) {
            float w = w1[c * 2048 + col];
            a0 += xs[0][c] * w; a1 += xs[1][c] * w;
            a2 += xs[2][c] * w; a3 += xs[3][c] * w;
        }
        hs[0 * 2048 + col] = fmaxf(a0, 0.f);
        hs[1 * 2048 + col] = fmaxf(a1, 0.f);
        hs[2 * 2048 + col] = fmaxf(a2, 0.f);
        hs[3 * 2048 + col] = fmaxf(a3, 0.f);
    }
    __syncthreads();
    if (t < 128) {
        float bb = b2[t];
        float a0 = bb, a1 = bb, a2 = bb, a3 = bb;
#pragma unroll 4
        for (int c = 0; c < 2048; c++) {
            float w = w2[c * 128 + t];
            a0 += hs[c] * w; a1 += hs[2048 + c] * w;
            a2 += hs[4096 + c] * w; a3 += hs[6144 + c] * w;
        }
        resid[0][t] = a0 + xs[0][t];
        resid[1][t] = a1 + xs[1][t];
        resid[2][t] = a2 + xs[2][t];
        resid[3][t] = a3 + xs[3][t];
    }
    __syncthreads();
    int warp = t >> 5, lane = t & 31;
    if (warp < 4) {
        int row = warp;
        float v0 = resid[row][lane], v1 = resid[row][lane + 32];
        float v2 = resid[row][lane + 64], v3 = resid[row][lane + 96];
        float sum = warp_sum(v0 + v1 + v2 + v3);
        float sq = warp_sum(v0 * v0 + v1 * v1 + v2 * v2 + v3 * v3);
        float mean = sum * (1.f / 128.f);
        float rs = rsqrtf(sq * (1.f / 128.f) - mean * mean + LN_EPS);
        out_x[(r0 + row) * 128 + lane]      = (v0 - mean) * rs * g3[lane]      + b3[lane];
        out_x[(r0 + row) * 128 + lane + 32] = (v1 - mean) * rs * g3[lane + 32] + b3[lane + 32];
        out_x[(r0 + row) * 128 + lane + 64] = (v2 - mean) * rs * g3[lane + 64] + b3[lane + 64];
        out_x[(r0 + row) * 128 + lane + 96] = (v3 - mean) * rs * g3[lane + 96] + b3[lane + 96];
    }
}

extern "C" void kernel_launch(void* const* d_in, const int* in_sizes, int n_in,
                              void* d_out, int out_size) {
    (void)in_sizes; (void)n_in; (void)out_size;
    const float* node     = (const float*)d_in[0];
    const float* edge     = (const float*)d_in[1];
    const unsigned char* mask = (const unsigned char*)d_in[2];
    const float* w_mem_e  = (const float*)d_in[3];
    const float* w_mem_s  = (const float*)d_in[4];
    const float* w_mem_t  = (const float*)d_in[5];
    const float* b_mem    = (const float*)d_in[6];
    const float* g_ln_mem = (const float*)d_in[7];
    const float* b_ln_mem = (const float*)d_in[8];
    const float* w_pe     = (const float*)d_in[9];
    const float* b_pe     = (const float*)d_in[10];
    const float* g_ln_pe  = (const float*)d_in[11];
    const float* b_ln_pe  = (const float*)d_in[12];
    const float* g_ln_edge= (const float*)d_in[13];
    const float* b_ln_edge= (const float*)d_in[14];
    const float* wq       = (const float*)d_in[15];
    const float* bq       = (const float*)d_in[16];
    const float* wk       = (const float*)d_in[17];
    /* bk (d_in[18]) provably drops out of softmax */
    const float* wv       = (const float*)d_in[19];
    const float* bv       = (const float*)d_in[20];
    const float* wo       = (const float*)d_in[21];
    const float* bo       = (const float*)d_in[22];
    const float* g_ln2    = (const float*)d_in[23];
    const float* b_ln2    = (const float*)d_in[24];
    const float* w_ff1    = (const float*)d_in[25];
    const float* b_ff1    = (const float*)d_in[26];
    const float* w_ff2    = (const float*)d_in[27];
    const float* b_ff2    = (const float*)d_in[28];
    const float* g_ln3    = (const float*)d_in[29];
    const float* b_ln3    = (const float*)d_in[30];

    float* out_x = (float*)d_out;
    float* out_edge = (float*)d_out + NSEQ * DMODEL;

    cudaFuncSetAttribute(k_gemm, cudaFuncAttributeMaxDynamicSharedMemorySize, GSMEM);
    cudaFuncSetAttribute(k_attn2, cudaFuncAttributeMaxDynamicSharedMemorySize, ATT_SMEM);

    k_pre<<<dim3(512, 3), 128>>>(node, w_mem_s, b_mem, w_mem_t, wq, bq);
    k_qh<<<512, 128>>>(wk);
    // memory = relu(LN(edge @ w_mem_e + ns + nt))
    k_gemm<<<2048, 256, GSMEM>>>(edge, w_mem_e, 0, g_ln_mem, b_ln_mem,
                                 nullptr, nullptr, nullptr, nullptr, nullptr);
    // edge_new = LN(edge + relu(LN(memory @ w_pe + b_pe)))
    k_gemm<<<2048, 256, GSMEM>>>(nullptr, w_pe, 1, g_ln_pe, b_ln_pe,
                                 edge, b_pe, g_ln_edge, b_ln_edge, out_edge);
    k_attn2<<<512, 256, ATT_SMEM>>>(mask, wv, bv);
    k_out1<<<512, 128>>>(node, wo, bo, g_ln2, b_ln2);
    k_ffn<<<128, 256>>>(w_ff1, b_ff1, w_ff2, b_ff2, g_ln3, b_ln3, out_x);
}

// round 6
// speedup vs baseline: 2.5806x; 1.6832x over previous
#include <cuda_runtime.h>
#include <cuda_bf16.h>
#include <cstdint>

#define NSEQ 512
#define DMODEL 128
#define LN_EPS 1e-5f

// ---- scratch (device globals; no runtime allocation) ----
__device__ float g_mem[(size_t)NSEQ * NSEQ * DMODEL];   // memory tensor (s, n, d)
__device__ float g_ns[NSEQ * DMODEL];
__device__ float g_nt[NSEQ * DMODEL];
__device__ float g_q[NSEQ * DMODEL];
__device__ float g_qh[NSEQ * 1024];                     // [n][h][c]
__device__ float g_ctx[NSEQ * DMODEL];
__device__ float g_x1[NSEQ * DMODEL];
__device__ float g_h[512 * 2048];                       // ffn hidden
__device__ float g_ffp[16 * 512 * DMODEL];              // ffn split-K partials

__device__ __forceinline__ float warp_sum(float v) {
#pragma unroll
    for (int o = 16; o; o >>= 1) v += __shfl_xor_sync(0xffffffffu, v, o);
    return v;
}
__device__ __forceinline__ float warp_max(float v) {
#pragma unroll
    for (int o = 16; o; o >>= 1) v = fmaxf(v, __shfl_xor_sync(0xffffffffu, v, o));
    return v;
}
__device__ __forceinline__ uint32_t smem_u32(const void* p) {
    uint32_t a;
    asm("{ .reg .u64 t; cvta.to.shared.u64 t, %1; cvt.u32.u64 %0, t; }" : "=r"(a) : "l"(p));
    return a;
}
__device__ __forceinline__ void mma_bf16(float* c, const uint32_t* a, const uint32_t* b) {
    asm volatile(
        "mma.sync.aligned.m16n8k16.row.col.f32.bf16.bf16.f32 "
        "{%0,%1,%2,%3}, {%4,%5,%6,%7}, {%8,%9}, {%0,%1,%2,%3};"
        : "+f"(c[0]), "+f"(c[1]), "+f"(c[2]), "+f"(c[3])
        : "r"(a[0]), "r"(a[1]), "r"(a[2]), "r"(a[3]), "r"(b[0]), "r"(b[1]));
}
#define LDSM4(r0, r1, r2, r3, addr)                                                     \
    asm volatile("ldmatrix.sync.aligned.m8n8.x4.shared.b16 {%0,%1,%2,%3}, [%4];"        \
        : "=r"(r0), "=r"(r1), "=r"(r2), "=r"(r3) : "r"(addr))
#define LDSM2(r0, r1, addr)                                                             \
    asm volatile("ldmatrix.sync.aligned.m8n8.x2.shared.b16 {%0,%1}, [%2];"              \
        : "=r"(r0), "=r"(r1) : "r"(addr))
__device__ __forceinline__ uint32_t pack_bf2(float a, float b) {
    __nv_bfloat162 p = __floats2bfloat162_rn(a, b);
    return *(uint32_t*)&p;
}

// smem layout shared by k_gemm / k_tile
#define AH_OFF 0
#define AL_OFF 18432
#define BH_OFF 36864
#define BL_OFF 71680
#define PS_OFF 106496
#define PQ_OFF 108544
#define GSMEM  110592
#define TSMEM  106496

__device__ __forceinline__ void load_achunk(const float* __restrict__ At, int lda, int coff,
                                            uint32_t* Ah, uint32_t* Al, int t) {
#pragma unroll
    for (int j = 0; j < 8; j++) {
        int idx = t + j * 256;
        int row = idx >> 4, c4 = (idx & 15) * 4;
        float4 v = *(const float4*)(At + (size_t)row * lda + coff + c4);
        uint32_t x = __float_as_uint(v.x), y = __float_as_uint(v.y);
        uint32_t z = __float_as_uint(v.z), w = __float_as_uint(v.w);
        uint32_t h0 = (y & 0xFFFF0000u) | (x >> 16);
        uint32_t h1 = (w & 0xFFFF0000u) | (z >> 16);
        float lx = v.x - __uint_as_float(x & 0xFFFF0000u);
        float ly = v.y - __uint_as_float(y & 0xFFFF0000u);
        float lz = v.z - __uint_as_float(z & 0xFFFF0000u);
        float lw = v.w - __uint_as_float(w & 0xFFFF0000u);
        int kp = c4 >> 1;
        *(uint2*)&Ah[row * 36 + kp] = make_uint2(h0, h1);
        *(uint2*)&Al[row * 36 + kp] = make_uint2(pack_bf2(lx, ly), pack_bf2(lz, lw));
    }
}

// ============ generic 128x128x128 bf16x3 tile GEMM: C = A@W (+bias)(relu) ============
__global__ __launch_bounds__(256, 2) void k_tile(
    const float* __restrict__ A, int lda, int aXstep, int aYstep,
    const float* __restrict__ W, int ldw, int wYstep,
    float* __restrict__ C, int ldc, int cXstep, int cYstep,
    const float* __restrict__ bias, int bYstep, int relu) {
    extern __shared__ char sm[];
    uint32_t* Ah = (uint32_t*)(sm + AH_OFF);
    uint32_t* Al = (uint32_t*)(sm + AL_OFF);
    uint32_t* Bh = (uint32_t*)(sm + BH_OFF);
    uint32_t* Bl = (uint32_t*)(sm + BL_OFF);
    const int t = threadIdx.x;
    const float* At = A + (size_t)blockIdx.x * aXstep + (size_t)blockIdx.y * aYstep;
    const float* Wt = W + (size_t)blockIdx.y * wYstep;
    float* Ct = C + (size_t)blockIdx.x * cXstep + (size_t)blockIdx.y * cYstep;
    const float* bt = bias ? bias + (size_t)blockIdx.y * bYstep : nullptr;

#pragma unroll
    for (int j = 0; j < 32; j++) {
        int e = t + j * 256;
        int kp = e >> 7, n = e & 127;
        float a = Wt[(size_t)(2 * kp) * ldw + n];
        float b = Wt[(size_t)(2 * kp + 1) * ldw + n];
        uint32_t ab = __float_as_uint(a), bb = __float_as_uint(b);
        Bh[n * 68 + kp] = (bb & 0xFFFF0000u) | (ab >> 16);
        float la = a - __uint_as_float(ab & 0xFFFF0000u);
        float lb = b - __uint_as_float(bb & 0xFFFF0000u);
        Bl[n * 68 + kp] = pack_bf2(la, lb);
    }
    load_achunk(At, lda, 0, Ah, Al, t);
    __syncthreads();

    const int w = t >> 5, lane = t & 31;
    const int wm = w >> 2, wn = w & 3;
    const int gid = lane >> 2, lid = lane & 3;
    const uint32_t sb = smem_u32(sm);
    const uint32_t aoff = (uint32_t)((lane & 15) * 144 + (lane >> 4) * 16);
    const uint32_t boff = (uint32_t)(((lane >> 4) * 8 + (lane & 7)) * 272 + ((lane >> 3) & 1) * 16);
    uint32_t addrA[4], addrB[2];
#pragma unroll
    for (int mt = 0; mt < 4; mt++)
        addrA[mt] = sb + AH_OFF + (wm * 64 + mt * 16) * 144 + aoff;
#pragma unroll
    for (int p = 0; p < 2; p++)
        addrB[p] = sb + BH_OFF + (wn * 32 + p * 16) * 272 + boff;

    float acc[4][4][4];
#pragma unroll
    for (int mt = 0; mt < 4; mt++)
#pragma unroll
        for (int nt = 0; nt < 4; nt++)
#pragma unroll
            for (int q = 0; q < 4; q++) acc[mt][nt][q] = 0.f;

#pragma unroll
    for (int chunk = 0; chunk < 2; chunk++) {
#pragma unroll
        for (int ks2 = 0; ks2 < 4; ks2++) {
            const uint32_t bAo = ks2 * 32;
            const uint32_t bBo = chunk * 128 + ks2 * 32;
            uint32_t ah[4][4], al[4][4], bh[4][2], bl[4][2];
#pragma unroll
            for (int mt = 0; mt < 4; mt++) {
                LDSM4(ah[mt][0], ah[mt][1], ah[mt][2], ah[mt][3], addrA[mt] + bAo);
                LDSM4(al[mt][0], al[mt][1], al[mt][2], al[mt][3], addrA[mt] + 18432 + bAo);
            }
            LDSM4(bh[0][0], bh[0][1], bh[1][0], bh[1][1], addrB[0] + bBo);
            LDSM4(bh[2][0], bh[2][1], bh[3][0], bh[3][1], addrB[1] + bBo);
            LDSM4(bl[0][0], bl[0][1], bl[1][0], bl[1][1], addrB[0] + 34816 + bBo);
            LDSM4(bl[2][0], bl[2][1], bl[3][0], bl[3][1], addrB[1] + 34816 + bBo);
#pragma unroll
            for (int mt = 0; mt < 4; mt++)
#pragma unroll
                for (int nt = 0; nt < 4; nt++) {
                    mma_bf16(acc[mt][nt], ah[mt], bh[nt]);
                    mma_bf16(acc[mt][nt], ah[mt], bl[nt]);
                    mma_bf16(acc[mt][nt], al[mt], bh[nt]);
                }
        }
        __syncthreads();
        if (chunk == 0) { load_achunk(At, lda, 64, Ah, Al, t); __syncthreads(); }
    }

    int cc[4];
#pragma unroll
    for (int nt = 0; nt < 4; nt++) cc[nt] = wn * 32 + nt * 8 + lid * 2;
#pragma unroll
    for (int nt = 0; nt < 4; nt++) {
        float2 bb = bt ? *(const float2*)&bt[cc[nt]] : make_float2(0.f, 0.f);
#pragma unroll
        for (int mt = 0; mt < 4; mt++) {
            int r0 = wm * 64 + mt * 16 + gid;
            float2 o0 = make_float2(acc[mt][nt][0] + bb.x, acc[mt][nt][1] + bb.y);
            float2 o1 = make_float2(acc[mt][nt][2] + bb.x, acc[mt][nt][3] + bb.y);
            if (relu) {
                o0.x = fmaxf(o0.x, 0.f); o0.y = fmaxf(o0.y, 0.f);
                o1.x = fmaxf(o1.x, 0.f); o1.y = fmaxf(o1.y, 0.f);
            }
            *(float2*)&Ct[(size_t)r0 * ldc + cc[nt]] = o0;
            *(float2*)&Ct[(size_t)(r0 + 8) * ldc + cc[nt]] = o1;
        }
    }
}

// qh[n][h][c] = sum_dh wk[c, h*16+dh] * q[n, h*16+dh] * 0.25  (bk drops out of softmax)
__global__ void k_qh(const float* __restrict__ wk) {
    int n = blockIdx.x, c = threadIdx.x;
    __shared__ float qs[DMODEL];
    qs[c] = g_q[n * DMODEL + c];
    __syncthreads();
    const float* wrow = wk + c * DMODEL;
#pragma unroll
    for (int h = 0; h < 8; h++) {
        float a = 0.f;
#pragma unroll
        for (int dh = 0; dh < 16; dh++) a += wrow[h * 16 + dh] * qs[h * 16 + dh];
        g_qh[n * 1024 + h * 128 + c] = a * 0.25f;
    }
}

// ============ big fused GEMM (unchanged from round 5) ============
__global__ __launch_bounds__(256, 2) void k_gemm(
    const float* __restrict__ Asrc, const float* __restrict__ W, int mode,
    const float* __restrict__ gA, const float* __restrict__ bA,
    const float* __restrict__ res_in, const float* __restrict__ bpe,
    const float* __restrict__ gB, const float* __restrict__ bB,
    float* __restrict__ outp) {
    extern __shared__ char sm[];
    uint32_t* Ah = (uint32_t*)(sm + AH_OFF);
    uint32_t* Al = (uint32_t*)(sm + AL_OFF);
    uint32_t* Bh = (uint32_t*)(sm + BH_OFF);
    uint32_t* Bl = (uint32_t*)(sm + BL_OFF);
    float* ps = (float*)(sm + PS_OFF);
    float* pq = (float*)(sm + PQ_OFF);
    const int t = threadIdx.x;
    const float* Abase = mode ? (const float*)g_mem : Asrc;
    const float* At = Abase + (size_t)blockIdx.x * 16384;

#pragma unroll
    for (int j = 0; j < 32; j++) {
        int e = t + j * 256;
        int kp = e >> 7, n = e & 127;
        float a = W[(2 * kp) * 128 + n];
        float b = W[(2 * kp + 1) * 128 + n];
        uint32_t ab = __float_as_uint(a), bb = __float_as_uint(b);
        Bh[n * 68 + kp] = (bb & 0xFFFF0000u) | (ab >> 16);
        float la = a - __uint_as_float(ab & 0xFFFF0000u);
        float lb = b - __uint_as_float(bb & 0xFFFF0000u);
        Bl[n * 68 + kp] = pack_bf2(la, lb);
    }
    load_achunk(At, 128, 0, Ah, Al, t);
    __syncthreads();

    const int w = t >> 5, lane = t & 31;
    const int wm = w >> 2, wn = w & 3;
    const int gid = lane >> 2, lid = lane & 3;
    const uint32_t sb = smem_u32(sm);
    const uint32_t aoff = (uint32_t)((lane & 15) * 144 + (lane >> 4) * 16);
    const uint32_t boff = (uint32_t)(((lane >> 4) * 8 + (lane & 7)) * 272 + ((lane >> 3) & 1) * 16);
    uint32_t addrA[4], addrB[2];
#pragma unroll
    for (int mt = 0; mt < 4; mt++)
        addrA[mt] = sb + AH_OFF + (wm * 64 + mt * 16) * 144 + aoff;
#pragma unroll
    for (int p = 0; p < 2; p++)
        addrB[p] = sb + BH_OFF + (wn * 32 + p * 16) * 272 + boff;

    float acc[4][4][4];
#pragma unroll
    for (int mt = 0; mt < 4; mt++)
#pragma unroll
        for (int nt = 0; nt < 4; nt++)
#pragma unroll
            for (int q = 0; q < 4; q++) acc[mt][nt][q] = 0.f;

#pragma unroll
    for (int chunk = 0; chunk < 2; chunk++) {
#pragma unroll
        for (int ks2 = 0; ks2 < 4; ks2++) {
            const uint32_t bAo = ks2 * 32;
            const uint32_t bBo = chunk * 128 + ks2 * 32;
            uint32_t ah[4][4], al[4][4], bh[4][2], bl[4][2];
#pragma unroll
            for (int mt = 0; mt < 4; mt++) {
                LDSM4(ah[mt][0], ah[mt][1], ah[mt][2], ah[mt][3], addrA[mt] + bAo);
                LDSM4(al[mt][0], al[mt][1], al[mt][2], al[mt][3], addrA[mt] + 18432 + bAo);
            }
            LDSM4(bh[0][0], bh[0][1], bh[1][0], bh[1][1], addrB[0] + bBo);
            LDSM4(bh[2][0], bh[2][1], bh[3][0], bh[3][1], addrB[1] + bBo);
            LDSM4(bl[0][0], bl[0][1], bl[1][0], bl[1][1], addrB[0] + 34816 + bBo);
            LDSM4(bl[2][0], bl[2][1], bl[3][0], bl[3][1], addrB[1] + 34816 + bBo);
#pragma unroll
            for (int mt = 0; mt < 4; mt++)
#pragma unroll
                for (int nt = 0; nt < 4; nt++) {
                    mma_bf16(acc[mt][nt], ah[mt], bh[nt]);
                    mma_bf16(acc[mt][nt], ah[mt], bl[nt]);
                    mma_bf16(acc[mt][nt], al[mt], bh[nt]);
                }
        }
        __syncthreads();
        if (chunk == 0) { load_achunk(At, 128, 64, Ah, Al, t); __syncthreads(); }
    }

    int cc[4];
#pragma unroll
    for (int nt = 0; nt < 4; nt++) cc[nt] = wn * 32 + nt * 8 + lid * 2;

    if (mode == 0) {
        const int s_tile = blockIdx.x >> 2, nbase = (blockIdx.x & 3) * 128;
#pragma unroll
        for (int nt = 0; nt < 4; nt++) {
            float2 ntv = *(const float2*)&g_nt[s_tile * 128 + cc[nt]];
#pragma unroll
            for (int mt = 0; mt < 4; mt++) {
                int r0 = wm * 64 + mt * 16 + gid;
                float2 n0 = *(const float2*)&g_ns[(nbase + r0) * 128 + cc[nt]];
                float2 n1 = *(const float2*)&g_ns[(nbase + r0 + 8) * 128 + cc[nt]];
                acc[mt][nt][0] += n0.x + ntv.x; acc[mt][nt][1] += n0.y + ntv.y;
                acc[mt][nt][2] += n1.x + ntv.x; acc[mt][nt][3] += n1.y + ntv.y;
            }
        }
        float s8[8], q8[8];
#pragma unroll
        for (int mt = 0; mt < 4; mt++) {
            float sl = 0, ql = 0, sh = 0, qh = 0;
#pragma unroll
            for (int nt = 0; nt < 4; nt++) {
                sl += acc[mt][nt][0] + acc[mt][nt][1];
                ql += acc[mt][nt][0]*acc[mt][nt][0] + acc[mt][nt][1]*acc[mt][nt][1];
                sh += acc[mt][nt][2] + acc[mt][nt][3];
                qh += acc[mt][nt][2]*acc[mt][nt][2] + acc[mt][nt][3]*acc[mt][nt][3];
            }
            s8[mt*2] = sl; q8[mt*2] = ql; s8[mt*2+1] = sh; q8[mt*2+1] = qh;
        }
#pragma unroll
        for (int i = 0; i < 8; i++) {
            s8[i] += __shfl_xor_sync(0xffffffffu, s8[i], 1);
            s8[i] += __shfl_xor_sync(0xffffffffu, s8[i], 2);
            q8[i] += __shfl_xor_sync(0xffffffffu, q8[i], 1);
            q8[i] += __shfl_xor_sync(0xffffffffu, q8[i], 2);
        }
        if (lid == 0) {
#pragma unroll
            for (int mt = 0; mt < 4; mt++) {
                int r0 = wm * 64 + mt * 16 + gid;
                ps[r0 * 4 + wn] = s8[mt*2];  pq[r0 * 4 + wn] = q8[mt*2];
                ps[(r0+8)*4 + wn] = s8[mt*2+1]; pq[(r0+8)*4 + wn] = q8[mt*2+1];
            }
        }
        __syncthreads();
        float mean[8], rstd[8];
#pragma unroll
        for (int mt = 0; mt < 4; mt++) {
#pragma unroll
            for (int hh = 0; hh < 2; hh++) {
                int r = wm * 64 + mt * 16 + gid + hh * 8;
                float4 a = *(float4*)&ps[r * 4];
                float4 b = *(float4*)&pq[r * 4];
                float m = (a.x + a.y + a.z + a.w) * (1.f/128.f);
                float v = (b.x + b.y + b.z + b.w) * (1.f/128.f) - m * m;
                mean[mt*2+hh] = m; rstd[mt*2+hh] = rsqrtf(v + LN_EPS);
            }
        }
        float* orow = g_mem + (size_t)blockIdx.x * 16384;
#pragma unroll
        for (int nt = 0; nt < 4; nt++) {
            float2 gv = *(const float2*)&gA[cc[nt]];
            float2 bv2 = *(const float2*)&bA[cc[nt]];
#pragma unroll
            for (int mt = 0; mt < 4; mt++) {
                int r0 = wm * 64 + mt * 16 + gid;
                float2 o0, o1;
                o0.x = fmaxf((acc[mt][nt][0]-mean[mt*2])*rstd[mt*2]*gv.x + bv2.x, 0.f);
                o0.y = fmaxf((acc[mt][nt][1]-mean[mt*2])*rstd[mt*2]*gv.y + bv2.y, 0.f);
                o1.x = fmaxf((acc[mt][nt][2]-mean[mt*2+1])*rstd[mt*2+1]*gv.x + bv2.x, 0.f);
                o1.y = fmaxf((acc[mt][nt][3]-mean[mt*2+1])*rstd[mt*2+1]*gv.y + bv2.y, 0.f);
                *(float2*)&orow[r0 * 128 + cc[nt]] = o0;
                *(float2*)&orow[(r0 + 8) * 128 + cc[nt]] = o1;
            }
        }
    } else {
#pragma unroll
        for (int nt = 0; nt < 4; nt++) {
            float2 bp = *(const float2*)&bpe[cc[nt]];
#pragma unroll
            for (int mt = 0; mt < 4; mt++) {
                acc[mt][nt][0] += bp.x; acc[mt][nt][1] += bp.y;
                acc[mt][nt][2] += bp.x; acc[mt][nt][3] += bp.y;
            }
        }
        float s8[8], q8[8];
#pragma unroll
        for (int mt = 0; mt < 4; mt++) {
            float sl = 0, ql = 0, sh = 0, qh = 0;
#pragma unroll
            for (int nt = 0; nt < 4; nt++) {
                sl += acc[mt][nt][0] + acc[mt][nt][1];
                ql += acc[mt][nt][0]*acc[mt][nt][0] + acc[mt][nt][1]*acc[mt][nt][1];
                sh += acc[mt][nt][2] + acc[mt][nt][3];
                qh += acc[mt][nt][2]*acc[mt][nt][2] + acc[mt][nt][3]*acc[mt][nt][3];
            }
            s8[mt*2] = sl; q8[mt*2] = ql; s8[mt*2+1] = sh; q8[mt*2+1] = qh;
        }
#pragma unroll
        for (int i = 0; i < 8; i++) {
            s8[i] += __shfl_xor_sync(0xffffffffu, s8[i], 1);
            s8[i] += __shfl_xor_sync(0xffffffffu, s8[i], 2);
            q8[i] += __shfl_xor_sync(0xffffffffu, q8[i], 1);
            q8[i] += __shfl_xor_sync(0xffffffffu, q8[i], 2);
        }
        if (lid == 0) {
#pragma unroll
            for (int mt = 0; mt < 4; mt++) {
                int r0 = wm * 64 + mt * 16 + gid;
                ps[r0 * 4 + wn] = s8[mt*2];  pq[r0 * 4 + wn] = q8[mt*2];
                ps[(r0+8)*4 + wn] = s8[mt*2+1]; pq[(r0+8)*4 + wn] = q8[mt*2+1];
            }
        }
        __syncthreads();
        float mean[8], rstd[8];
#pragma unroll
        for (int mt = 0; mt < 4; mt++) {
#pragma unroll
            for (int hh = 0; hh < 2; hh++) {
                int r = wm * 64 + mt * 16 + gid + hh * 8;
                float4 a = *(float4*)&ps[r * 4];
                float4 b = *(float4*)&pq[r * 4];
                float m = (a.x + a.y + a.z + a.w) * (1.f/128.f);
                float v = (b.x + b.y + b.z + b.w) * (1.f/128.f) - m * m;
                mean[mt*2+hh] = m; rstd[mt*2+hh] = rsqrtf(v + LN_EPS);
            }
        }
        const float* erow = res_in + (size_t)blockIdx.x * 16384;
#pragma unroll
        for (int nt = 0; nt < 4; nt++) {
            float2 g1 = *(const float2*)&gA[cc[nt]];
            float2 b1 = *(const float2*)&bA[cc[nt]];
#pragma unroll
            for (int mt = 0; mt < 4; mt++) {
                int r0 = wm * 64 + mt * 16 + gid;
                float2 e0 = *(const float2*)&erow[r0 * 128 + cc[nt]];
                float2 e1 = *(const float2*)&erow[(r0 + 8) * 128 + cc[nt]];
                acc[mt][nt][0] = e0.x + fmaxf((acc[mt][nt][0]-mean[mt*2])*rstd[mt*2]*g1.x + b1.x, 0.f);
                acc[mt][nt][1] = e0.y + fmaxf((acc[mt][nt][1]-mean[mt*2])*rstd[mt*2]*g1.y + b1.y, 0.f);
                acc[mt][nt][2] = e1.x + fmaxf((acc[mt][nt][2]-mean[mt*2+1])*rstd[mt*2+1]*g1.x + b1.x, 0.f);
                acc[mt][nt][3] = e1.y + fmaxf((acc[mt][nt][3]-mean[mt*2+1])*rstd[mt*2+1]*g1.y + b1.y, 0.f);
            }
        }
        __syncthreads();
#pragma unroll
        for (int mt = 0; mt < 4; mt++) {
            float sl = 0, ql = 0, sh = 0, qh = 0;
#pragma unroll
            for (int nt = 0; nt < 4; nt++) {
                sl += acc[mt][nt][0] + acc[mt][nt][1];
                ql += acc[mt][nt][0]*acc[mt][nt][0] + acc[mt][nt][1]*acc[mt][nt][1];
                sh += acc[mt][nt][2] + acc[mt][nt][3];
                qh += acc[mt][nt][2]*acc[mt][nt][2] + acc[mt][nt][3]*acc[mt][nt][3];
            }
            s8[mt*2] = sl; q8[mt*2] = ql; s8[mt*2+1] = sh; q8[mt*2+1] = qh;
        }
#pragma unroll
        for (int i = 0; i < 8; i++) {
            s8[i] += __shfl_xor_sync(0xffffffffu, s8[i], 1);
            s8[i] += __shfl_xor_sync(0xffffffffu, s8[i], 2);
            q8[i] += __shfl_xor_sync(0xffffffffu, q8[i], 1);
            q8[i] += __shfl_xor_sync(0xffffffffu, q8[i], 2);
        }
        if (lid == 0) {
#pragma unroll
            for (int mt = 0; mt < 4; mt++) {
                int r0 = wm * 64 + mt * 16 + gid;
                ps[r0 * 4 + wn] = s8[mt*2];  pq[r0 * 4 + wn] = q8[mt*2];
                ps[(r0+8)*4 + wn] = s8[mt*2+1]; pq[(r0+8)*4 + wn] = q8[mt*2+1];
            }
        }
        __syncthreads();
#pragma unroll
        for (int mt = 0; mt < 4; mt++) {
#pragma unroll
            for (int hh = 0; hh < 2; hh++) {
                int r = wm * 64 + mt * 16 + gid + hh * 8;
                float4 a = *(float4*)&ps[r * 4];
                float4 b = *(float4*)&pq[r * 4];
                float m = (a.x + a.y + a.z + a.w) * (1.f/128.f);
                float v = (b.x + b.y + b.z + b.w) * (1.f/128.f) - m * m;
                mean[mt*2+hh] = m; rstd[mt*2+hh] = rsqrtf(v + LN_EPS);
            }
        }
        float* orow = outp + (size_t)blockIdx.x * 16384;
#pragma unroll
        for (int nt = 0; nt < 4; nt++) {
            float2 g2 = *(const float2*)&gB[cc[nt]];
            float2 b2 = *(const float2*)&bB[cc[nt]];
#pragma unroll
            for (int mt = 0; mt < 4; mt++) {
                int r0 = wm * 64 + mt * 16 + gid;
                float2 o0, o1;
                o0.x = (acc[mt][nt][0]-mean[mt*2])*rstd[mt*2]*g2.x + b2.x;
                o0.y = (acc[mt][nt][1]-mean[mt*2])*rstd[mt*2]*g2.y + b2.y;
                o1.x = (acc[mt][nt][2]-mean[mt*2+1])*rstd[mt*2+1]*g2.x + b2.x;
                o1.y = (acc[mt][nt][3]-mean[mt*2+1])*rstd[mt*2+1]*g2.y + b2.y;
                *(float2*)&orow[r0 * 128 + cc[nt]] = o0;
                *(float2*)&orow[(r0 + 8) * 128 + cc[nt]] = o1;
            }
        }
    }
}

// ============ fused attention (512 threads, MMA scores): one block per n ============
#define MH_OFF   0
#define QB_OFF   139264
#define ATT_OFF  141440
#define MK_OFF   157824
#define ATT_SMEM 158336
__global__ __launch_bounds__(512) void k_attn2(
    const unsigned char* __restrict__ mask,
    const float* __restrict__ wv, const float* __restrict__ bv) {
    extern __shared__ char sm[];
    __nv_bfloat16* mh = (__nv_bfloat16*)(sm + MH_OFF);
    __nv_bfloat16* qb = (__nv_bfloat16*)(sm + QB_OFF);
    float* att = (float*)(sm + ATT_OFF);
    unsigned char* mk = (unsigned char*)(sm + MK_OFF);
    const int n = blockIdx.x, t = threadIdx.x, w = t >> 5, lane = t & 31;
    const uint32_t sb = smem_u32(sm);

    for (int i = t; i < 1024; i += 512) {
        int h = i >> 7, c = i & 127;
        qb[h * 136 + c] = __float2bfloat16_rn(g_qh[n * 1024 + i]);
    }
    mk[t & 511] = mask[n * 512 + (t & 511)];
#pragma unroll 4
    for (int j = 0; j < 32; j++) {
        int idx = t + j * 512;
        int s = idx >> 5, c4 = (idx & 31) * 4;
        float4 v = *(const float4*)&g_mem[((size_t)s * 512 + n) * 128 + c4];
        *(uint2*)&mh[s * 136 + c4] = make_uint2(pack_bf2(v.x, v.y), pack_bf2(v.z, v.w));
    }
    __syncthreads();

    // ---- scores via MMA: warp w covers s in [w*32, w*32+32) ----
    {
        const int l2 = lane & 15;
        const uint32_t aoffA = (uint32_t)((lane & 15) * 272 + (lane >> 4) * 16);
        const uint32_t qaddr = sb + QB_OFF + (uint32_t)((l2 & 7) * 272 + ((l2 >> 3) & 1) * 16);
        float acc[2][4];
#pragma unroll
        for (int mt = 0; mt < 2; mt++)
#pragma unroll
            for (int q = 0; q < 4; q++) acc[mt][q] = 0.f;
#pragma unroll
        for (int ks = 0; ks < 8; ks++) {
            uint32_t bq[2];
            LDSM2(bq[0], bq[1], qaddr + ks * 32);
#pragma unroll
            for (int mt = 0; mt < 2; mt++) {
                uint32_t a[4];
                LDSM4(a[0], a[1], a[2], a[3],
                      sb + MH_OFF + (w * 32 + mt * 16) * 272 + aoffA + ks * 32);
                mma_bf16(acc[mt], a, bq);
            }
        }
        const int gid = lane >> 2, lid = lane & 3;
#pragma unroll
        for (int mt = 0; mt < 2; mt++) {
            int s = w * 32 + mt * 16 + gid;
            att[(2 * lid) * 512 + s]     = acc[mt][0];
            att[(2 * lid + 1) * 512 + s] = acc[mt][1];
            att[(2 * lid) * 512 + s + 8]     = acc[mt][2];
            att[(2 * lid + 1) * 512 + s + 8] = acc[mt][3];
        }
    }
    __syncthreads();

    // ---- softmax per head (warps 0..7), apply mask ----
    if (w < 8) {
        const int h = w;
        float sc[16];
        float mx = -3.402823466e38f;
#pragma unroll
        for (int i = 0; i < 16; i++) {
            int s = lane + i * 32;
            sc[i] = mk[s] ? -3.402823466e38f : att[h * 512 + s];
            mx = fmaxf(mx, sc[i]);
        }
        mx = warp_max(mx);
        float sum = 0.f;
#pragma unroll
        for (int i = 0; i < 16; i++) { sc[i] = __expf(sc[i] - mx); sum += sc[i]; }
        sum = warp_sum(sum);
        float inv = 1.f / sum;
#pragma unroll
        for (int i = 0; i < 16; i++) att[h * 512 + lane + i * 32] = sc[i] * inv;
    }
    __syncthreads();

    // ---- weighted sum: warp w handles s in [w*32, w*32+32) ----
    float r8[8][4];
#pragma unroll
    for (int h = 0; h < 8; h++)
#pragma unroll
        for (int q = 0; q < 4; q++) r8[h][q] = 0.f;
    for (int si = 0; si < 32; si++) {
        int s = w * 32 + si;
        float2 f0 = __bfloat1622float2(*(__nv_bfloat162*)&mh[s * 136 + lane * 4]);
        float2 f1 = __bfloat1622float2(*(__nv_bfloat162*)&mh[s * 136 + lane * 4 + 2]);
#pragma unroll
        for (int h = 0; h < 8; h++) {
            float a = att[h * 512 + s];
            r8[h][0] += a * f0.x; r8[h][1] += a * f0.y;
            r8[h][2] += a * f1.x; r8[h][3] += a * f1.y;
        }
    }
    __syncthreads();                     // all mh reads done
    float* rp = (float*)sm;              // [16 warps][8h][128] = 64KB, aliases mh
#pragma unroll
    for (int h = 0; h < 8; h++)
        *(float4*)&rp[(w * 8 + h) * 128 + lane * 4] =
            make_float4(r8[h][0], r8[h][1], r8[h][2], r8[h][3]);
    __syncthreads();
    float* rfin = (float*)(sm + 65536);  // [h][128], 4KB
    for (int i = t; i < 1024; i += 512) {
        int h = i >> 7, c = i & 127;
        float v = 0.f;
#pragma unroll
        for (int ww = 0; ww < 16; ww++) v += rp[(ww * 8 + h) * 128 + c];
        rfin[i] = v;
    }
    __syncthreads();

    // ---- ctx = r @ wv + bv (sum attn = 1 folds bv through) ----
    if (t < 128) {
        int h = t >> 4;
        float a = bv[t];
#pragma unroll 8
        for (int c = 0; c < 128; c++) a += rfin[h * 128 + c] * wv[c * 128 + t];
        g_ctx[n * 128 + t] = a;
    }
}

// ============ x1 = LN(node + ctx @ wo + bo) ============
__global__ void k_out1(const float* __restrict__ node, const float* __restrict__ wo,
                       const float* __restrict__ bo, const float* __restrict__ g2,
                       const float* __restrict__ b2) {
    int row = blockIdx.x, d = threadIdx.x;
    __shared__ float cs[128];
    __shared__ float rsum[4], rsq[4];
    cs[d] = g_ctx[row * 128 + d];
    __syncthreads();
    float a = bo[d];
#pragma unroll 8
    for (int c = 0; c < 128; c++) a += cs[c] * wo[c * 128 + d];
    a += node[row * 128 + d];
    float s1 = warp_sum(a), s2 = warp_sum(a * a);
    if ((d & 31) == 0) { rsum[d >> 5] = s1; rsq[d >> 5] = s2; }
    __syncthreads();
    float sum = rsum[0] + rsum[1] + rsum[2] + rsum[3];
    float sq = rsq[0] + rsq[1] + rsq[2] + rsq[3];
    float mean = sum * (1.f / 128.f);
    float rs = rsqrtf(sq * (1.f / 128.f) - mean * mean + LN_EPS);
    g_x1[row * 128 + d] = (a - mean) * rs * g2[d] + b2[d];
}

// ============ final: out_x = LN(x1 + sum_k ffp[k] + b2) ============
__global__ void k_fin(const float* __restrict__ b2, const float* __restrict__ g3,
                      const float* __restrict__ b3, float* __restrict__ out_x) {
    int row = blockIdx.x, d = threadIdx.x;
    __shared__ float rsum[4], rsq[4];
    float v = g_x1[row * 128 + d] + b2[d];
#pragma unroll
    for (int k = 0; k < 16; k++) v += g_ffp[k * 65536 + row * 128 + d];
    float s1 = warp_sum(v), s2 = warp_sum(v * v);
    if ((d & 31) == 0) { rsum[d >> 5] = s1; rsq[d >> 5] = s2; }
    __syncthreads();
    float sum = rsum[0] + rsum[1] + rsum[2] + rsum[3];
    float sq = rsq[0] + rsq[1] + rsq[2] + rsq[3];
    float mean = sum * (1.f / 128.f);
    float rs = rsqrtf(sq * (1.f / 128.f) - mean * mean + LN_EPS);
    out_x[row * 128 + d] = (v - mean) * rs * g3[d] + b3[d];
}

extern "C" void kernel_launch(void* const* d_in, const int* in_sizes, int n_in,
                              void* d_out, int out_size) {
    (void)in_sizes; (void)n_in; (void)out_size;
    const float* node     = (const float*)d_in[0];
    const float* edge     = (const float*)d_in[1];
    const unsigned char* mask = (const unsigned char*)d_in[2];
    const float* w_mem_e  = (const float*)d_in[3];
    const float* w_mem_s  = (const float*)d_in[4];
    const float* w_mem_t  = (const float*)d_in[5];
    const float* b_mem    = (const float*)d_in[6];
    const float* g_ln_mem = (const float*)d_in[7];
    const float* b_ln_mem = (const float*)d_in[8];
    const float* w_pe     = (const float*)d_in[9];
    const float* b_pe     = (const float*)d_in[10];
    const float* g_ln_pe  = (const float*)d_in[11];
    const float* b_ln_pe  = (const float*)d_in[12];
    const float* g_ln_edge= (const float*)d_in[13];
    const float* b_ln_edge= (const float*)d_in[14];
    const float* wq       = (const float*)d_in[15];
    const float* bq       = (const float*)d_in[16];
    const float* wk       = (const float*)d_in[17];
    /* bk (d_in[18]) provably drops out of softmax */
    const float* wv       = (const float*)d_in[19];
    const float* bv       = (const float*)d_in[20];
    const float* wo       = (const float*)d_in[21];
    const float* bo       = (const float*)d_in[22];
    const float* g_ln2    = (const float*)d_in[23];
    const float* b_ln2    = (const float*)d_in[24];
    const float* w_ff1    = (const float*)d_in[25];
    const float* b_ff1    = (const float*)d_in[26];
    const float* w_ff2    = (const float*)d_in[27];
    const float* b_ff2    = (const float*)d_in[28];
    const float* g_ln3    = (const float*)d_in[29];
    const float* b_ln3    = (const float*)d_in[30];

    float* out_x = (float*)d_out;
    float* out_edge = (float*)d_out + NSEQ * DMODEL;

    cudaFuncSetAttribute(k_gemm, cudaFuncAttributeMaxDynamicSharedMemorySize, GSMEM);
    cudaFuncSetAttribute(k_tile, cudaFuncAttributeMaxDynamicSharedMemorySize, TSMEM);
    cudaFuncSetAttribute(k_attn2, cudaFuncAttributeMaxDynamicSharedMemorySize, ATT_SMEM);

    float* d_ns; cudaGetSymbolAddress((void**)&d_ns, g_ns);
    float* d_nt; cudaGetSymbolAddress((void**)&d_nt, g_nt);
    float* d_q;  cudaGetSymbolAddress((void**)&d_q, g_q);
    float* d_h;  cudaGetSymbolAddress((void**)&d_h, g_h);
    float* d_ffp;cudaGetSymbolAddress((void**)&d_ffp, g_ffp);
    float* d_x1; cudaGetSymbolAddress((void**)&d_x1, g_x1);

    // ns = node@w_mem_s + b_mem ; nt = node@w_mem_t ; q = node@wq + bq
    k_tile<<<dim3(4,1), 256, TSMEM>>>(node, 128, 16384, 0, w_mem_s, 128, 0,
                                      d_ns, 128, 16384, 0, b_mem, 0, 0);
    k_tile<<<dim3(4,1), 256, TSMEM>>>(node, 128, 16384, 0, w_mem_t, 128, 0,
                                      d_nt, 128, 16384, 0, nullptr, 0, 0);
    k_tile<<<dim3(4,1), 256, TSMEM>>>(node, 128, 16384, 0, wq, 128, 0,
                                      d_q, 128, 16384, 0, bq, 0, 0);
    k_qh<<<512, 128>>>(wk);
    // memory = relu(LN(edge @ w_mem_e + ns + nt))
    k_gemm<<<2048, 256, GSMEM>>>(edge, w_mem_e, 0, g_ln_mem, b_ln_mem,
                                 nullptr, nullptr, nullptr, nullptr, nullptr);
    // edge_new = LN(edge + relu(LN(memory @ w_pe + b_pe)))
    k_gemm<<<2048, 256, GSMEM>>>(nullptr, w_pe, 1, g_ln_pe, b_ln_pe,
                                 edge, b_pe, g_ln_edge, b_ln_edge, out_edge);
    k_attn2<<<512, 512, ATT_SMEM>>>(mask, wv, bv);
    k_out1<<<512, 128>>>(node, wo, bo, g_ln2, b_ln2);
    // h = relu(x1 @ w1 + b1)
    k_tile<<<dim3(4,16), 256, TSMEM>>>(d_x1, 128, 16384, 0, w_ff1, 2048, 128,
                                       d_h, 2048, 262144, 128, b_ff1, 128, 1);
    // ffp[k] = h_chunk @ w2_chunk
    k_tile<<<dim3(4,16), 256, TSMEM>>>(d_h, 2048, 262144, 128, w_ff2, 128, 16384,
                                       d_ffp, 128, 16384, 65536, nullptr, 0, 0);
    k_fin<<<512, 128>>>(b_ff2, g_ln3, b_ln3, out_x);
}

// round 7
// speedup vs baseline: 3.8508x; 1.4922x over previous
#include <cuda_runtime.h>
#include <cuda_bf16.h>
#include <cuda_fp16.h>
#include <cstdint>

#define NSEQ 512
#define DMODEL 128
#define LN_EPS 1e-5f

// ---- scratch (device globals; no runtime allocation) ----
__device__ float g_mem[(size_t)NSEQ * NSEQ * DMODEL];   // memory tensor (s, n, d)
__device__ float g_pre[3 * NSEQ * DMODEL];              // [ns | nt | q]
__device__ float g_qh[NSEQ * 1024];                     // [n][h][c]
__device__ float g_ctx[NSEQ * DMODEL];
__device__ float g_x1[NSEQ * DMODEL];
__device__ float g_h[512 * 2048];                       // ffn hidden
__device__ float g_ffp[16 * 512 * DMODEL];              // ffn split-K partials
__device__ float g_wcat[3 * DMODEL * DMODEL];           // packed pre weights
__device__ float g_bcat[3 * DMODEL];                    // packed pre biases

__device__ __forceinline__ float warp_sum(float v) {
#pragma unroll
    for (int o = 16; o; o >>= 1) v += __shfl_xor_sync(0xffffffffu, v, o);
    return v;
}
__device__ __forceinline__ float warp_max(float v) {
#pragma unroll
    for (int o = 16; o; o >>= 1) v = fmaxf(v, __shfl_xor_sync(0xffffffffu, v, o));
    return v;
}
__device__ __forceinline__ uint32_t smem_u32(const void* p) {
    uint32_t a;
    asm("{ .reg .u64 t; cvta.to.shared.u64 t, %1; cvt.u32.u64 %0, t; }" : "=r"(a) : "l"(p));
    return a;
}
__device__ __forceinline__ void mma_f16(float* c, const uint32_t* a, const uint32_t* b) {
    asm volatile(
        "mma.sync.aligned.m16n8k16.row.col.f32.f16.f16.f32 "
        "{%0,%1,%2,%3}, {%4,%5,%6,%7}, {%8,%9}, {%0,%1,%2,%3};"
        : "+f"(c[0]), "+f"(c[1]), "+f"(c[2]), "+f"(c[3])
        : "r"(a[0]), "r"(a[1]), "r"(a[2]), "r"(a[3]), "r"(b[0]), "r"(b[1]));
}
__device__ __forceinline__ void mma_bf16(float* c, const uint32_t* a, const uint32_t* b) {
    asm volatile(
        "mma.sync.aligned.m16n8k16.row.col.f32.bf16.bf16.f32 "
        "{%0,%1,%2,%3}, {%4,%5,%6,%7}, {%8,%9}, {%0,%1,%2,%3};"
        : "+f"(c[0]), "+f"(c[1]), "+f"(c[2]), "+f"(c[3])
        : "r"(a[0]), "r"(a[1]), "r"(a[2]), "r"(a[3]), "r"(b[0]), "r"(b[1]));
}
#define LDSM4(r0, r1, r2, r3, addr)                                                     \
    asm volatile("ldmatrix.sync.aligned.m8n8.x4.shared.b16 {%0,%1,%2,%3}, [%4];"        \
        : "=r"(r0), "=r"(r1), "=r"(r2), "=r"(r3) : "r"(addr))
#define LDSM2(r0, r1, addr)                                                             \
    asm volatile("ldmatrix.sync.aligned.m8n8.x2.shared.b16 {%0,%1}, [%2];"              \
        : "=r"(r0), "=r"(r1) : "r"(addr))
__device__ __forceinline__ uint32_t pack_h2(float a, float b) {
    __half2 p = __floats2half2_rn(a, b);
    return *(uint32_t*)&p;
}
__device__ __forceinline__ uint32_t pack_bf2(float a, float b) {
    __nv_bfloat162 p = __floats2bfloat162_rn(a, b);
    return *(uint32_t*)&p;
}

// smem layout: A h2 u32[128][68], B h2 u32[128][68], ps/pq f32[128][4]
#define AH_OFF 0
#define BH_OFF 34816
#define PS_OFF 69632
#define PQ_OFF 71680
#define GSMEM  73728
#define TSMEM  69632

__device__ __forceinline__ void load_atile(const float* __restrict__ At, int lda,
                                           uint32_t* Ah, int t) {
#pragma unroll
    for (int j = 0; j < 16; j++) {
        int idx = t + j * 256;
        int row = idx >> 5, c4 = (idx & 31) * 4;
        float4 v = *(const float4*)(At + (size_t)row * lda + c4);
        *(uint2*)&Ah[row * 68 + (c4 >> 1)] =
            make_uint2(pack_h2(v.x, v.y), pack_h2(v.z, v.w));
    }
}
__device__ __forceinline__ void load_btile(const float* __restrict__ Wt, int ldw,
                                           uint32_t* Bh, int t) {
#pragma unroll
    for (int j = 0; j < 32; j++) {
        int e = t + j * 256;
        int kp = e >> 7, n = e & 127;
        float a = Wt[(size_t)(2 * kp) * ldw + n];
        float b = Wt[(size_t)(2 * kp + 1) * ldw + n];
        Bh[n * 68 + kp] = pack_h2(a, b);
    }
}

// shared fp16 MMA mainloop: acc[4][4][4] for 64x32 warp tile, K=128
#define MMA_MAIN(sb)                                                                    \
    const int w = t >> 5, lane = t & 31;                                                \
    const int wm = w >> 2, wn = w & 3;                                                  \
    const int gid = lane >> 2, lid = lane & 3;                                          \
    const uint32_t aoff = (uint32_t)((lane & 15) * 272 + (lane >> 4) * 16);             \
    const uint32_t boff = (uint32_t)(((lane >> 4) * 8 + (lane & 7)) * 272               \
                                     + ((lane >> 3) & 1) * 16);                         \
    uint32_t addrA[4], addrB[2];                                                        \
    _Pragma("unroll")                                                                   \
    for (int mt = 0; mt < 4; mt++)                                                      \
        addrA[mt] = (sb) + AH_OFF + (wm * 64 + mt * 16) * 272 + aoff;                   \
    _Pragma("unroll")                                                                   \
    for (int p = 0; p < 2; p++)                                                         \
        addrB[p] = (sb) + BH_OFF + (wn * 32 + p * 16) * 272 + boff;                     \
    float acc[4][4][4];                                                                 \
    _Pragma("unroll")                                                                   \
    for (int mt = 0; mt < 4; mt++)                                                      \
        _Pragma("unroll")                                                               \
        for (int nt = 0; nt < 4; nt++)                                                  \
            _Pragma("unroll")                                                           \
            for (int q = 0; q < 4; q++) acc[mt][nt][q] = 0.f;                           \
    _Pragma("unroll")                                                                   \
    for (int ks = 0; ks < 8; ks++) {                                                    \
        uint32_t ah[4][4], bh[4][2];                                                    \
        _Pragma("unroll")                                                               \
        for (int mt = 0; mt < 4; mt++)                                                  \
            LDSM4(ah[mt][0], ah[mt][1], ah[mt][2], ah[mt][3], addrA[mt] + ks * 32);     \
        LDSM4(bh[0][0], bh[0][1], bh[1][0], bh[1][1], addrB[0] + ks * 32);              \
        LDSM4(bh[2][0], bh[2][1], bh[3][0], bh[3][1], addrB[1] + ks * 32);              \
        _Pragma("unroll")                                                               \
        for (int mt = 0; mt < 4; mt++)                                                  \
            _Pragma("unroll")                                                           \
            for (int nt = 0; nt < 4; nt++)                                              \
                mma_f16(acc[mt][nt], ah[mt], bh[nt]);                                   \
    }

// ============ generic 128x128x128 fp16 tile GEMM: C = A@W (+bias)(relu) ============
__global__ __launch_bounds__(256, 2) void k_tile(
    const float* __restrict__ A, int lda, int aXstep, int aYstep,
    const float* __restrict__ W, int ldw, int wYstep,
    float* __restrict__ C, int ldc, int cXstep, int cYstep,
    const float* __restrict__ bias, int bYstep, int relu) {
    extern __shared__ char sm[];
    uint32_t* Ah = (uint32_t*)(sm + AH_OFF);
    uint32_t* Bh = (uint32_t*)(sm + BH_OFF);
    const int t = threadIdx.x;
    const float* At = A + (size_t)blockIdx.x * aXstep + (size_t)blockIdx.y * aYstep;
    const float* Wt = W + (size_t)blockIdx.y * wYstep;
    float* Ct = C + (size_t)blockIdx.x * cXstep + (size_t)blockIdx.y * cYstep;
    const float* bt = bias ? bias + (size_t)blockIdx.y * bYstep : nullptr;

    load_btile(Wt, ldw, Bh, t);
    load_atile(At, lda, Ah, t);
    __syncthreads();
    MMA_MAIN(smem_u32(sm));

    int cc[4];
#pragma unroll
    for (int nt = 0; nt < 4; nt++) cc[nt] = wn * 32 + nt * 8 + lid * 2;
#pragma unroll
    for (int nt = 0; nt < 4; nt++) {
        float2 bb = bt ? *(const float2*)&bt[cc[nt]] : make_float2(0.f, 0.f);
#pragma unroll
        for (int mt = 0; mt < 4; mt++) {
            int r0 = wm * 64 + mt * 16 + gid;
            float2 o0 = make_float2(acc[mt][nt][0] + bb.x, acc[mt][nt][1] + bb.y);
            float2 o1 = make_float2(acc[mt][nt][2] + bb.x, acc[mt][nt][3] + bb.y);
            if (relu) {
                o0.x = fmaxf(o0.x, 0.f); o0.y = fmaxf(o0.y, 0.f);
                o1.x = fmaxf(o1.x, 0.f); o1.y = fmaxf(o1.y, 0.f);
            }
            *(float2*)&Ct[(size_t)r0 * ldc + cc[nt]] = o0;
            *(float2*)&Ct[(size_t)(r0 + 8) * ldc + cc[nt]] = o1;
        }
    }
}

// ============ pack pre weights/biases contiguous ============
__global__ void k_pack(const float* __restrict__ ws, const float* __restrict__ wt,
                       const float* __restrict__ wq2, const float* __restrict__ bm,
                       const float* __restrict__ bq2) {
    int i = blockIdx.x * 256 + threadIdx.x;
    if (i < 16384) {
        g_wcat[i] = ws[i];
        g_wcat[16384 + i] = wt[i];
        g_wcat[32768 + i] = wq2[i];
    }
    if (i < 128) {
        g_bcat[i] = bm[i];
        g_bcat[128 + i] = 0.f;
        g_bcat[256 + i] = bq2[i];
    }
}

// ============ qh precompute: smem-staged transposed wk ============
// qh[n][h][c] = sum_dh wk[c, h*16+dh] * q[n, h*16+dh] * 0.25
#define QH_SMEM 68096
__global__ __launch_bounds__(256) void k_qh(const float* __restrict__ wk) {
    extern __shared__ float wsT[];              // [128 k][133]
    __shared__ float qs[4][128];
    const int t = threadIdx.x;
    for (int i = t; i < 16384; i += 256) {
        int c = i >> 7, k = i & 127;
        wsT[k * 133 + c] = wk[i] * 0.25f;       // coalesced read
    }
    for (int i = t; i < 512; i += 256) {
        int j = i >> 7, c = i & 127;
        qs[j][c] = g_pre[2 * 65536 + (blockIdx.x * 4 + j) * 128 + c];
    }
    __syncthreads();
    const int c = t & 127, hb = (t >> 7) * 4;
#pragma unroll
    for (int j = 0; j < 4; j++) {
        int n = blockIdx.x * 4 + j;
#pragma unroll
        for (int ho = 0; ho < 4; ho++) {
            int h = hb + ho;
            float a = 0.f;
#pragma unroll
            for (int dh = 0; dh < 16; dh++)
                a += wsT[(h * 16 + dh) * 133 + c] * qs[j][h * 16 + dh];
            g_qh[n * 1024 + h * 128 + c] = a;
        }
    }
}

// ============ big fused GEMM (fp16 single-pass + register LN epilogue) ============
// mode 0: g_mem = relu(LN(edge @ W + ns[n] + nt[s]))
// mode 1: outp  = LN(edge + relu(LN(g_mem @ W + bpe)))
__global__ __launch_bounds__(256, 2) void k_gemm(
    const float* __restrict__ Asrc, const float* __restrict__ W, int mode,
    const float* __restrict__ gA, const float* __restrict__ bA,
    const float* __restrict__ res_in, const float* __restrict__ bpe,
    const float* __restrict__ gB, const float* __restrict__ bB,
    float* __restrict__ outp) {
    extern __shared__ char sm[];
    uint32_t* Ah = (uint32_t*)(sm + AH_OFF);
    uint32_t* Bh = (uint32_t*)(sm + BH_OFF);
    float* ps = (float*)(sm + PS_OFF);
    float* pq = (float*)(sm + PQ_OFF);
    const int t = threadIdx.x;
    const float* Abase = mode ? (const float*)g_mem : Asrc;
    const float* At = Abase + (size_t)blockIdx.x * 16384;

    load_btile(W, 128, Bh, t);
    load_atile(At, 128, Ah, t);
    __syncthreads();
    MMA_MAIN(smem_u32(sm));

    int cc[4];
#pragma unroll
    for (int nt = 0; nt < 4; nt++) cc[nt] = wn * 32 + nt * 8 + lid * 2;

    if (mode == 0) {
        const int s_tile = blockIdx.x >> 2, nbase = (blockIdx.x & 3) * 128;
#pragma unroll
        for (int nt = 0; nt < 4; nt++) {
            float2 ntv = *(const float2*)&g_pre[65536 + s_tile * 128 + cc[nt]];
#pragma unroll
            for (int mt = 0; mt < 4; mt++) {
                int r0 = wm * 64 + mt * 16 + gid;
                float2 n0 = *(const float2*)&g_pre[(nbase + r0) * 128 + cc[nt]];
                float2 n1 = *(const float2*)&g_pre[(nbase + r0 + 8) * 128 + cc[nt]];
                acc[mt][nt][0] += n0.x + ntv.x; acc[mt][nt][1] += n0.y + ntv.y;
                acc[mt][nt][2] += n1.x + ntv.x; acc[mt][nt][3] += n1.y + ntv.y;
            }
        }
        float s8[8], q8[8];
#pragma unroll
        for (int mt = 0; mt < 4; mt++) {
            float sl = 0, ql = 0, sh = 0, qh = 0;
#pragma unroll
            for (int nt = 0; nt < 4; nt++) {
                sl += acc[mt][nt][0] + acc[mt][nt][1];
                ql += acc[mt][nt][0]*acc[mt][nt][0] + acc[mt][nt][1]*acc[mt][nt][1];
                sh += acc[mt][nt][2] + acc[mt][nt][3];
                qh += acc[mt][nt][2]*acc[mt][nt][2] + acc[mt][nt][3]*acc[mt][nt][3];
            }
            s8[mt*2] = sl; q8[mt*2] = ql; s8[mt*2+1] = sh; q8[mt*2+1] = qh;
        }
#pragma unroll
        for (int i = 0; i < 8; i++) {
            s8[i] += __shfl_xor_sync(0xffffffffu, s8[i], 1);
            s8[i] += __shfl_xor_sync(0xffffffffu, s8[i], 2);
            q8[i] += __shfl_xor_sync(0xffffffffu, q8[i], 1);
            q8[i] += __shfl_xor_sync(0xffffffffu, q8[i], 2);
        }
        if (lid == 0) {
#pragma unroll
            for (int mt = 0; mt < 4; mt++) {
                int r0 = wm * 64 + mt * 16 + gid;
                ps[r0 * 4 + wn] = s8[mt*2];  pq[r0 * 4 + wn] = q8[mt*2];
                ps[(r0+8)*4 + wn] = s8[mt*2+1]; pq[(r0+8)*4 + wn] = q8[mt*2+1];
            }
        }
        __syncthreads();
        float mean[8], rstd[8];
#pragma unroll
        for (int mt = 0; mt < 4; mt++) {
#pragma unroll
            for (int hh = 0; hh < 2; hh++) {
                int r = wm * 64 + mt * 16 + gid + hh * 8;
                float4 a = *(float4*)&ps[r * 4];
                float4 b = *(float4*)&pq[r * 4];
                float m = (a.x + a.y + a.z + a.w) * (1.f/128.f);
                float v = (b.x + b.y + b.z + b.w) * (1.f/128.f) - m * m;
                mean[mt*2+hh] = m; rstd[mt*2+hh] = rsqrtf(v + LN_EPS);
            }
        }
        float* orow = g_mem + (size_t)blockIdx.x * 16384;
#pragma unroll
        for (int nt = 0; nt < 4; nt++) {
            float2 gv = *(const float2*)&gA[cc[nt]];
            float2 bv2 = *(const float2*)&bA[cc[nt]];
#pragma unroll
            for (int mt = 0; mt < 4; mt++) {
                int r0 = wm * 64 + mt * 16 + gid;
                float2 o0, o1;
                o0.x = fmaxf((acc[mt][nt][0]-mean[mt*2])*rstd[mt*2]*gv.x + bv2.x, 0.f);
                o0.y = fmaxf((acc[mt][nt][1]-mean[mt*2])*rstd[mt*2]*gv.y + bv2.y, 0.f);
                o1.x = fmaxf((acc[mt][nt][2]-mean[mt*2+1])*rstd[mt*2+1]*gv.x + bv2.x, 0.f);
                o1.y = fmaxf((acc[mt][nt][3]-mean[mt*2+1])*rstd[mt*2+1]*gv.y + bv2.y, 0.f);
                *(float2*)&orow[r0 * 128 + cc[nt]] = o0;
                *(float2*)&orow[(r0 + 8) * 128 + cc[nt]] = o1;
            }
        }
    } else {
#pragma unroll
        for (int nt = 0; nt < 4; nt++) {
            float2 bp = *(const float2*)&bpe[cc[nt]];
#pragma unroll
            for (int mt = 0; mt < 4; mt++) {
                acc[mt][nt][0] += bp.x; acc[mt][nt][1] += bp.y;
                acc[mt][nt][2] += bp.x; acc[mt][nt][3] += bp.y;
            }
        }
        float s8[8], q8[8];
#pragma unroll
        for (int mt = 0; mt < 4; mt++) {
            float sl = 0, ql = 0, sh = 0, qh = 0;
#pragma unroll
            for (int nt = 0; nt < 4; nt++) {
                sl += acc[mt][nt][0] + acc[mt][nt][1];
                ql += acc[mt][nt][0]*acc[mt][nt][0] + acc[mt][nt][1]*acc[mt][nt][1];
                sh += acc[mt][nt][2] + acc[mt][nt][3];
                qh += acc[mt][nt][2]*acc[mt][nt][2] + acc[mt][nt][3]*acc[mt][nt][3];
            }
            s8[mt*2] = sl; q8[mt*2] = ql; s8[mt*2+1] = sh; q8[mt*2+1] = qh;
        }
#pragma unroll
        for (int i = 0; i < 8; i++) {
            s8[i] += __shfl_xor_sync(0xffffffffu, s8[i], 1);
            s8[i] += __shfl_xor_sync(0xffffffffu, s8[i], 2);
            q8[i] += __shfl_xor_sync(0xffffffffu, q8[i], 1);
            q8[i] += __shfl_xor_sync(0xffffffffu, q8[i], 2);
        }
        if (lid == 0) {
#pragma unroll
            for (int mt = 0; mt < 4; mt++) {
                int r0 = wm * 64 + mt * 16 + gid;
                ps[r0 * 4 + wn] = s8[mt*2];  pq[r0 * 4 + wn] = q8[mt*2];
                ps[(r0+8)*4 + wn] = s8[mt*2+1]; pq[(r0+8)*4 + wn] = q8[mt*2+1];
            }
        }
        __syncthreads();
        float mean[8], rstd[8];
#pragma unroll
        for (int mt = 0; mt < 4; mt++) {
#pragma unroll
            for (int hh = 0; hh < 2; hh++) {
                int r = wm * 64 + mt * 16 + gid + hh * 8;
                float4 a = *(float4*)&ps[r * 4];
                float4 b = *(float4*)&pq[r * 4];
                float m = (a.x + a.y + a.z + a.w) * (1.f/128.f);
                float v = (b.x + b.y + b.z + b.w) * (1.f/128.f) - m * m;
                mean[mt*2+hh] = m; rstd[mt*2+hh] = rsqrtf(v + LN_EPS);
            }
        }
        const float* erow = res_in + (size_t)blockIdx.x * 16384;
#pragma unroll
        for (int nt = 0; nt < 4; nt++) {
            float2 g1 = *(const float2*)&gA[cc[nt]];
            float2 b1 = *(const float2*)&bA[cc[nt]];
#pragma unroll
            for (int mt = 0; mt < 4; mt++) {
                int r0 = wm * 64 + mt * 16 + gid;
                float2 e0 = *(const float2*)&erow[r0 * 128 + cc[nt]];
                float2 e1 = *(const float2*)&erow[(r0 + 8) * 128 + cc[nt]];
                acc[mt][nt][0] = e0.x + fmaxf((acc[mt][nt][0]-mean[mt*2])*rstd[mt*2]*g1.x + b1.x, 0.f);
                acc[mt][nt][1] = e0.y + fmaxf((acc[mt][nt][1]-mean[mt*2])*rstd[mt*2]*g1.y + b1.y, 0.f);
                acc[mt][nt][2] = e1.x + fmaxf((acc[mt][nt][2]-mean[mt*2+1])*rstd[mt*2+1]*g1.x + b1.x, 0.f);
                acc[mt][nt][3] = e1.y + fmaxf((acc[mt][nt][3]-mean[mt*2+1])*rstd[mt*2+1]*g1.y + b1.y, 0.f);
            }
        }
        __syncthreads();
#pragma unroll
        for (int mt = 0; mt < 4; mt++) {
            float sl = 0, ql = 0, sh = 0, qh = 0;
#pragma unroll
            for (int nt = 0; nt < 4; nt++) {
                sl += acc[mt][nt][0] + acc[mt][nt][1];
                ql += acc[mt][nt][0]*acc[mt][nt][0] + acc[mt][nt][1]*acc[mt][nt][1];
                sh += acc[mt][nt][2] + acc[mt][nt][3];
                qh += acc[mt][nt][2]*acc[mt][nt][2] + acc[mt][nt][3]*acc[mt][nt][3];
            }
            s8[mt*2] = sl; q8[mt*2] = ql; s8[mt*2+1] = sh; q8[mt*2+1] = qh;
        }
#pragma unroll
        for (int i = 0; i < 8; i++) {
            s8[i] += __shfl_xor_sync(0xffffffffu, s8[i], 1);
            s8[i] += __shfl_xor_sync(0xffffffffu, s8[i], 2);
            q8[i] += __shfl_xor_sync(0xffffffffu, q8[i], 1);
            q8[i] += __shfl_xor_sync(0xffffffffu, q8[i], 2);
        }
        if (lid == 0) {
#pragma unroll
            for (int mt = 0; mt < 4; mt++) {
                int r0 = wm * 64 + mt * 16 + gid;
                ps[r0 * 4 + wn] = s8[mt*2];  pq[r0 * 4 + wn] = q8[mt*2];
                ps[(r0+8)*4 + wn] = s8[mt*2+1]; pq[(r0+8)*4 + wn] = q8[mt*2+1];
            }
        }
        __syncthreads();
#pragma unroll
        for (int mt = 0; mt < 4; mt++) {
#pragma unroll
            for (int hh = 0; hh < 2; hh++) {
                int r = wm * 64 + mt * 16 + gid + hh * 8;
                float4 a = *(float4*)&ps[r * 4];
                float4 b = *(float4*)&pq[r * 4];
                float m = (a.x + a.y + a.z + a.w) * (1.f/128.f);
                float v = (b.x + b.y + b.z + b.w) * (1.f/128.f) - m * m;
                mean[mt*2+hh] = m; rstd[mt*2+hh] = rsqrtf(v + LN_EPS);
            }
        }
        float* orow = outp + (size_t)blockIdx.x * 16384;
#pragma unroll
        for (int nt = 0; nt < 4; nt++) {
            float2 g2 = *(const float2*)&gB[cc[nt]];
            float2 b2 = *(const float2*)&bB[cc[nt]];
#pragma unroll
            for (int mt = 0; mt < 4; mt++) {
                int r0 = wm * 64 + mt * 16 + gid;
                float2 o0, o1;
                o0.x = (acc[mt][nt][0]-mean[mt*2])*rstd[mt*2]*g2.x + b2.x;
                o0.y = (acc[mt][nt][1]-mean[mt*2])*rstd[mt*2]*g2.y + b2.y;
                o1.x = (acc[mt][nt][2]-mean[mt*2+1])*rstd[mt*2+1]*g2.x + b2.x;
                o1.y = (acc[mt][nt][3]-mean[mt*2+1])*rstd[mt*2+1]*g2.y + b2.y;
                *(float2*)&orow[r0 * 128 + cc[nt]] = o0;
                *(float2*)&orow[(r0 + 8) * 128 + cc[nt]] = o1;
            }
        }
    }
}

// ============ fused attention (512 threads, MMA scores): one block per n ============
#define MH_OFF   0
#define QB_OFF   139264
#define ATT_OFF  141440
#define MK_OFF   157824
#define ATT_SMEM 158336
__global__ __launch_bounds__(512) void k_attn2(
    const unsigned char* __restrict__ mask,
    const float* __restrict__ wv, const float* __restrict__ bv) {
    extern __shared__ char sm[];
    __nv_bfloat16* mh = (__nv_bfloat16*)(sm + MH_OFF);
    __nv_bfloat16* qb = (__nv_bfloat16*)(sm + QB_OFF);
    float* att = (float*)(sm + ATT_OFF);
    unsigned char* mk = (unsigned char*)(sm + MK_OFF);
    const int n = blockIdx.x, t = threadIdx.x, w = t >> 5, lane = t & 31;
    const uint32_t sb = smem_u32(sm);

    for (int i = t; i < 1024; i += 512) {
        int h = i >> 7, c = i & 127;
        qb[h * 136 + c] = __float2bfloat16_rn(g_qh[n * 1024 + i]);
    }
    mk[t & 511] = mask[n * 512 + (t & 511)];
#pragma unroll 4
    for (int j = 0; j < 32; j++) {
        int idx = t + j * 512;
        int s = idx >> 5, c4 = (idx & 31) * 4;
        float4 v = *(const float4*)&g_mem[((size_t)s * 512 + n) * 128 + c4];
        *(uint2*)&mh[s * 136 + c4] = make_uint2(pack_bf2(v.x, v.y), pack_bf2(v.z, v.w));
    }
    __syncthreads();

    // ---- scores via MMA: warp w covers s in [w*32, w*32+32) ----
    {
        const int l2 = lane & 15;
        const uint32_t aoffA = (uint32_t)((lane & 15) * 272 + (lane >> 4) * 16);
        const uint32_t qaddr = sb + QB_OFF + (uint32_t)((l2 & 7) * 272 + ((l2 >> 3) & 1) * 16);
        float acc[2][4];
#pragma unroll
        for (int mt = 0; mt < 2; mt++)
#pragma unroll
            for (int q = 0; q < 4; q++) acc[mt][q] = 0.f;
#pragma unroll
        for (int ks = 0; ks < 8; ks++) {
            uint32_t bq[2];
            LDSM2(bq[0], bq[1], qaddr + ks * 32);
#pragma unroll
            for (int mt = 0; mt < 2; mt++) {
                uint32_t a[4];
                LDSM4(a[0], a[1], a[2], a[3],
                      sb + MH_OFF + (w * 32 + mt * 16) * 272 + aoffA + ks * 32);
                mma_bf16(acc[mt], a, bq);
            }
        }
        const int gid = lane >> 2, lid = lane & 3;
#pragma unroll
        for (int mt = 0; mt < 2; mt++) {
            int s = w * 32 + mt * 16 + gid;
            att[(2 * lid) * 512 + s]     = acc[mt][0];
            att[(2 * lid + 1) * 512 + s] = acc[mt][1];
            att[(2 * lid) * 512 + s + 8]     = acc[mt][2];
            att[(2 * lid + 1) * 512 + s + 8] = acc[mt][3];
        }
    }
    __syncthreads();

    // ---- softmax per head (warps 0..7), apply mask ----
    if (w < 8) {
        const int h = w;
        float sc[16];
        float mx = -3.402823466e38f;
#pragma unroll
        for (int i = 0; i < 16; i++) {
            int s = lane + i * 32;
            sc[i] = mk[s] ? -3.402823466e38f : att[h * 512 + s];
            mx = fmaxf(mx, sc[i]);
        }
        mx = warp_max(mx);
        float sum = 0.f;
#pragma unroll
        for (int i = 0; i < 16; i++) { sc[i] = __expf(sc[i] - mx); sum += sc[i]; }
        sum = warp_sum(sum);
        float inv = 1.f / sum;
#pragma unroll
        for (int i = 0; i < 16; i++) att[h * 512 + lane + i * 32] = sc[i] * inv;
    }
    __syncthreads();

    // ---- weighted sum: warp w handles s in [w*32, w*32+32) ----
    float r8[8][4];
#pragma unroll
    for (int h = 0; h < 8; h++)
#pragma unroll
        for (int q = 0; q < 4; q++) r8[h][q] = 0.f;
    for (int si = 0; si < 32; si++) {
        int s = w * 32 + si;
        float2 f0 = __bfloat1622float2(*(__nv_bfloat162*)&mh[s * 136 + lane * 4]);
        float2 f1 = __bfloat1622float2(*(__nv_bfloat162*)&mh[s * 136 + lane * 4 + 2]);
#pragma unroll
        for (int h = 0; h < 8; h++) {
            float a = att[h * 512 + s];
            r8[h][0] += a * f0.x; r8[h][1] += a * f0.y;
            r8[h][2] += a * f1.x; r8[h][3] += a * f1.y;
        }
    }
    __syncthreads();                     // all mh reads done
    float* rp = (float*)sm;              // [16 warps][8h][128] = 64KB, aliases mh
#pragma unroll
    for (int h = 0; h < 8; h++)
        *(float4*)&rp[(w * 8 + h) * 128 + lane * 4] =
            make_float4(r8[h][0], r8[h][1], r8[h][2], r8[h][3]);
    __syncthreads();
    float* rfin = (float*)(sm + 65536);  // [h][128], 4KB
    for (int i = t; i < 1024; i += 512) {
        int h = i >> 7, c = i & 127;
        float v = 0.f;
#pragma unroll
        for (int ww = 0; ww < 16; ww++) v += rp[(ww * 8 + h) * 128 + c];
        rfin[i] = v;
    }
    __syncthreads();

    // ---- ctx = r @ wv + bv (sum attn = 1 folds bv through) ----
    if (t < 128) {
        int h = t >> 4;
        float a = bv[t];
#pragma unroll 8
        for (int c = 0; c < 128; c++) a += rfin[h * 128 + c] * wv[c * 128 + t];
        g_ctx[n * 128 + t] = a;
    }
}

// ============ x1 = LN(node + ctx @ wo + bo) ============
__global__ void k_out1(const float* __restrict__ node, const float* __restrict__ wo,
                       const float* __restrict__ bo, const float* __restrict__ g2,
                       const float* __restrict__ b2) {
    int row = blockIdx.x, d = threadIdx.x;
    __shared__ float cs[128];
    __shared__ float rsum[4], rsq[4];
    cs[d] = g_ctx[row * 128 + d];
    __syncthreads();
    float a = bo[d];
#pragma unroll 8
    for (int c = 0; c < 128; c++) a += cs[c] * wo[c * 128 + d];
    a += node[row * 128 + d];
    float s1 = warp_sum(a), s2 = warp_sum(a * a);
    if ((d & 31) == 0) { rsum[d >> 5] = s1; rsq[d >> 5] = s2; }
    __syncthreads();
    float sum = rsum[0] + rsum[1] + rsum[2] + rsum[3];
    float sq = rsq[0] + rsq[1] + rsq[2] + rsq[3];
    float mean = sum * (1.f / 128.f);
    float rs = rsqrtf(sq * (1.f / 128.f) - mean * mean + LN_EPS);
    g_x1[row * 128 + d] = (a - mean) * rs * g2[d] + b2[d];
}

// ============ final: out_x = LN(x1 + sum_k ffp[k] + b2) ============
__global__ void k_fin(const float* __restrict__ b2, const float* __restrict__ g3,
                      const float* __restrict__ b3, float* __restrict__ out_x) {
    int row = blockIdx.x, d = threadIdx.x;
    __shared__ float rsum[4], rsq[4];
    float v = g_x1[row * 128 + d] + b2[d];
#pragma unroll
    for (int k = 0; k < 16; k++) v += g_ffp[k * 65536 + row * 128 + d];
    float s1 = warp_sum(v), s2 = warp_sum(v * v);
    if ((d & 31) == 0) { rsum[d >> 5] = s1; rsq[d >> 5] = s2; }
    __syncthreads();
    float sum = rsum[0] + rsum[1] + rsum[2] + rsum[3];
    float sq = rsq[0] + rsq[1] + rsq[2] + rsq[3];
    float mean = sum * (1.f / 128.f);
    float rs = rsqrtf(sq * (1.f / 128.f) - mean * mean + LN_EPS);
    out_x[row * 128 + d] = (v - mean) * rs * g3[d] + b3[d];
}

extern "C" void kernel_launch(void* const* d_in, const int* in_sizes, int n_in,
                              void* d_out, int out_size) {
    (void)in_sizes; (void)n_in; (void)out_size;
    const float* node     = (const float*)d_in[0];
    const float* edge     = (const float*)d_in[1];
    const unsigned char* mask = (const unsigned char*)d_in[2];
    const float* w_mem_e  = (const float*)d_in[3];
    const float* w_mem_s  = (const float*)d_in[4];
    const float* w_mem_t  = (const float*)d_in[5];
    const float* b_mem    = (const float*)d_in[6];
    const float* g_ln_mem = (const float*)d_in[7];
    const float* b_ln_mem = (const float*)d_in[8];
    const float* w_pe     = (const float*)d_in[9];
    const float* b_pe     = (const float*)d_in[10];
    const float* g_ln_pe  = (const float*)d_in[11];
    const float* b_ln_pe  = (const float*)d_in[12];
    const float* g_ln_edge= (const float*)d_in[13];
    const float* b_ln_edge= (const float*)d_in[14];
    const float* wq       = (const float*)d_in[15];
    const float* bq       = (const float*)d_in[16];
    const float* wk       = (const float*)d_in[17];
    /* bk (d_in[18]) provably drops out of softmax */
    const float* wv       = (const float*)d_in[19];
    const float* bv       = (const float*)d_in[20];
    const float* wo       = (const float*)d_in[21];
    const float* bo       = (const float*)d_in[22];
    const float* g_ln2    = (const float*)d_in[23];
    const float* b_ln2    = (const float*)d_in[24];
    const float* w_ff1    = (const float*)d_in[25];
    const float* b_ff1    = (const float*)d_in[26];
    const float* w_ff2    = (const float*)d_in[27];
    const float* b_ff2    = (const float*)d_in[28];
    const float* g_ln3    = (const float*)d_in[29];
    const float* b_ln3    = (const float*)d_in[30];

    float* out_x = (float*)d_out;
    float* out_edge = (float*)d_out + NSEQ * DMODEL;

    cudaFuncSetAttribute(k_gemm, cudaFuncAttributeMaxDynamicSharedMemorySize, GSMEM);
    cudaFuncSetAttribute(k_tile, cudaFuncAttributeMaxDynamicSharedMemorySize, TSMEM);
    cudaFuncSetAttribute(k_attn2, cudaFuncAttributeMaxDynamicSharedMemorySize, ATT_SMEM);
    cudaFuncSetAttribute(k_qh, cudaFuncAttributeMaxDynamicSharedMemorySize, QH_SMEM);

    float* d_pre; cudaGetSymbolAddress((void**)&d_pre, g_pre);
    float* d_wcat; cudaGetSymbolAddress((void**)&d_wcat, g_wcat);
    float* d_bcat; cudaGetSymbolAddress((void**)&d_bcat, g_bcat);
    float* d_h;  cudaGetSymbolAddress((void**)&d_h, g_h);
    float* d_ffp;cudaGetSymbolAddress((void**)&d_ffp, g_ffp);
    float* d_x1; cudaGetSymbolAddress((void**)&d_x1, g_x1);

    k_pack<<<64, 256>>>(w_mem_s, w_mem_t, wq, b_mem, bq);
    // [ns|nt|q] = node @ [w_mem_s|w_mem_t|wq] + [b_mem|0|bq]
    k_tile<<<dim3(4, 3), 256, TSMEM>>>(node, 128, 16384, 0, d_wcat, 128, 16384,
                                       d_pre, 128, 16384, 65536, d_bcat, 128, 0);
    k_qh<<<128, 256, QH_SMEM>>>(wk);
    // memory = relu(LN(edge @ w_mem_e + ns + nt))
    k_gemm<<<2048, 256, GSMEM>>>(edge, w_mem_e, 0, g_ln_mem, b_ln_mem,
                                 nullptr, nullptr, nullptr, nullptr, nullptr);
    // edge_new = LN(edge + relu(LN(memory @ w_pe + b_pe)))
    k_gemm<<<2048, 256, GSMEM>>>(nullptr, w_pe, 1, g_ln_pe, b_ln_pe,
                                 edge, b_pe, g_ln_edge, b_ln_edge, out_edge);
    k_attn2<<<512, 512, ATT_SMEM>>>(mask, wv, bv);
    k_out1<<<512, 128>>>(node, wo, bo, g_ln2, b_ln2);
    // h = relu(x1 @ w1 + b1)
    k_tile<<<dim3(4, 16), 256, TSMEM>>>(d_x1, 128, 16384, 0, w_ff1, 2048, 128,
                                        d_h, 2048, 262144, 128, b_ff1, 128, 1);
    // ffp[k] = h_chunk @ w2_chunk
    k_tile<<<dim3(4, 16), 256, TSMEM>>>(d_h, 2048, 262144, 128, w_ff2, 128, 16384,
                                        d_ffp, 128, 16384, 65536, nullptr, 0, 0);
    k_fin<<<512, 128>>>(b_ff2, g_ln3, b_ln3, out_x);
}

// round 8
// speedup vs baseline: 4.2443x; 1.1022x over previous
#include <cuda_runtime.h>
#include <cuda_fp16.h>
#include <cstdint>

#define NSEQ 512
#define DMODEL 128
#define LN_EPS 1e-5f

// ---- scratch (device globals; no runtime allocation) ----
__device__ __half g_mem[(size_t)NSEQ * NSEQ * DMODEL];  // memory tensor (s, n, d) fp16
__device__ float g_pre[3 * NSEQ * DMODEL];              // [ns | nt | q]
__device__ float g_qh[NSEQ * 1024];                     // [n][h][c]
__device__ float g_ctx[NSEQ * DMODEL];
__device__ float g_x1[NSEQ * DMODEL];
__device__ float g_h[512 * 2048];                       // ffn hidden
__device__ float g_ffp[16 * 512 * DMODEL];              // ffn split-K partials
__device__ float g_wcat[3 * DMODEL * DMODEL];           // packed pre weights
__device__ float g_bcat[3 * DMODEL];                    // packed pre biases

__device__ __forceinline__ float warp_sum(float v) {
#pragma unroll
    for (int o = 16; o; o >>= 1) v += __shfl_xor_sync(0xffffffffu, v, o);
    return v;
}
__device__ __forceinline__ float warp_max(float v) {
#pragma unroll
    for (int o = 16; o; o >>= 1) v = fmaxf(v, __shfl_xor_sync(0xffffffffu, v, o));
    return v;
}
__device__ __forceinline__ uint32_t smem_u32(const void* p) {
    uint32_t a;
    asm("{ .reg .u64 t; cvta.to.shared.u64 t, %1; cvt.u32.u64 %0, t; }" : "=r"(a) : "l"(p));
    return a;
}
__device__ __forceinline__ void mma_f16(float* c, const uint32_t* a, const uint32_t* b) {
    asm volatile(
        "mma.sync.aligned.m16n8k16.row.col.f32.f16.f16.f32 "
        "{%0,%1,%2,%3}, {%4,%5,%6,%7}, {%8,%9}, {%0,%1,%2,%3};"
        : "+f"(c[0]), "+f"(c[1]), "+f"(c[2]), "+f"(c[3])
        : "r"(a[0]), "r"(a[1]), "r"(a[2]), "r"(a[3]), "r"(b[0]), "r"(b[1]));
}
#define LDSM4(r0, r1, r2, r3, addr)                                                     \
    asm volatile("ldmatrix.sync.aligned.m8n8.x4.shared.b16 {%0,%1,%2,%3}, [%4];"        \
        : "=r"(r0), "=r"(r1), "=r"(r2), "=r"(r3) : "r"(addr))
#define LDSM2(r0, r1, addr)                                                             \
    asm volatile("ldmatrix.sync.aligned.m8n8.x2.shared.b16 {%0,%1}, [%2];"              \
        : "=r"(r0), "=r"(r1) : "r"(addr))
__device__ __forceinline__ uint32_t pack_h2(float a, float b) {
    __half2 p = __floats2half2_rn(a, b);
    return *(uint32_t*)&p;
}

// smem maps. k_tile: A@0, B@34816 (69632). k_fused: A@0, B1@34816, B2@69632, ps/pq.
#define A_OFF  0
#define B1_OFF 34816
#define B2_OFF 69632
#define PS_OFF 104448
#define PQ_OFF 106496
#define GSMEM  108544
#define TSMEM  69632

__device__ __forceinline__ void load_atile(const float* __restrict__ At, int lda,
                                           uint32_t* Ah, int t) {
#pragma unroll
    for (int j = 0; j < 16; j++) {
        int idx = t + j * 256;
        int row = idx >> 5, c4 = (idx & 31) * 4;
        float4 v = *(const float4*)(At + (size_t)row * lda + c4);
        *(uint2*)&Ah[row * 68 + (c4 >> 1)] =
            make_uint2(pack_h2(v.x, v.y), pack_h2(v.z, v.w));
    }
}
__device__ __forceinline__ void load_btile(const float* __restrict__ Wt, int ldw,
                                           uint32_t* Bh, int t) {
#pragma unroll
    for (int j = 0; j < 32; j++) {
        int e = t + j * 256;
        int kp = e >> 7, n = e & 127;
        float a = Wt[(size_t)(2 * kp) * ldw + n];
        float b = Wt[(size_t)(2 * kp + 1) * ldw + n];
        Bh[n * 68 + kp] = pack_h2(a, b);
    }
}

// fp16 MMA mainloop over K=128: warp tile 64(m) x 32(n)
__device__ __forceinline__ void mma_loop(uint32_t aBase, uint32_t bBase,
                                         int wm, int wn, int lane, float acc[4][4][4]) {
    const uint32_t aoff = (uint32_t)((lane & 15) * 272 + (lane >> 4) * 16);
    const uint32_t boff = (uint32_t)(((lane >> 4) * 8 + (lane & 7)) * 272
                                     + ((lane >> 3) & 1) * 16);
    uint32_t addrA[4], addrB[2];
#pragma unroll
    for (int mt = 0; mt < 4; mt++) addrA[mt] = aBase + (wm * 64 + mt * 16) * 272 + aoff;
#pragma unroll
    for (int p = 0; p < 2; p++)    addrB[p] = bBase + (wn * 32 + p * 16) * 272 + boff;
#pragma unroll
    for (int mt = 0; mt < 4; mt++)
#pragma unroll
        for (int nt = 0; nt < 4; nt++)
#pragma unroll
            for (int q = 0; q < 4; q++) acc[mt][nt][q] = 0.f;
#pragma unroll
    for (int ks = 0; ks < 8; ks++) {
        uint32_t ah[4][4], bh[4][2];
#pragma unroll
        for (int mt = 0; mt < 4; mt++)
            LDSM4(ah[mt][0], ah[mt][1], ah[mt][2], ah[mt][3], addrA[mt] + ks * 32);
        LDSM4(bh[0][0], bh[0][1], bh[1][0], bh[1][1], addrB[0] + ks * 32);
        LDSM4(bh[2][0], bh[2][1], bh[3][0], bh[3][1], addrB[1] + ks * 32);
#pragma unroll
        for (int mt = 0; mt < 4; mt++)
#pragma unroll
            for (int nt = 0; nt < 4; nt++)
                mma_f16(acc[mt][nt], ah[mt], bh[nt]);
    }
}

// per-row mean/rstd across 128 cols (acc spread over 4 warps x 4 lanes per row)
__device__ __forceinline__ void row_stats(float acc[4][4][4], float* ps, float* pq,
                                          int wm, int wn, int gid, int lid,
                                          float mean[8], float rstd[8]) {
    float s8[8], q8[8];
#pragma unroll
    for (int mt = 0; mt < 4; mt++) {
        float sl = 0, ql = 0, sh = 0, qh = 0;
#pragma unroll
        for (int nt = 0; nt < 4; nt++) {
            sl += acc[mt][nt][0] + acc[mt][nt][1];
            ql += acc[mt][nt][0]*acc[mt][nt][0] + acc[mt][nt][1]*acc[mt][nt][1];
            sh += acc[mt][nt][2] + acc[mt][nt][3];
            qh += acc[mt][nt][2]*acc[mt][nt][2] + acc[mt][nt][3]*acc[mt][nt][3];
        }
        s8[mt*2] = sl; q8[mt*2] = ql; s8[mt*2+1] = sh; q8[mt*2+1] = qh;
    }
#pragma unroll
    for (int i = 0; i < 8; i++) {
        s8[i] += __shfl_xor_sync(0xffffffffu, s8[i], 1);
        s8[i] += __shfl_xor_sync(0xffffffffu, s8[i], 2);
        q8[i] += __shfl_xor_sync(0xffffffffu, q8[i], 1);
        q8[i] += __shfl_xor_sync(0xffffffffu, q8[i], 2);
    }
    __syncthreads();                       // protect ps/pq reuse + orders prior smem reads
    if (lid == 0) {
#pragma unroll
        for (int mt = 0; mt < 4; mt++) {
            int r0 = wm * 64 + mt * 16 + gid;
            ps[r0 * 4 + wn] = s8[mt*2];   pq[r0 * 4 + wn] = q8[mt*2];
            ps[(r0+8)*4 + wn] = s8[mt*2+1]; pq[(r0+8)*4 + wn] = q8[mt*2+1];
        }
    }
    __syncthreads();
#pragma unroll
    for (int mt = 0; mt < 4; mt++)
#pragma unroll
        for (int hh = 0; hh < 2; hh++) {
            int r = wm * 64 + mt * 16 + gid + hh * 8;
            float4 a = *(float4*)&ps[r * 4];
            float4 b = *(float4*)&pq[r * 4];
            float m = (a.x + a.y + a.z + a.w) * (1.f/128.f);
            float v = (b.x + b.y + b.z + b.w) * (1.f/128.f) - m * m;
            mean[mt*2+hh] = m; rstd[mt*2+hh] = rsqrtf(v + LN_EPS);
        }
}

// ============ generic 128x128x128 fp16 tile GEMM: C = A@W (+bias)(relu) ============
__global__ __launch_bounds__(256, 2) void k_tile(
    const float* __restrict__ A, int lda, int aXstep, int aYstep,
    const float* __restrict__ W, int ldw, int wYstep,
    float* __restrict__ C, int ldc, int cXstep, int cYstep,
    const float* __restrict__ bias, int bYstep, int relu) {
    extern __shared__ char sm[];
    uint32_t* Ah = (uint32_t*)(sm + A_OFF);
    uint32_t* Bh = (uint32_t*)(sm + B1_OFF);
    const int t = threadIdx.x;
    const float* At = A + (size_t)blockIdx.x * aXstep + (size_t)blockIdx.y * aYstep;
    const float* Wt = W + (size_t)blockIdx.y * wYstep;
    float* Ct = C + (size_t)blockIdx.x * cXstep + (size_t)blockIdx.y * cYstep;
    const float* bt = bias ? bias + (size_t)blockIdx.y * bYstep : nullptr;

    load_btile(Wt, ldw, Bh, t);
    load_atile(At, lda, Ah, t);
    __syncthreads();

    const int w = t >> 5, lane = t & 31, wm = w >> 2, wn = w & 3;
    const int gid = lane >> 2, lid = lane & 3;
    const uint32_t sb = smem_u32(sm);
    float acc[4][4][4];
    mma_loop(sb + A_OFF, sb + B1_OFF, wm, wn, lane, acc);

    int cc[4];
#pragma unroll
    for (int nt = 0; nt < 4; nt++) cc[nt] = wn * 32 + nt * 8 + lid * 2;
#pragma unroll
    for (int nt = 0; nt < 4; nt++) {
        float2 bb = bt ? *(const float2*)&bt[cc[nt]] : make_float2(0.f, 0.f);
#pragma unroll
        for (int mt = 0; mt < 4; mt++) {
            int r0 = wm * 64 + mt * 16 + gid;
            float2 o0 = make_float2(acc[mt][nt][0] + bb.x, acc[mt][nt][1] + bb.y);
            float2 o1 = make_float2(acc[mt][nt][2] + bb.x, acc[mt][nt][3] + bb.y);
            if (relu) {
                o0.x = fmaxf(o0.x, 0.f); o0.y = fmaxf(o0.y, 0.f);
                o1.x = fmaxf(o1.x, 0.f); o1.y = fmaxf(o1.y, 0.f);
            }
            *(float2*)&Ct[(size_t)r0 * ldc + cc[nt]] = o0;
            *(float2*)&Ct[(size_t)(r0 + 8) * ldc + cc[nt]] = o1;
        }
    }
}

// ============ pack pre weights/biases contiguous ============
__global__ void k_pack(const float* __restrict__ ws, const float* __restrict__ wt,
                       const float* __restrict__ wq2, const float* __restrict__ bm,
                       const float* __restrict__ bq2) {
    int i = blockIdx.x * 256 + threadIdx.x;
    if (i < 16384) {
        g_wcat[i] = ws[i];
        g_wcat[16384 + i] = wt[i];
        g_wcat[32768 + i] = wq2[i];
    }
    if (i < 128) {
        g_bcat[i] = bm[i];
        g_bcat[128 + i] = 0.f;
        g_bcat[256 + i] = bq2[i];
    }
}

// ============ qh precompute (smem-staged transposed wk) ============
#define QH_SMEM 68096
__global__ __launch_bounds__(256) void k_qh(const float* __restrict__ wk) {
    extern __shared__ float wsT[];              // [128 k][133]
    __shared__ float qs[4][128];
    const int t = threadIdx.x;
    for (int i = t; i < 16384; i += 256) {
        int c = i >> 7, k = i & 127;
        wsT[k * 133 + c] = wk[i] * 0.25f;
    }
    for (int i = t; i < 512; i += 256) {
        int j = i >> 7, c = i & 127;
        qs[j][c] = g_pre[2 * 65536 + (blockIdx.x * 4 + j) * 128 + c];
    }
    __syncthreads();
    const int c = t & 127, hb = (t >> 7) * 4;
#pragma unroll
    for (int j = 0; j < 4; j++) {
        int n = blockIdx.x * 4 + j;
#pragma unroll
        for (int ho = 0; ho < 4; ho++) {
            int h = hb + ho;
            float a = 0.f;
#pragma unroll
            for (int dh = 0; dh < 16; dh++)
                a += wsT[(h * 16 + dh) * 133 + c] * qs[j][h * 16 + dh];
            g_qh[n * 1024 + h * 128 + c] = a;
        }
    }
}

// ============ fused double GEMM ============
// memory = relu(LN(edge @ W1 + ns[n] + nt[s]))  -> g_mem (fp16) + smem
// edge_new = LN(edge + relu(LN(memory @ W2 + bpe)))  -> out_edge
__global__ __launch_bounds__(256, 2) void k_fused(
    const float* __restrict__ edge, const float* __restrict__ W1,
    const float* __restrict__ W2,
    const float* __restrict__ g1m, const float* __restrict__ b1m,
    const float* __restrict__ bpe,
    const float* __restrict__ gpe, const float* __restrict__ bpe_ln,
    const float* __restrict__ gle, const float* __restrict__ ble,
    float* __restrict__ out_edge) {
    extern __shared__ char sm[];
    uint32_t* A  = (uint32_t*)(sm + A_OFF);
    uint32_t* B1 = (uint32_t*)(sm + B1_OFF);
    uint32_t* B2 = (uint32_t*)(sm + B2_OFF);
    float* ps = (float*)(sm + PS_OFF);
    float* pq = (float*)(sm + PQ_OFF);
    const int t = threadIdx.x;
    const float* At = edge + (size_t)blockIdx.x * 16384;

    load_btile(W1, 128, B1, t);
    load_btile(W2, 128, B2, t);
    load_atile(At, 128, A, t);
    __syncthreads();

    const int w = t >> 5, lane = t & 31, wm = w >> 2, wn = w & 3;
    const int gid = lane >> 2, lid = lane & 3;
    const uint32_t sb = smem_u32(sm);
    float acc[4][4][4];
    int cc[4];
#pragma unroll
    for (int nt = 0; nt < 4; nt++) cc[nt] = wn * 32 + nt * 8 + lid * 2;

    // ---- GEMM1: edge @ W1 ----
    mma_loop(sb + A_OFF, sb + B1_OFF, wm, wn, lane, acc);

    // ---- epilogue 1: += ns[n] + nt[s]; LN; relu; store fp16 (gmem + B1 slot) ----
    {
        const int s_tile = blockIdx.x >> 2, nbase = (blockIdx.x & 3) * 128;
#pragma unroll
        for (int nt = 0; nt < 4; nt++) {
            float2 ntv = *(const float2*)&g_pre[65536 + s_tile * 128 + cc[nt]];
#pragma unroll
            for (int mt = 0; mt < 4; mt++) {
                int r0 = wm * 64 + mt * 16 + gid;
                float2 n0 = *(const float2*)&g_pre[(nbase + r0) * 128 + cc[nt]];
                float2 n1 = *(const float2*)&g_pre[(nbase + r0 + 8) * 128 + cc[nt]];
                acc[mt][nt][0] += n0.x + ntv.x; acc[mt][nt][1] += n0.y + ntv.y;
                acc[mt][nt][2] += n1.x + ntv.x; acc[mt][nt][3] += n1.y + ntv.y;
            }
        }
        float mean[8], rstd[8];
        row_stats(acc, ps, pq, wm, wn, gid, lid, mean, rstd);
        // after row_stats' barriers, all warps are done reading B1 (MMA1 finished)
        __half* gm = g_mem + (size_t)blockIdx.x * 16384;
#pragma unroll
        for (int nt = 0; nt < 4; nt++) {
            float2 gv = *(const float2*)&g1m[cc[nt]];
            float2 bv2 = *(const float2*)&b1m[cc[nt]];
#pragma unroll
            for (int mt = 0; mt < 4; mt++) {
                int r0 = wm * 64 + mt * 16 + gid;
                float o0x = fmaxf((acc[mt][nt][0]-mean[mt*2])*rstd[mt*2]*gv.x + bv2.x, 0.f);
                float o0y = fmaxf((acc[mt][nt][1]-mean[mt*2])*rstd[mt*2]*gv.y + bv2.y, 0.f);
                float o1x = fmaxf((acc[mt][nt][2]-mean[mt*2+1])*rstd[mt*2+1]*gv.x + bv2.x, 0.f);
                float o1y = fmaxf((acc[mt][nt][3]-mean[mt*2+1])*rstd[mt*2+1]*gv.y + bv2.y, 0.f);
                uint32_t p0 = pack_h2(o0x, o0y), p1 = pack_h2(o1x, o1y);
                B1[r0 * 68 + (cc[nt] >> 1)] = p0;
                B1[(r0 + 8) * 68 + (cc[nt] >> 1)] = p1;
                *(uint32_t*)&gm[r0 * 128 + cc[nt]] = p0;
                *(uint32_t*)&gm[(r0 + 8) * 128 + cc[nt]] = p1;
            }
        }
    }
    __syncthreads();   // B1 now holds the memory tile (fp16)

    // ---- GEMM2: memory @ W2 ----
    mma_loop(sb + B1_OFF, sb + B2_OFF, wm, wn, lane, acc);

    // ---- epilogue 2: + bpe; LN1; relu; + edge (fp16 from A slot); LN2; write ----
    {
#pragma unroll
        for (int nt = 0; nt < 4; nt++) {
            float2 bp = *(const float2*)&bpe[cc[nt]];
#pragma unroll
            for (int mt = 0; mt < 4; mt++) {
                acc[mt][nt][0] += bp.x; acc[mt][nt][1] += bp.y;
                acc[mt][nt][2] += bp.x; acc[mt][nt][3] += bp.y;
            }
        }
        float mean[8], rstd[8];
        row_stats(acc, ps, pq, wm, wn, gid, lid, mean, rstd);
#pragma unroll
        for (int nt = 0; nt < 4; nt++) {
            float2 g1 = *(const float2*)&gpe[cc[nt]];
            float2 b1 = *(const float2*)&bpe_ln[cc[nt]];
#pragma unroll
            for (int mt = 0; mt < 4; mt++) {
                int r0 = wm * 64 + mt * 16 + gid;
                float2 e0 = __half22float2(*(__half2*)&A[r0 * 68 + (cc[nt] >> 1)]);
                float2 e1 = __half22float2(*(__half2*)&A[(r0 + 8) * 68 + (cc[nt] >> 1)]);
                acc[mt][nt][0] = e0.x + fmaxf((acc[mt][nt][0]-mean[mt*2])*rstd[mt*2]*g1.x + b1.x, 0.f);
                acc[mt][nt][1] = e0.y + fmaxf((acc[mt][nt][1]-mean[mt*2])*rstd[mt*2]*g1.y + b1.y, 0.f);
                acc[mt][nt][2] = e1.x + fmaxf((acc[mt][nt][2]-mean[mt*2+1])*rstd[mt*2+1]*g1.x + b1.x, 0.f);
                acc[mt][nt][3] = e1.y + fmaxf((acc[mt][nt][3]-mean[mt*2+1])*rstd[mt*2+1]*g1.y + b1.y, 0.f);
            }
        }
        row_stats(acc, ps, pq, wm, wn, gid, lid, mean, rstd);
        float* orow = out_edge + (size_t)blockIdx.x * 16384;
#pragma unroll
        for (int nt = 0; nt < 4; nt++) {
            float2 g2 = *(const float2*)&gle[cc[nt]];
            float2 b2 = *(const float2*)&ble[cc[nt]];
#pragma unroll
            for (int mt = 0; mt < 4; mt++) {
                int r0 = wm * 64 + mt * 16 + gid;
                float2 o0, o1;
                o0.x = (acc[mt][nt][0]-mean[mt*2])*rstd[mt*2]*g2.x + b2.x;
                o0.y = (acc[mt][nt][1]-mean[mt*2])*rstd[mt*2]*g2.y + b2.y;
                o1.x = (acc[mt][nt][2]-mean[mt*2+1])*rstd[mt*2+1]*g2.x + b2.x;
                o1.y = (acc[mt][nt][3]-mean[mt*2+1])*rstd[mt*2+1]*g2.y + b2.y;
                *(float2*)&orow[r0 * 128 + cc[nt]] = o0;
                *(float2*)&orow[(r0 + 8) * 128 + cc[nt]] = o1;
            }
        }
    }
}

// ============ fused attention (512 threads, fp16 MMA scores): one block per n ============
#define MH_OFF   0
#define QB_OFF   139264
#define ATT_OFF  141440
#define MK_OFF   157824
#define ATT_SMEM 158336
__global__ __launch_bounds__(512) void k_attn2(
    const unsigned char* __restrict__ mask,
    const float* __restrict__ wv, const float* __restrict__ bv) {
    extern __shared__ char sm[];
    __half* mh = (__half*)(sm + MH_OFF);
    __half* qb = (__half*)(sm + QB_OFF);
    float* att = (float*)(sm + ATT_OFF);
    unsigned char* mk = (unsigned char*)(sm + MK_OFF);
    const int n = blockIdx.x, t = threadIdx.x, w = t >> 5, lane = t & 31;
    const uint32_t sb = smem_u32(sm);

    for (int i = t; i < 1024; i += 512) {
        int h = i >> 7, c = i & 127;
        qb[h * 136 + c] = __float2half_rn(g_qh[n * 1024 + i]);
    }
    mk[t & 511] = mask[n * 512 + (t & 511)];
#pragma unroll 4
    for (int j = 0; j < 16; j++) {
        int idx = t + j * 512;
        int s = idx >> 4, c8 = (idx & 15) * 8;
        uint4 v = *(const uint4*)&g_mem[((size_t)s * 512 + n) * 128 + c8];
        *(uint4*)&mh[s * 136 + c8] = v;
    }
    __syncthreads();

    // ---- scores via MMA: warp w covers s in [w*32, w*32+32) ----
    {
        const int l2 = lane & 15;
        const uint32_t aoffA = (uint32_t)((lane & 15) * 272 + (lane >> 4) * 16);
        const uint32_t qaddr = sb + QB_OFF + (uint32_t)((l2 & 7) * 272 + ((l2 >> 3) & 1) * 16);
        float acc[2][4];
#pragma unroll
        for (int mt = 0; mt < 2; mt++)
#pragma unroll
            for (int q = 0; q < 4; q++) acc[mt][q] = 0.f;
#pragma unroll
        for (int ks = 0; ks < 8; ks++) {
            uint32_t bq[2];
            LDSM2(bq[0], bq[1], qaddr + ks * 32);
#pragma unroll
            for (int mt = 0; mt < 2; mt++) {
                uint32_t a[4];
                LDSM4(a[0], a[1], a[2], a[3],
                      sb + MH_OFF + (w * 32 + mt * 16) * 272 + aoffA + ks * 32);
                mma_f16(acc[mt], a, bq);
            }
        }
        const int gid = lane >> 2, lid = lane & 3;
#pragma unroll
        for (int mt = 0; mt < 2; mt++) {
            int s = w * 32 + mt * 16 + gid;
            att[(2 * lid) * 512 + s]     = acc[mt][0];
            att[(2 * lid + 1) * 512 + s] = acc[mt][1];
            att[(2 * lid) * 512 + s + 8]     = acc[mt][2];
            att[(2 * lid + 1) * 512 + s + 8] = acc[mt][3];
        }
    }
    __syncthreads();

    // ---- softmax per head (warps 0..7), apply mask ----
    if (w < 8) {
        const int h = w;
        float sc[16];
        float mx = -3.402823466e38f;
#pragma unroll
        for (int i = 0; i < 16; i++) {
            int s = lane + i * 32;
            sc[i] = mk[s] ? -3.402823466e38f : att[h * 512 + s];
            mx = fmaxf(mx, sc[i]);
        }
        mx = warp_max(mx);
        float sum = 0.f;
#pragma unroll
        for (int i = 0; i < 16; i++) { sc[i] = __expf(sc[i] - mx); sum += sc[i]; }
        sum = warp_sum(sum);
        float inv = 1.f / sum;
#pragma unroll
        for (int i = 0; i < 16; i++) att[h * 512 + lane + i * 32] = sc[i] * inv;
    }
    __syncthreads();

    // ---- weighted sum: warp w handles s in [w*32, w*32+32) ----
    float r8[8][4];
#pragma unroll
    for (int h = 0; h < 8; h++)
#pragma unroll
        for (int q = 0; q < 4; q++) r8[h][q] = 0.f;
    for (int si = 0; si < 32; si++) {
        int s = w * 32 + si;
        float2 f0 = __half22float2(*(__half2*)&mh[s * 136 + lane * 4]);
        float2 f1 = __half22float2(*(__half2*)&mh[s * 136 + lane * 4 + 2]);
#pragma unroll
        for (int h = 0; h < 8; h++) {
            float a = att[h * 512 + s];
            r8[h][0] += a * f0.x; r8[h][1] += a * f0.y;
            r8[h][2] += a * f1.x; r8[h][3] += a * f1.y;
        }
    }
    __syncthreads();                     // all mh reads done
    float* rp = (float*)sm;              // [16 warps][8h][128] = 64KB, aliases mh
#pragma unroll
    for (int h = 0; h < 8; h++)
        *(float4*)&rp[(w * 8 + h) * 128 + lane * 4] =
            make_float4(r8[h][0], r8[h][1], r8[h][2], r8[h][3]);
    __syncthreads();
    float* rfin = (float*)(sm + 65536);  // [h][128], 4KB
    for (int i = t; i < 1024; i += 512) {
        int h = i >> 7, c = i & 127;
        float v = 0.f;
#pragma unroll
        for (int ww = 0; ww < 16; ww++) v += rp[(ww * 8 + h) * 128 + c];
        rfin[i] = v;
    }
    __syncthreads();

    // ---- ctx = r @ wv + bv ----
    if (t < 128) {
        int h = t >> 4;
        float a = bv[t];
#pragma unroll 8
        for (int c = 0; c < 128; c++) a += rfin[h * 128 + c] * wv[c * 128 + t];
        g_ctx[n * 128 + t] = a;
    }
}

// ============ x1 = LN(node + ctx @ wo + bo) ============
__global__ void k_out1(const float* __restrict__ node, const float* __restrict__ wo,
                       const float* __restrict__ bo, const float* __restrict__ g2,
                       const float* __restrict__ b2) {
    int row = blockIdx.x, d = threadIdx.x;
    __shared__ float cs[128];
    __shared__ float rsum[4], rsq[4];
    cs[d] = g_ctx[row * 128 + d];
    __syncthreads();
    float a = bo[d];
#pragma unroll 8
    for (int c = 0; c < 128; c++) a += cs[c] * wo[c * 128 + d];
    a += node[row * 128 + d];
    float s1 = warp_sum(a), s2 = warp_sum(a * a);
    if ((d & 31) == 0) { rsum[d >> 5] = s1; rsq[d >> 5] = s2; }
    __syncthreads();
    float sum = rsum[0] + rsum[1] + rsum[2] + rsum[3];
    float sq = rsq[0] + rsq[1] + rsq[2] + rsq[3];
    float mean = sum * (1.f / 128.f);
    float rs = rsqrtf(sq * (1.f / 128.f) - mean * mean + LN_EPS);
    g_x1[row * 128 + d] = (a - mean) * rs * g2[d] + b2[d];
}

// ============ final: out_x = LN(x1 + sum_k ffp[k] + b2) ============
__global__ void k_fin(const float* __restrict__ b2, const float* __restrict__ g3,
                      const float* __restrict__ b3, float* __restrict__ out_x) {
    int row = blockIdx.x, d = threadIdx.x;
    __shared__ float rsum[4], rsq[4];
    float v = g_x1[row * 128 + d] + b2[d];
#pragma unroll
    for (int k = 0; k < 16; k++) v += g_ffp[k * 65536 + row * 128 + d];
    float s1 = warp_sum(v), s2 = warp_sum(v * v);
    if ((d & 31) == 0) { rsum[d >> 5] = s1; rsq[d >> 5] = s2; }
    __syncthreads();
    float sum = rsum[0] + rsum[1] + rsum[2] + rsum[3];
    float sq = rsq[0] + rsq[1] + rsq[2] + rsq[3];
    float mean = sum * (1.f / 128.f);
    float rs = rsqrtf(sq * (1.f / 128.f) - mean * mean + LN_EPS);
    out_x[row * 128 + d] = (v - mean) * rs * g3[d] + b3[d];
}

extern "C" void kernel_launch(void* const* d_in, const int* in_sizes, int n_in,
                              void* d_out, int out_size) {
    (void)in_sizes; (void)n_in; (void)out_size;
    const float* node     = (const float*)d_in[0];
    const float* edge     = (const float*)d_in[1];
    const unsigned char* mask = (const unsigned char*)d_in[2];
    const float* w_mem_e  = (const float*)d_in[3];
    const float* w_mem_s  = (const float*)d_in[4];
    const float* w_mem_t  = (const float*)d_in[5];
    const float* b_mem    = (const float*)d_in[6];
    const float* g_ln_mem = (const float*)d_in[7];
    const float* b_ln_mem = (const float*)d_in[8];
    const float* w_pe     = (const float*)d_in[9];
    const float* b_pe     = (const float*)d_in[10];
    const float* g_ln_pe  = (const float*)d_in[11];
    const float* b_ln_pe  = (const float*)d_in[12];
    const float* g_ln_edge= (const float*)d_in[13];
    const float* b_ln_edge= (const float*)d_in[14];
    const float* wq       = (const float*)d_in[15];
    const float* bq       = (const float*)d_in[16];
    const float* wk       = (const float*)d_in[17];
    /* bk (d_in[18]) provably drops out of softmax */
    const float* wv       = (const float*)d_in[19];
    const float* bv       = (const float*)d_in[20];
    const float* wo       = (const float*)d_in[21];
    const float* bo       = (const float*)d_in[22];
    const float* g_ln2    = (const float*)d_in[23];
    const float* b_ln2    = (const float*)d_in[24];
    const float* w_ff1    = (const float*)d_in[25];
    const float* b_ff1    = (const float*)d_in[26];
    const float* w_ff2    = (const float*)d_in[27];
    const float* b_ff2    = (const float*)d_in[28];
    const float* g_ln3    = (const float*)d_in[29];
    const float* b_ln3    = (const float*)d_in[30];

    float* out_x = (float*)d_out;
    float* out_edge = (float*)d_out + NSEQ * DMODEL;

    cudaFuncSetAttribute(k_fused, cudaFuncAttributeMaxDynamicSharedMemorySize, GSMEM);
    cudaFuncSetAttribute(k_tile, cudaFuncAttributeMaxDynamicSharedMemorySize, TSMEM);
    cudaFuncSetAttribute(k_attn2, cudaFuncAttributeMaxDynamicSharedMemorySize, ATT_SMEM);
    cudaFuncSetAttribute(k_qh, cudaFuncAttributeMaxDynamicSharedMemorySize, QH_SMEM);

    float* d_pre;  cudaGetSymbolAddress((void**)&d_pre, g_pre);
    float* d_wcat; cudaGetSymbolAddress((void**)&d_wcat, g_wcat);
    float* d_bcat; cudaGetSymbolAddress((void**)&d_bcat, g_bcat);
    float* d_h;    cudaGetSymbolAddress((void**)&d_h, g_h);
    float* d_ffp;  cudaGetSymbolAddress((void**)&d_ffp, g_ffp);
    float* d_x1;   cudaGetSymbolAddress((void**)&d_x1, g_x1);

    k_pack<<<64, 256>>>(w_mem_s, w_mem_t, wq, b_mem, bq);
    // [ns|nt|q] = node @ [w_mem_s|w_mem_t|wq] + [b_mem|0|bq]
    k_tile<<<dim3(4, 3), 256, TSMEM>>>(node, 128, 16384, 0, d_wcat, 128, 16384,
                                       d_pre, 128, 16384, 65536, d_bcat, 128, 0);
    k_qh<<<128, 256, QH_SMEM>>>(wk);
    // memory (fp16) + edge_new in one pass
    k_fused<<<2048, 256, GSMEM>>>(edge, w_mem_e, w_pe, g_ln_mem, b_ln_mem,
                                  b_pe, g_ln_pe, b_ln_pe, g_ln_edge, b_ln_edge, out_edge);
    k_attn2<<<512, 512, ATT_SMEM>>>(mask, wv, bv);
    k_out1<<<512, 128>>>(node, wo, bo, g_ln2, b_ln2);
    // h = relu(x1 @ w1 + b1)
    k_tile<<<dim3(4, 16), 256, TSMEM>>>(d_x1, 128, 16384, 0, w_ff1, 2048, 128,
                                        d_h, 2048, 262144, 128, b_ff1, 128, 1);
    // ffp[k] = h_chunk @ w2_chunk
    k_tile<<<dim3(4, 16), 256, TSMEM>>>(d_h, 2048, 262144, 128, w_ff2, 128, 16384,
                                        d_ffp, 128, 16384, 65536, nullptr, 0, 0);
    k_fin<<<512, 128>>>(b_ff2, g_ln3, b_ln3, out_x);
}